// round 7
// baseline (speedup 1.0000x reference)
#include <cuda_runtime.h>
#include <cuda.h>
#include <math.h>
#include <stdint.h>

#define B_   4
#define T_   2048
#define C_   1024
#define NH_  16
#define HD_  64
#define M_   (B_*T_)      // 8192

// Scratch (allocation-free: __device__ globals)
__device__ float g_q[B_*NH_*T_*HD_];
__device__ float g_k[B_*NH_*T_*HD_];
__device__ float g_v[B_*NH_*T_*HD_];
__device__ float g_xhi[M_*C_],  g_xlo[M_*C_];      // split x
__device__ float g_ahi[M_*C_],  g_alo[M_*C_];      // split attention output
__device__ float g_wthi[3*C_*C_], g_wtlo[3*C_*C_]; // w_attn^T split
__device__ float g_wphi[C_*C_],   g_wplo[C_*C_];   // w_proj^T split

// ===========================================================================
// Helpers
// ===========================================================================
__device__ __forceinline__ float tf32_rd(float x) {
    uint32_t u; asm("cvt.rna.tf32.f32 %0, %1;" : "=r"(u) : "f"(x));
    return __uint_as_float(u);
}
#define SPLIT(raw, hi, lo) do { \
    float _h = tf32_rd(raw); \
    hi = __float_as_uint(_h); \
    lo = __float_as_uint(tf32_rd((raw) - _h)); \
} while (0)
__device__ __forceinline__ void split4f(float4 x, float4& h, float4& l) {
    h.x = tf32_rd(x.x); l.x = tf32_rd(x.x - h.x);
    h.y = tf32_rd(x.y); l.y = tf32_rd(x.y - h.y);
    h.z = tf32_rd(x.z); l.z = tf32_rd(x.z - h.z);
    h.w = tf32_rd(x.w); l.w = tf32_rd(x.w - h.w);
}

#define MMA_TF32(c, a0v, a1v, a2v, a3v, b0v, b1v) \
    asm volatile("mma.sync.aligned.m16n8k8.row.col.f32.tf32.tf32.f32 " \
        "{%0,%1,%2,%3}, {%4,%5,%6,%7}, {%8,%9}, {%0,%1,%2,%3};" \
        : "+f"((c)[0]), "+f"((c)[1]), "+f"((c)[2]), "+f"((c)[3]) \
        : "r"(a0v), "r"(a1v), "r"(a2v), "r"(a3v), "r"(b0v), "r"(b1v))

__device__ __forceinline__ uint32_t smem_u32(const void* p) {
    uint32_t a;
    asm("{ .reg .u64 t; cvta.to.shared.u64 t, %1; cvt.u32.u64 %0, t; }" : "=r"(a) : "l"(p));
    return a;
}
#define CP_ASYNC16(saddr, gptr) \
    asm volatile("cp.async.cg.shared.global [%0], [%1], 16;" :: "r"(saddr), "l"(gptr))
#define CP_COMMIT() asm volatile("cp.async.commit_group;" ::: "memory")
#define CP_WAIT(n)  asm volatile("cp.async.wait_group %0;" :: "n"(n) : "memory")

// ===========================================================================
// Prologue kernels
// ===========================================================================
__global__ __launch_bounds__(256)
void split_elem(const float* __restrict__ in, float* __restrict__ hi,
                float* __restrict__ lo, int n4)
{
    int i = blockIdx.x * 256 + threadIdx.x;
    if (i < n4) {
        float4 v = ((const float4*)in)[i];
        float4 h, l; split4f(v, h, l);
        ((float4*)hi)[i] = h;
        ((float4*)lo)[i] = l;
    }
}

// out_{hi,lo}[c][r] = split(in[r][c]),  R rows x C cols input
__global__ __launch_bounds__(256)
void transpose_split(const float* __restrict__ in, float* __restrict__ ohi,
                     float* __restrict__ olo, int R, int C)
{
    __shared__ float t[32][33];
    int x  = blockIdx.x * 32 + threadIdx.x;
    int y0 = blockIdx.y * 32 + threadIdx.y;
#pragma unroll
    for (int i = 0; i < 32; i += 8)
        t[threadIdx.y + i][threadIdx.x] = in[(size_t)(y0 + i) * C + x];
    __syncthreads();
    int x2 = blockIdx.y * 32 + threadIdx.x;
    int y2 = blockIdx.x * 32 + threadIdx.y;
#pragma unroll
    for (int i = 0; i < 32; i += 8) {
        float v = t[threadIdx.x][threadIdx.y + i];
        float h = tf32_rd(v);
        ohi[(size_t)(y2 + i) * R + x2] = h;
        olo[(size_t)(y2 + i) * R + x2] = tf32_rd(v - h);
    }
}

// ===========================================================================
// HMMA tf32 GEMM v3 (3xTF32, fully pre-split operands):
//   D[M,N] = (Ahi+Alo)[M,K] @ (Bhi+Blo)[N,K]^T + bias
//   Tile 128x128, BK=16, 4-matrix double-buffered cp.async. Zero in-loop cvt.
// ===========================================================================
#define G3LD 20                        // row stride (16 + pad4); conflict-free
#define G3STG (128*G3LD)               // 2560 floats per matrix per stage
#define GEMM_SMEM_V3 (8*G3STG*4)       // 2 stages x 4 matrices = 81920 B

template<int NTOT, bool QKV>
__global__ __launch_bounds__(256, 2)
void hmma_gemm(const float* __restrict__ Ahi, const float* __restrict__ Alo,
               const float* __restrict__ Bhi, const float* __restrict__ Blo,
               const float* __restrict__ bias, float* __restrict__ out)
{
    extern __shared__ float smg[];
    const uint32_t sbase = smem_u32(smg);

    const int tid  = threadIdx.x;
    const int lane = tid & 31;
    const int wid  = tid >> 5;
    const int wm   = wid & 1;
    const int wn   = wid >> 1;
    const int m0   = blockIdx.y * 128;
    const int n0   = blockIdx.x * 128;
    const int g    = lane >> 2;
    const int tig  = lane & 3;

    const float* src[4];
    src[0] = Ahi + (size_t)m0 * 1024;
    src[1] = Alo + (size_t)m0 * 1024;
    src[2] = Bhi + (size_t)n0 * 1024;
    src[3] = Blo + (size_t)n0 * 1024;

    float acc[4][4][4];
#pragma unroll
    for (int i = 0; i < 4; i++)
#pragma unroll
        for (int j = 0; j < 4; j++)
#pragma unroll
            for (int e = 0; e < 4; e++) acc[i][j][e] = 0.f;

    const int crow = tid >> 2;          // 0..63
    const int cc4  = tid & 3;           // float4 col 0..3

#pragma unroll 1
    for (int kc = -1; kc < 64; kc++) {
        const int knext = kc + 1;
        if (knext < 64) {
            const int s = knext & 1;
            const uint32_t stg = sbase + s * 4 * G3STG * 4;
#pragma unroll
            for (int m = 0; m < 4; m++) {
#pragma unroll
                for (int i = 0; i < 2; i++) {
                    const int row = crow + i * 64;
                    const uint32_t so = stg + (uint32_t)(m * G3STG + row * G3LD + cc4 * 4) * 4u;
                    CP_ASYNC16(so, src[m] + (size_t)row * 1024 + knext * 16 + cc4 * 4);
                }
            }
            CP_COMMIT();
        }
        if (kc < 0) continue;

        if (knext < 64) CP_WAIT(1); else CP_WAIT(0);
        __syncthreads();

        const float* st = smg + (kc & 1) * 4 * G3STG;
        const float* Ah = st;
        const float* Al = st + G3STG;
        const float* Bh = st + 2 * G3STG;
        const float* Bl = st + 3 * G3STG;

#pragma unroll
        for (int ks = 0; ks < 2; ks++) {
            const int k0 = ks * 8;
            uint32_t ah[4][4], al[4][4];
#pragma unroll
            for (int mt = 0; mt < 4; mt++) {
                const int r  = wm * 64 + mt * 16;
                const int i0 = (r + g)     * G3LD + k0 + tig;
                const int i1 = (r + 8 + g) * G3LD + k0 + tig;
                ah[mt][0] = __float_as_uint(Ah[i0]);
                ah[mt][1] = __float_as_uint(Ah[i1]);
                ah[mt][2] = __float_as_uint(Ah[i0 + 4]);
                ah[mt][3] = __float_as_uint(Ah[i1 + 4]);
                al[mt][0] = __float_as_uint(Al[i0]);
                al[mt][1] = __float_as_uint(Al[i1]);
                al[mt][2] = __float_as_uint(Al[i0 + 4]);
                al[mt][3] = __float_as_uint(Al[i1 + 4]);
            }
#pragma unroll
            for (int nt = 0; nt < 4; nt++) {
                const int nb = (wn * 32 + nt * 8 + g) * G3LD + k0 + tig;
                const uint32_t bh0 = __float_as_uint(Bh[nb]);
                const uint32_t bh1 = __float_as_uint(Bh[nb + 4]);
                const uint32_t bl0 = __float_as_uint(Bl[nb]);
                const uint32_t bl1 = __float_as_uint(Bl[nb + 4]);
#pragma unroll
                for (int mt = 0; mt < 4; mt++) {
                    MMA_TF32(acc[mt][nt], ah[mt][0], ah[mt][1], ah[mt][2], ah[mt][3], bh0, bh1);
                    MMA_TF32(acc[mt][nt], al[mt][0], al[mt][1], al[mt][2], al[mt][3], bh0, bh1);
                    MMA_TF32(acc[mt][nt], ah[mt][0], ah[mt][1], ah[mt][2], ah[mt][3], bl0, bl1);
                }
            }
        }
        __syncthreads();
    }

    // ---- epilogue ----
#pragma unroll
    for (int mt = 0; mt < 4; mt++) {
#pragma unroll
        for (int nt = 0; nt < 4; nt++) {
            const int n = n0 + wn * 32 + nt * 8 + tig * 2;
            const float bx = bias[n], by = bias[n + 1];
#pragma unroll
            for (int half = 0; half < 2; half++) {
                const int m = m0 + wm * 64 + mt * 16 + g + half * 8;
                float2 v;
                v.x = acc[mt][nt][half * 2 + 0] + bx;
                v.y = acc[mt][nt][half * 2 + 1] + by;
                if (QKV) {
                    const int bb = m >> 11;
                    const int tt = m & (T_ - 1);
                    const int which = n >> 10;
                    const int cc = n & (C_ - 1);
                    const int h = cc >> 6;
                    const int d = cc & (HD_ - 1);
                    float* dst = (which == 0) ? g_q : (which == 1) ? g_k : g_v;
                    *(float2*)&dst[(((size_t)(bb * NH_ + h)) * T_ + tt) * HD_ + d] = v;
                } else {
                    *(float2*)&out[(size_t)m * NTOT + n] = v;
                }
            }
        }
    }
}

// ===========================================================================
// HMMA flash attention v3: Q fragments split once into registers,
// K/V split-staged (each element split once). Writes split output.
// Float offsets: Qs 0(4352), Khi 4352(2176), Klo 6528(2176),
//   Vhi 8704(2304), Vlo 11008(2304), Ps 13312(2304),
//   rowm 15616, rowl 15680, smax 15744(128), ssum 15872(128)  -> 16000 floats
// ===========================================================================
#define FQ_LD 68
#define FK_LD 68
#define FV_LD 72
#define FP_LD 36
#define FL_SMEM (16000 * 4)

__global__ __launch_bounds__(256, 2)
void flash_hmma()
{
    extern __shared__ float sm[];
    float* Qs   = sm;
    float* Khi  = sm + 4352;
    float* Klo  = sm + 6528;
    float* Vhi  = sm + 8704;
    float* Vlo  = sm + 11008;
    float* Ps   = sm + 13312;
    float* rowm = sm + 15616;
    float* rowl = sm + 15680;
    float* smax = sm + 15744;
    float* ssum = sm + 15872;

    const int tid  = threadIdx.x;
    const int lane = tid & 31;
    const int wid  = tid >> 5;
    const int wm   = wid & 3;
    const int wn   = wid >> 2;
    const int g    = lane >> 2;
    const int tig  = lane & 3;

    const int qi = blockIdx.x;
    const int bh = blockIdx.y;
    const int q0 = qi * 64;

    const float* Qg = g_q + (size_t)bh * T_ * HD_ + (size_t)q0 * HD_;
    const float* Kg = g_k + (size_t)bh * T_ * HD_;
    const float* Vg = g_v + (size_t)bh * T_ * HD_;

    // stage Q raw
#pragma unroll
    for (int it = 0; it < 4; it++) {
        const int idx = tid + it * 256;
        const int r = idx >> 4, c4 = idx & 15;
        *(float4*)&Qs[r * FQ_LD + c4 * 4] = *(const float4*)(Qg + r * HD_ + c4 * 4);
    }
    if (tid < 64) { rowm[tid] = -INFINITY; rowl[tid] = 0.f; }

    const int rlo = wm * 16 + g;
    const int rhi = rlo + 8;
    __syncthreads();

    // hoist Q fragments: split once into registers (loop-invariant)
    uint32_t qah[8][4], qal[8][4];
#pragma unroll
    for (int ks = 0; ks < 8; ks++) {
        const int k0 = ks * 8;
        const int a0i = rlo * FQ_LD + k0 + tig;
        const int a1i = rhi * FQ_LD + k0 + tig;
        const float v0 = Qs[a0i], v1 = Qs[a1i], v2 = Qs[a0i + 4], v3 = Qs[a1i + 4];
        SPLIT(v0, qah[ks][0], qal[ks][0]);
        SPLIT(v1, qah[ks][1], qal[ks][1]);
        SPLIT(v2, qah[ks][2], qal[ks][2]);
        SPLIT(v3, qah[ks][3], qal[ks][3]);
    }

    float o[4][4];
#pragma unroll
    for (int nt = 0; nt < 4; nt++)
#pragma unroll
        for (int e = 0; e < 4; e++) o[nt][e] = 0.f;

    const int nkt = 2 * qi + 2;
    for (int kt = 0; kt < nkt; kt++) {
        // split-stage K,V (each element split exactly once)
#pragma unroll
        for (int it = 0; it < 2; it++) {
            const int idx = tid + it * 256;
            const int r = idx >> 4, c4 = idx & 15;
            float4 kv = *(const float4*)(Kg + (size_t)(kt * 32 + r) * HD_ + c4 * 4);
            float4 h, l; split4f(kv, h, l);
            *(float4*)&Khi[r * FK_LD + c4 * 4] = h;
            *(float4*)&Klo[r * FK_LD + c4 * 4] = l;
            float4 vv = *(const float4*)(Vg + (size_t)(kt * 32 + r) * HD_ + c4 * 4);
            split4f(vv, h, l);
            *(float4*)&Vhi[r * FV_LD + c4 * 4] = h;
            *(float4*)&Vlo[r * FV_LD + c4 * 4] = l;
        }
        __syncthreads();   // (A)

        // ---- S = Q @ K^T (3xTF32), zero cvt ----
        float s[2][4];
#pragma unroll
        for (int nt = 0; nt < 2; nt++)
#pragma unroll
            for (int e = 0; e < 4; e++) s[nt][e] = 0.f;

#pragma unroll
        for (int ks = 0; ks < 8; ks++) {
            const int k0 = ks * 8;
#pragma unroll
            for (int nt = 0; nt < 2; nt++) {
                const int nb = (wn * 16 + nt * 8 + g) * FK_LD + k0 + tig;
                const uint32_t bh0 = __float_as_uint(Khi[nb]);
                const uint32_t bh1 = __float_as_uint(Khi[nb + 4]);
                const uint32_t bl0 = __float_as_uint(Klo[nb]);
                const uint32_t bl1 = __float_as_uint(Klo[nb + 4]);
                MMA_TF32(s[nt], qah[ks][0], qah[ks][1], qah[ks][2], qah[ks][3], bh0, bh1);
                MMA_TF32(s[nt], qal[ks][0], qal[ks][1], qal[ks][2], qal[ks][3], bh0, bh1);
                MMA_TF32(s[nt], qah[ks][0], qah[ks][1], qah[ks][2], qah[ks][3], bl0, bl1);
            }
        }

        // ---- scale + causal mask + row max ----
        const int qrow_lo = q0 + rlo;
        const int qrow_hi = q0 + rhi;
        float mlo = -INFINITY, mhi = -INFINITY;
#pragma unroll
        for (int nt = 0; nt < 2; nt++) {
            const int colb = kt * 32 + wn * 16 + nt * 8 + 2 * tig;
#pragma unroll
            for (int j = 0; j < 2; j++) {
                float v0 = s[nt][j] * 0.125f;
                if (colb + j > qrow_lo) v0 = -INFINITY;
                s[nt][j] = v0;
                mlo = fmaxf(mlo, v0);
                float v1 = s[nt][2 + j] * 0.125f;
                if (colb + j > qrow_hi) v1 = -INFINITY;
                s[nt][2 + j] = v1;
                mhi = fmaxf(mhi, v1);
            }
        }
#pragma unroll
        for (int off = 1; off < 4; off <<= 1) {
            mlo = fmaxf(mlo, __shfl_xor_sync(0xffffffffu, mlo, off));
            mhi = fmaxf(mhi, __shfl_xor_sync(0xffffffffu, mhi, off));
        }
        if (tig == 0) { smax[wn * 64 + rlo] = mlo; smax[wn * 64 + rhi] = mhi; }
        __syncthreads();   // (B)

        // ---- combine stats, exp, write P ----
        const float mold_lo = rowm[rlo];
        const float mold_hi = rowm[rhi];
        const float mnew_lo = fmaxf(mold_lo, fmaxf(smax[rlo], smax[64 + rlo]));
        const float mnew_hi = fmaxf(mold_hi, fmaxf(smax[rhi], smax[64 + rhi]));
        const float corr_lo = __expf(mold_lo - mnew_lo);
        const float corr_hi = __expf(mold_hi - mnew_hi);

        float sumlo = 0.f, sumhi = 0.f;
#pragma unroll
        for (int nt = 0; nt < 2; nt++) {
            float p0 = __expf(s[nt][0] - mnew_lo);
            float p1 = __expf(s[nt][1] - mnew_lo);
            float p2 = __expf(s[nt][2] - mnew_hi);
            float p3 = __expf(s[nt][3] - mnew_hi);
            sumlo += p0 + p1;
            sumhi += p2 + p3;
            const int col = wn * 16 + nt * 8 + 2 * tig;
            float2 w0; w0.x = tf32_rd(p0); w0.y = tf32_rd(p1);
            float2 w1; w1.x = tf32_rd(p2); w1.y = tf32_rd(p3);
            *(float2*)&Ps[rlo * FP_LD + col] = w0;
            *(float2*)&Ps[rhi * FP_LD + col] = w1;
        }
#pragma unroll
        for (int off = 1; off < 4; off <<= 1) {
            sumlo += __shfl_xor_sync(0xffffffffu, sumlo, off);
            sumhi += __shfl_xor_sync(0xffffffffu, sumhi, off);
        }
        if (tig == 0) { ssum[wn * 64 + rlo] = sumlo; ssum[wn * 64 + rhi] = sumhi; }

#pragma unroll
        for (int nt = 0; nt < 4; nt++) {
            o[nt][0] *= corr_lo; o[nt][1] *= corr_lo;
            o[nt][2] *= corr_hi; o[nt][3] *= corr_hi;
        }
        __syncthreads();   // (C)

        if (tid < 64) {
            const int r = tid;
            const float mo = rowm[r];
            const float mn = fmaxf(mo, fmaxf(smax[r], smax[64 + r]));
            const float c  = __expf(mo - mn);
            rowl[r] = rowl[r] * c + ssum[r] + ssum[64 + r];
            rowm[r] = mn;
        }

        // ---- O += P @ V (V pre-split in smem) ----
#pragma unroll
        for (int ks = 0; ks < 4; ks++) {
            const int k0 = ks * 8;
            const int a0i = rlo * FP_LD + k0 + tig;
            const int a1i = rhi * FP_LD + k0 + tig;
            const uint32_t a0 = __float_as_uint(Ps[a0i]);
            const uint32_t a1 = __float_as_uint(Ps[a1i]);
            const uint32_t a2 = __float_as_uint(Ps[a0i + 4]);
            const uint32_t a3 = __float_as_uint(Ps[a1i + 4]);
#pragma unroll
            for (int nt = 0; nt < 4; nt++) {
                const int nb0 = (k0 + tig)     * FV_LD + wn * 32 + nt * 8 + g;
                const int nb1 = (k0 + tig + 4) * FV_LD + wn * 32 + nt * 8 + g;
                const uint32_t vh0 = __float_as_uint(Vhi[nb0]);
                const uint32_t vh1 = __float_as_uint(Vhi[nb1]);
                const uint32_t vl0 = __float_as_uint(Vlo[nb0]);
                const uint32_t vl1 = __float_as_uint(Vlo[nb1]);
                MMA_TF32(o[nt], a0, a1, a2, a3, vh0, vh1);
                MMA_TF32(o[nt], a0, a1, a2, a3, vl0, vl1);
            }
        }
        __syncthreads();   // (D)
    }

    // ---- normalize + store SPLIT output for projection GEMM ----
    const float inv_lo = 1.f / rowl[rlo];
    const float inv_hi = 1.f / rowl[rhi];
    const int b = bh >> 4, h = bh & 15;
    const int t_lo = q0 + rlo, t_hi = q0 + rhi;
#pragma unroll
    for (int nt = 0; nt < 4; nt++) {
        const int d = wn * 32 + nt * 8 + 2 * tig;
        float v00 = o[nt][0] * inv_lo, v01 = o[nt][1] * inv_lo;
        float v10 = o[nt][2] * inv_hi, v11 = o[nt][3] * inv_hi;
        float2 h0, l0, h1, l1;
        h0.x = tf32_rd(v00); l0.x = tf32_rd(v00 - h0.x);
        h0.y = tf32_rd(v01); l0.y = tf32_rd(v01 - h0.y);
        h1.x = tf32_rd(v10); l1.x = tf32_rd(v10 - h1.x);
        h1.y = tf32_rd(v11); l1.y = tf32_rd(v11 - h1.y);
        const size_t o_lo = ((size_t)(b * T_ + t_lo)) * C_ + h * HD_ + d;
        const size_t o_hi = ((size_t)(b * T_ + t_hi)) * C_ + h * HD_ + d;
        *(float2*)&g_ahi[o_lo] = h0;
        *(float2*)&g_alo[o_lo] = l0;
        *(float2*)&g_ahi[o_hi] = h1;
        *(float2*)&g_alo[o_hi] = l1;
    }
}

// ===========================================================================
// Launch
// ===========================================================================
extern "C" void kernel_launch(void* const* d_in, const int* in_sizes, int n_in,
                              void* d_out, int out_size)
{
    const float* x      = (const float*)d_in[0];
    const float* w_attn = (const float*)d_in[1];
    const float* b_attn = (const float*)d_in[2];
    const float* w_proj = (const float*)d_in[3];
    const float* b_proj = (const float*)d_in[4];
    float* out = (float*)d_out;

    float *xhi, *xlo, *ahi, *alo, *wthi, *wtlo, *wphi, *wplo;
    cudaGetSymbolAddress((void**)&xhi,  g_xhi);
    cudaGetSymbolAddress((void**)&xlo,  g_xlo);
    cudaGetSymbolAddress((void**)&ahi,  g_ahi);
    cudaGetSymbolAddress((void**)&alo,  g_alo);
    cudaGetSymbolAddress((void**)&wthi, g_wthi);
    cudaGetSymbolAddress((void**)&wtlo, g_wtlo);
    cudaGetSymbolAddress((void**)&wphi, g_wphi);
    cudaGetSymbolAddress((void**)&wplo, g_wplo);

    cudaFuncSetAttribute(flash_hmma,
                         cudaFuncAttributeMaxDynamicSharedMemorySize, FL_SMEM);
    cudaFuncSetAttribute(hmma_gemm<3072, true>,
                         cudaFuncAttributeMaxDynamicSharedMemorySize, GEMM_SMEM_V3);
    cudaFuncSetAttribute(hmma_gemm<1024, false>,
                         cudaFuncAttributeMaxDynamicSharedMemorySize, GEMM_SMEM_V3);

    // Prologue: split x; transpose+split weights
    split_elem<<<(M_*C_/4 + 255)/256, 256>>>(x, xhi, xlo, M_*C_/4);
    transpose_split<<<dim3(3072/32, 1024/32), dim3(32, 8)>>>(w_attn, wthi, wtlo, 1024, 3072);
    transpose_split<<<dim3(1024/32, 1024/32), dim3(32, 8)>>>(w_proj, wphi, wplo, 1024, 1024);

    // QKV GEMM
    hmma_gemm<3072, true><<<dim3(3072/128, M_/128), 256, GEMM_SMEM_V3>>>(
        xhi, xlo, wthi, wtlo, b_attn, nullptr);

    // Flash attention (writes split att)
    flash_hmma<<<dim3(T_/64, B_*NH_), 256, FL_SMEM>>>();

    // Output projection
    hmma_gemm<1024, false><<<dim3(1024/128, M_/128), 256, GEMM_SMEM_V3>>>(
        ahi, alo, wphi, wplo, b_proj, out);
}

// round 8
// speedup vs baseline: 1.5274x; 1.5274x over previous
#include <cuda_runtime.h>
#include <cuda.h>
#include <math.h>
#include <stdint.h>

#define B_   4
#define T_   2048
#define C_   1024
#define NH_  16
#define HD_  64
#define M_   (B_*T_)      // 8192

// Scratch (allocation-free: __device__ globals)
__device__ float g_q[B_*NH_*T_*HD_];
__device__ float g_k[B_*NH_*T_*HD_];
__device__ float g_v[B_*NH_*T_*HD_];
__device__ float g_xhi[M_*C_],  g_xlo[M_*C_];      // split x
__device__ float g_ahi[M_*C_],  g_alo[M_*C_];      // split attention output
__device__ float g_wthi[3*C_*C_], g_wtlo[3*C_*C_]; // w_attn^T split
__device__ float g_wphi[C_*C_],   g_wplo[C_*C_];   // w_proj^T split

// ===========================================================================
// Helpers
// ===========================================================================
__device__ __forceinline__ float tf32_rd(float x) {
    uint32_t u; asm("cvt.rna.tf32.f32 %0, %1;" : "=r"(u) : "f"(x));
    return __uint_as_float(u);
}
#define SPLIT(raw, hi, lo) do { \
    float _h = tf32_rd(raw); \
    hi = __float_as_uint(_h); \
    lo = __float_as_uint(tf32_rd((raw) - _h)); \
} while (0)
__device__ __forceinline__ void split4f(float4 x, float4& h, float4& l) {
    h.x = tf32_rd(x.x); l.x = tf32_rd(x.x - h.x);
    h.y = tf32_rd(x.y); l.y = tf32_rd(x.y - h.y);
    h.z = tf32_rd(x.z); l.z = tf32_rd(x.z - h.z);
    h.w = tf32_rd(x.w); l.w = tf32_rd(x.w - h.w);
}

#define MMA_TF32(c, a0v, a1v, a2v, a3v, b0v, b1v) \
    asm volatile("mma.sync.aligned.m16n8k8.row.col.f32.tf32.tf32.f32 " \
        "{%0,%1,%2,%3}, {%4,%5,%6,%7}, {%8,%9}, {%0,%1,%2,%3};" \
        : "+f"((c)[0]), "+f"((c)[1]), "+f"((c)[2]), "+f"((c)[3]) \
        : "r"(a0v), "r"(a1v), "r"(a2v), "r"(a3v), "r"(b0v), "r"(b1v))

__device__ __forceinline__ uint32_t smem_u32(const void* p) {
    uint32_t a;
    asm("{ .reg .u64 t; cvta.to.shared.u64 t, %1; cvt.u32.u64 %0, t; }" : "=r"(a) : "l"(p));
    return a;
}
#define CP_ASYNC16(saddr, gptr) \
    asm volatile("cp.async.cg.shared.global [%0], [%1], 16;" :: "r"(saddr), "l"(gptr))
#define CP_COMMIT() asm volatile("cp.async.commit_group;" ::: "memory")
#define CP_WAIT(n)  asm volatile("cp.async.wait_group %0;" :: "n"(n) : "memory")

// ===========================================================================
// Prologue kernels
// ===========================================================================
__global__ __launch_bounds__(256)
void split_elem(const float* __restrict__ in, float* __restrict__ hi,
                float* __restrict__ lo, int n4)
{
    int i = blockIdx.x * 256 + threadIdx.x;
    if (i < n4) {
        float4 v = ((const float4*)in)[i];
        float4 h, l; split4f(v, h, l);
        ((float4*)hi)[i] = h;
        ((float4*)lo)[i] = l;
    }
}

// out_{hi,lo}[c][r] = split(in[r][c]),  R rows x C cols input
__global__ __launch_bounds__(256)
void transpose_split(const float* __restrict__ in, float* __restrict__ ohi,
                     float* __restrict__ olo, int R, int C)
{
    __shared__ float t[32][33];
    int x  = blockIdx.x * 32 + threadIdx.x;
    int y0 = blockIdx.y * 32 + threadIdx.y;
#pragma unroll
    for (int i = 0; i < 32; i += 8)
        t[threadIdx.y + i][threadIdx.x] = in[(size_t)(y0 + i) * C + x];
    __syncthreads();
    int x2 = blockIdx.y * 32 + threadIdx.x;
    int y2 = blockIdx.x * 32 + threadIdx.y;
#pragma unroll
    for (int i = 0; i < 32; i += 8) {
        float v = t[threadIdx.x][threadIdx.y + i];
        float h = tf32_rd(v);
        ohi[(size_t)(y2 + i) * R + x2] = h;
        olo[(size_t)(y2 + i) * R + x2] = tf32_rd(v - h);
    }
}

// ===========================================================================
// HMMA tf32 GEMM v3 (3xTF32, fully pre-split operands):
//   D[M,N] = (Ahi+Alo)[M,K] @ (Bhi+Blo)[N,K]^T + bias
//   Tile 128x128, BK=16, 4-matrix double-buffered cp.async. Zero in-loop cvt.
// ===========================================================================
#define G3LD 20                        // row stride (16 + pad4); conflict-free
#define G3STG (128*G3LD)               // 2560 floats per matrix per stage
#define GEMM_SMEM_V3 (8*G3STG*4)       // 2 stages x 4 matrices = 81920 B

template<int NTOT, bool QKV>
__global__ __launch_bounds__(256, 2)
void hmma_gemm(const float* __restrict__ Ahi, const float* __restrict__ Alo,
               const float* __restrict__ Bhi, const float* __restrict__ Blo,
               const float* __restrict__ bias, float* __restrict__ out)
{
    extern __shared__ float smg[];
    const uint32_t sbase = smem_u32(smg);

    const int tid  = threadIdx.x;
    const int lane = tid & 31;
    const int wid  = tid >> 5;
    const int wm   = wid & 1;
    const int wn   = wid >> 1;
    const int m0   = blockIdx.y * 128;
    const int n0   = blockIdx.x * 128;
    const int g    = lane >> 2;
    const int tig  = lane & 3;

    const float* src[4];
    src[0] = Ahi + (size_t)m0 * 1024;
    src[1] = Alo + (size_t)m0 * 1024;
    src[2] = Bhi + (size_t)n0 * 1024;
    src[3] = Blo + (size_t)n0 * 1024;

    float acc[4][4][4];
#pragma unroll
    for (int i = 0; i < 4; i++)
#pragma unroll
        for (int j = 0; j < 4; j++)
#pragma unroll
            for (int e = 0; e < 4; e++) acc[i][j][e] = 0.f;

    const int crow = tid >> 2;          // 0..63
    const int cc4  = tid & 3;           // float4 col 0..3

#pragma unroll 1
    for (int kc = -1; kc < 64; kc++) {
        const int knext = kc + 1;
        if (knext < 64) {
            const int s = knext & 1;
            const uint32_t stg = sbase + s * 4 * G3STG * 4;
#pragma unroll
            for (int m = 0; m < 4; m++) {
#pragma unroll
                for (int i = 0; i < 2; i++) {
                    const int row = crow + i * 64;
                    const uint32_t so = stg + (uint32_t)(m * G3STG + row * G3LD + cc4 * 4) * 4u;
                    CP_ASYNC16(so, src[m] + (size_t)row * 1024 + knext * 16 + cc4 * 4);
                }
            }
            CP_COMMIT();
        }
        if (kc < 0) continue;

        if (knext < 64) CP_WAIT(1); else CP_WAIT(0);
        __syncthreads();

        const float* st = smg + (kc & 1) * 4 * G3STG;
        const float* Ah = st;
        const float* Al = st + G3STG;
        const float* Bh = st + 2 * G3STG;
        const float* Bl = st + 3 * G3STG;

#pragma unroll
        for (int ks = 0; ks < 2; ks++) {
            const int k0 = ks * 8;
            uint32_t ah[4][4], al[4][4];
#pragma unroll
            for (int mt = 0; mt < 4; mt++) {
                const int r  = wm * 64 + mt * 16;
                const int i0 = (r + g)     * G3LD + k0 + tig;
                const int i1 = (r + 8 + g) * G3LD + k0 + tig;
                ah[mt][0] = __float_as_uint(Ah[i0]);
                ah[mt][1] = __float_as_uint(Ah[i1]);
                ah[mt][2] = __float_as_uint(Ah[i0 + 4]);
                ah[mt][3] = __float_as_uint(Ah[i1 + 4]);
                al[mt][0] = __float_as_uint(Al[i0]);
                al[mt][1] = __float_as_uint(Al[i1]);
                al[mt][2] = __float_as_uint(Al[i0 + 4]);
                al[mt][3] = __float_as_uint(Al[i1 + 4]);
            }
#pragma unroll
            for (int nt = 0; nt < 4; nt++) {
                const int nb = (wn * 32 + nt * 8 + g) * G3LD + k0 + tig;
                const uint32_t bh0 = __float_as_uint(Bh[nb]);
                const uint32_t bh1 = __float_as_uint(Bh[nb + 4]);
                const uint32_t bl0 = __float_as_uint(Bl[nb]);
                const uint32_t bl1 = __float_as_uint(Bl[nb + 4]);
#pragma unroll
                for (int mt = 0; mt < 4; mt++) {
                    MMA_TF32(acc[mt][nt], ah[mt][0], ah[mt][1], ah[mt][2], ah[mt][3], bh0, bh1);
                    MMA_TF32(acc[mt][nt], al[mt][0], al[mt][1], al[mt][2], al[mt][3], bh0, bh1);
                    MMA_TF32(acc[mt][nt], ah[mt][0], ah[mt][1], ah[mt][2], ah[mt][3], bl0, bl1);
                }
            }
        }
        __syncthreads();
    }

    // ---- epilogue ----
#pragma unroll
    for (int mt = 0; mt < 4; mt++) {
#pragma unroll
        for (int nt = 0; nt < 4; nt++) {
            const int n = n0 + wn * 32 + nt * 8 + tig * 2;
            const float bx = bias[n], by = bias[n + 1];
#pragma unroll
            for (int half = 0; half < 2; half++) {
                const int m = m0 + wm * 64 + mt * 16 + g + half * 8;
                float2 v;
                v.x = acc[mt][nt][half * 2 + 0] + bx;
                v.y = acc[mt][nt][half * 2 + 1] + by;
                if (QKV) {
                    const int bb = m >> 11;
                    const int tt = m & (T_ - 1);
                    const int which = n >> 10;
                    const int cc = n & (C_ - 1);
                    const int h = cc >> 6;
                    const int d = cc & (HD_ - 1);
                    float* dst = (which == 0) ? g_q : (which == 1) ? g_k : g_v;
                    *(float2*)&dst[(((size_t)(bb * NH_ + h)) * T_ + tt) * HD_ + d] = v;
                } else {
                    *(float2*)&out[(size_t)m * NTOT + n] = v;
                }
            }
        }
    }
}

// ===========================================================================
// HMMA flash attention v3: Q fragments split once into registers,
// K/V split-staged (each element split once). Writes split output.
// Float offsets: Qs 0(4352), Khi 4352(2176), Klo 6528(2176),
//   Vhi 8704(2304), Vlo 11008(2304), Ps 13312(2304),
//   rowm 15616, rowl 15680, smax 15744(128), ssum 15872(128)  -> 16000 floats
// ===========================================================================
#define FQ_LD 68
#define FK_LD 68
#define FV_LD 72
#define FP_LD 36
#define FL_SMEM (16000 * 4)

__global__ __launch_bounds__(256, 2)
void flash_hmma()
{
    extern __shared__ float sm[];
    float* Qs   = sm;
    float* Khi  = sm + 4352;
    float* Klo  = sm + 6528;
    float* Vhi  = sm + 8704;
    float* Vlo  = sm + 11008;
    float* Ps   = sm + 13312;
    float* rowm = sm + 15616;
    float* rowl = sm + 15680;
    float* smax = sm + 15744;
    float* ssum = sm + 15872;

    const int tid  = threadIdx.x;
    const int lane = tid & 31;
    const int wid  = tid >> 5;
    const int wm   = wid & 3;
    const int wn   = wid >> 2;
    const int g    = lane >> 2;
    const int tig  = lane & 3;

    const int qi = blockIdx.x;
    const int bh = blockIdx.y;
    const int q0 = qi * 64;

    const float* Qg = g_q + (size_t)bh * T_ * HD_ + (size_t)q0 * HD_;
    const float* Kg = g_k + (size_t)bh * T_ * HD_;
    const float* Vg = g_v + (size_t)bh * T_ * HD_;

    // stage Q raw
#pragma unroll
    for (int it = 0; it < 4; it++) {
        const int idx = tid + it * 256;
        const int r = idx >> 4, c4 = idx & 15;
        *(float4*)&Qs[r * FQ_LD + c4 * 4] = *(const float4*)(Qg + r * HD_ + c4 * 4);
    }
    if (tid < 64) { rowm[tid] = -INFINITY; rowl[tid] = 0.f; }

    const int rlo = wm * 16 + g;
    const int rhi = rlo + 8;
    __syncthreads();

    // hoist Q fragments: split once into registers (loop-invariant)
    uint32_t qah[8][4], qal[8][4];
#pragma unroll
    for (int ks = 0; ks < 8; ks++) {
        const int k0 = ks * 8;
        const int a0i = rlo * FQ_LD + k0 + tig;
        const int a1i = rhi * FQ_LD + k0 + tig;
        const float v0 = Qs[a0i], v1 = Qs[a1i], v2 = Qs[a0i + 4], v3 = Qs[a1i + 4];
        SPLIT(v0, qah[ks][0], qal[ks][0]);
        SPLIT(v1, qah[ks][1], qal[ks][1]);
        SPLIT(v2, qah[ks][2], qal[ks][2]);
        SPLIT(v3, qah[ks][3], qal[ks][3]);
    }

    float o[4][4];
#pragma unroll
    for (int nt = 0; nt < 4; nt++)
#pragma unroll
        for (int e = 0; e < 4; e++) o[nt][e] = 0.f;

    const int nkt = 2 * qi + 2;
    for (int kt = 0; kt < nkt; kt++) {
        // split-stage K,V (each element split exactly once)
#pragma unroll
        for (int it = 0; it < 2; it++) {
            const int idx = tid + it * 256;
            const int r = idx >> 4, c4 = idx & 15;
            float4 kv = *(const float4*)(Kg + (size_t)(kt * 32 + r) * HD_ + c4 * 4);
            float4 h, l; split4f(kv, h, l);
            *(float4*)&Khi[r * FK_LD + c4 * 4] = h;
            *(float4*)&Klo[r * FK_LD + c4 * 4] = l;
            float4 vv = *(const float4*)(Vg + (size_t)(kt * 32 + r) * HD_ + c4 * 4);
            split4f(vv, h, l);
            *(float4*)&Vhi[r * FV_LD + c4 * 4] = h;
            *(float4*)&Vlo[r * FV_LD + c4 * 4] = l;
        }
        __syncthreads();   // (A)

        // ---- S = Q @ K^T (3xTF32), zero cvt ----
        float s[2][4];
#pragma unroll
        for (int nt = 0; nt < 2; nt++)
#pragma unroll
            for (int e = 0; e < 4; e++) s[nt][e] = 0.f;

#pragma unroll
        for (int ks = 0; ks < 8; ks++) {
            const int k0 = ks * 8;
#pragma unroll
            for (int nt = 0; nt < 2; nt++) {
                const int nb = (wn * 16 + nt * 8 + g) * FK_LD + k0 + tig;
                const uint32_t bh0 = __float_as_uint(Khi[nb]);
                const uint32_t bh1 = __float_as_uint(Khi[nb + 4]);
                const uint32_t bl0 = __float_as_uint(Klo[nb]);
                const uint32_t bl1 = __float_as_uint(Klo[nb + 4]);
                MMA_TF32(s[nt], qah[ks][0], qah[ks][1], qah[ks][2], qah[ks][3], bh0, bh1);
                MMA_TF32(s[nt], qal[ks][0], qal[ks][1], qal[ks][2], qal[ks][3], bh0, bh1);
                MMA_TF32(s[nt], qah[ks][0], qah[ks][1], qah[ks][2], qah[ks][3], bl0, bl1);
            }
        }

        // ---- scale + causal mask + row max ----
        const int qrow_lo = q0 + rlo;
        const int qrow_hi = q0 + rhi;
        float mlo = -INFINITY, mhi = -INFINITY;
#pragma unroll
        for (int nt = 0; nt < 2; nt++) {
            const int colb = kt * 32 + wn * 16 + nt * 8 + 2 * tig;
#pragma unroll
            for (int j = 0; j < 2; j++) {
                float v0 = s[nt][j] * 0.125f;
                if (colb + j > qrow_lo) v0 = -INFINITY;
                s[nt][j] = v0;
                mlo = fmaxf(mlo, v0);
                float v1 = s[nt][2 + j] * 0.125f;
                if (colb + j > qrow_hi) v1 = -INFINITY;
                s[nt][2 + j] = v1;
                mhi = fmaxf(mhi, v1);
            }
        }
#pragma unroll
        for (int off = 1; off < 4; off <<= 1) {
            mlo = fmaxf(mlo, __shfl_xor_sync(0xffffffffu, mlo, off));
            mhi = fmaxf(mhi, __shfl_xor_sync(0xffffffffu, mhi, off));
        }
        if (tig == 0) { smax[wn * 64 + rlo] = mlo; smax[wn * 64 + rhi] = mhi; }
        __syncthreads();   // (B)

        // ---- combine stats, exp, write P ----
        const float mold_lo = rowm[rlo];
        const float mold_hi = rowm[rhi];
        const float mnew_lo = fmaxf(mold_lo, fmaxf(smax[rlo], smax[64 + rlo]));
        const float mnew_hi = fmaxf(mold_hi, fmaxf(smax[rhi], smax[64 + rhi]));
        const float corr_lo = __expf(mold_lo - mnew_lo);
        const float corr_hi = __expf(mold_hi - mnew_hi);

        float sumlo = 0.f, sumhi = 0.f;
#pragma unroll
        for (int nt = 0; nt < 2; nt++) {
            float p0 = __expf(s[nt][0] - mnew_lo);
            float p1 = __expf(s[nt][1] - mnew_lo);
            float p2 = __expf(s[nt][2] - mnew_hi);
            float p3 = __expf(s[nt][3] - mnew_hi);
            sumlo += p0 + p1;
            sumhi += p2 + p3;
            const int col = wn * 16 + nt * 8 + 2 * tig;
            float2 w0; w0.x = tf32_rd(p0); w0.y = tf32_rd(p1);
            float2 w1; w1.x = tf32_rd(p2); w1.y = tf32_rd(p3);
            *(float2*)&Ps[rlo * FP_LD + col] = w0;
            *(float2*)&Ps[rhi * FP_LD + col] = w1;
        }
#pragma unroll
        for (int off = 1; off < 4; off <<= 1) {
            sumlo += __shfl_xor_sync(0xffffffffu, sumlo, off);
            sumhi += __shfl_xor_sync(0xffffffffu, sumhi, off);
        }
        if (tig == 0) { ssum[wn * 64 + rlo] = sumlo; ssum[wn * 64 + rhi] = sumhi; }

#pragma unroll
        for (int nt = 0; nt < 4; nt++) {
            o[nt][0] *= corr_lo; o[nt][1] *= corr_lo;
            o[nt][2] *= corr_hi; o[nt][3] *= corr_hi;
        }
        __syncthreads();   // (C)

        if (tid < 64) {
            const int r = tid;
            const float mo = rowm[r];
            const float mn = fmaxf(mo, fmaxf(smax[r], smax[64 + r]));
            const float c  = __expf(mo - mn);
            rowl[r] = rowl[r] * c + ssum[r] + ssum[64 + r];
            rowm[r] = mn;
        }

        // ---- O += P @ V (V pre-split in smem) ----
#pragma unroll
        for (int ks = 0; ks < 4; ks++) {
            const int k0 = ks * 8;
            const int a0i = rlo * FP_LD + k0 + tig;
            const int a1i = rhi * FP_LD + k0 + tig;
            const uint32_t a0 = __float_as_uint(Ps[a0i]);
            const uint32_t a1 = __float_as_uint(Ps[a1i]);
            const uint32_t a2 = __float_as_uint(Ps[a0i + 4]);
            const uint32_t a3 = __float_as_uint(Ps[a1i + 4]);
#pragma unroll
            for (int nt = 0; nt < 4; nt++) {
                const int nb0 = (k0 + tig)     * FV_LD + wn * 32 + nt * 8 + g;
                const int nb1 = (k0 + tig + 4) * FV_LD + wn * 32 + nt * 8 + g;
                const uint32_t vh0 = __float_as_uint(Vhi[nb0]);
                const uint32_t vh1 = __float_as_uint(Vhi[nb1]);
                const uint32_t vl0 = __float_as_uint(Vlo[nb0]);
                const uint32_t vl1 = __float_as_uint(Vlo[nb1]);
                MMA_TF32(o[nt], a0, a1, a2, a3, vh0, vh1);
                MMA_TF32(o[nt], a0, a1, a2, a3, vl0, vl1);
            }
        }
        __syncthreads();   // (D)
    }

    // ---- normalize + store SPLIT output for projection GEMM ----
    const float inv_lo = 1.f / rowl[rlo];
    const float inv_hi = 1.f / rowl[rhi];
    const int b = bh >> 4, h = bh & 15;
    const int t_lo = q0 + rlo, t_hi = q0 + rhi;
#pragma unroll
    for (int nt = 0; nt < 4; nt++) {
        const int d = wn * 32 + nt * 8 + 2 * tig;
        float v00 = o[nt][0] * inv_lo, v01 = o[nt][1] * inv_lo;
        float v10 = o[nt][2] * inv_hi, v11 = o[nt][3] * inv_hi;
        float2 h0, l0, h1, l1;
        h0.x = tf32_rd(v00); l0.x = tf32_rd(v00 - h0.x);
        h0.y = tf32_rd(v01); l0.y = tf32_rd(v01 - h0.y);
        h1.x = tf32_rd(v10); l1.x = tf32_rd(v10 - h1.x);
        h1.y = tf32_rd(v11); l1.y = tf32_rd(v11 - h1.y);
        const size_t o_lo = ((size_t)(b * T_ + t_lo)) * C_ + h * HD_ + d;
        const size_t o_hi = ((size_t)(b * T_ + t_hi)) * C_ + h * HD_ + d;
        *(float2*)&g_ahi[o_lo] = h0;
        *(float2*)&g_alo[o_lo] = l0;
        *(float2*)&g_ahi[o_hi] = h1;
        *(float2*)&g_alo[o_hi] = l1;
    }
}

// ===========================================================================
// Launch
// ===========================================================================
extern "C" void kernel_launch(void* const* d_in, const int* in_sizes, int n_in,
                              void* d_out, int out_size)
{
    const float* x      = (const float*)d_in[0];
    const float* w_attn = (const float*)d_in[1];
    const float* b_attn = (const float*)d_in[2];
    const float* w_proj = (const float*)d_in[3];
    const float* b_proj = (const float*)d_in[4];
    float* out = (float*)d_out;

    float *xhi, *xlo, *ahi, *alo, *wthi, *wtlo, *wphi, *wplo;
    cudaGetSymbolAddress((void**)&xhi,  g_xhi);
    cudaGetSymbolAddress((void**)&xlo,  g_xlo);
    cudaGetSymbolAddress((void**)&ahi,  g_ahi);
    cudaGetSymbolAddress((void**)&alo,  g_alo);
    cudaGetSymbolAddress((void**)&wthi, g_wthi);
    cudaGetSymbolAddress((void**)&wtlo, g_wtlo);
    cudaGetSymbolAddress((void**)&wphi, g_wphi);
    cudaGetSymbolAddress((void**)&wplo, g_wplo);

    cudaFuncSetAttribute(flash_hmma,
                         cudaFuncAttributeMaxDynamicSharedMemorySize, FL_SMEM);
    cudaFuncSetAttribute(hmma_gemm<3072, true>,
                         cudaFuncAttributeMaxDynamicSharedMemorySize, GEMM_SMEM_V3);
    cudaFuncSetAttribute(hmma_gemm<1024, false>,
                         cudaFuncAttributeMaxDynamicSharedMemorySize, GEMM_SMEM_V3);

    // Prologue: split x; transpose+split weights
    split_elem<<<(M_*C_/4 + 255)/256, 256>>>(x, xhi, xlo, M_*C_/4);
    transpose_split<<<dim3(3072/32, 1024/32), dim3(32, 8)>>>(w_attn, wthi, wtlo, 1024, 3072);
    transpose_split<<<dim3(1024/32, 1024/32), dim3(32, 8)>>>(w_proj, wphi, wplo, 1024, 1024);

    // QKV GEMM
    hmma_gemm<3072, true><<<dim3(3072/128, M_/128), 256, GEMM_SMEM_V3>>>(
        xhi, xlo, wthi, wtlo, b_attn, nullptr);

    // Flash attention (writes split att)
    flash_hmma<<<dim3(T_/64, B_*NH_), 256, FL_SMEM>>>();

    // Output projection
    hmma_gemm<1024, false><<<dim3(1024/128, M_/128), 256, GEMM_SMEM_V3>>>(
        ahi, alo, wphi, wplo, b_proj, out);
}

// round 9
// speedup vs baseline: 2.6240x; 1.7180x over previous
#include <cuda_runtime.h>
#include <cuda.h>
#include <math.h>
#include <stdint.h>

#define B_   4
#define T_   2048
#define C_   1024
#define NH_  16
#define HD_  64
#define M_   (B_*T_)      // 8192
#define KW_  (C_/2)       // 512 packed words per K=1024 row

// Scratch (allocation-free: __device__ globals)
__device__ uint32_t g_qhi[B_*NH_*T_*HD_/2], g_qlo[B_*NH_*T_*HD_/2];
__device__ uint32_t g_khi[B_*NH_*T_*HD_/2], g_klo[B_*NH_*T_*HD_/2];
__device__ float    g_v  [B_*NH_*T_*HD_];
__device__ uint32_t g_xhi[M_*KW_],  g_xlo[M_*KW_];      // packed split x
__device__ uint32_t g_ahi[M_*KW_],  g_alo[M_*KW_];      // packed split attention out
__device__ uint32_t g_wthi[3*C_*KW_], g_wtlo[3*C_*KW_]; // w_attn^T packed split
__device__ uint32_t g_wphi[C_*KW_],   g_wplo[C_*KW_];   // w_proj^T packed split

// ===========================================================================
// Helpers
// ===========================================================================
// split pair (even,odd) into packed bf16x2 hi + residual lo.
// cvt.rn.bf16x2.f32 d, a, b  ->  d.hi = bf16(a), d.lo = bf16(b)
__device__ __forceinline__ void split2(float e, float o, uint32_t& hi, uint32_t& lo) {
    asm("cvt.rn.bf16x2.f32 %0, %1, %2;" : "=r"(hi) : "f"(o), "f"(e));
    float he = __uint_as_float(hi << 16);
    float ho = __uint_as_float(hi & 0xffff0000u);
    asm("cvt.rn.bf16x2.f32 %0, %1, %2;" : "=r"(lo) : "f"(o - ho), "f"(e - he));
}

#define MMA_BF16(c, a0v, a1v, a2v, a3v, b0v, b1v) \
    asm volatile("mma.sync.aligned.m16n8k16.row.col.f32.bf16.bf16.f32 " \
        "{%0,%1,%2,%3}, {%4,%5,%6,%7}, {%8,%9}, {%0,%1,%2,%3};" \
        : "+f"((c)[0]), "+f"((c)[1]), "+f"((c)[2]), "+f"((c)[3]) \
        : "r"(a0v), "r"(a1v), "r"(a2v), "r"(a3v), "r"(b0v), "r"(b1v))

__device__ __forceinline__ uint32_t smem_u32(const void* p) {
    uint32_t a;
    asm("{ .reg .u64 t; cvta.to.shared.u64 t, %1; cvt.u32.u64 %0, t; }" : "=r"(a) : "l"(p));
    return a;
}
#define CP_ASYNC16(saddr, gptr) \
    asm volatile("cp.async.cg.shared.global [%0], [%1], 16;" :: "r"(saddr), "l"(gptr))
#define CP_COMMIT() asm volatile("cp.async.commit_group;" ::: "memory")
#define CP_WAIT(n)  asm volatile("cp.async.wait_group %0;" :: "n"(n) : "memory")

// ===========================================================================
// Prologue kernels
// ===========================================================================
__global__ __launch_bounds__(256)
void split_pack_elem(const float* __restrict__ in, uint32_t* __restrict__ hi,
                     uint32_t* __restrict__ lo, int n4)
{
    int i = blockIdx.x * 256 + threadIdx.x;
    if (i < n4) {
        float4 v = ((const float4*)in)[i];
        uint2 h, l;
        split2(v.x, v.y, h.x, l.x);
        split2(v.z, v.w, h.y, l.y);
        ((uint2*)hi)[i] = h;
        ((uint2*)lo)[i] = l;
    }
}

// in [R rows=k][C cols=n] f32 -> out_{hi,lo}[n][R/2 packed words]
__global__ __launch_bounds__(256)
void transpose_split_pack(const float* __restrict__ in, uint32_t* __restrict__ ohi,
                          uint32_t* __restrict__ olo, int R, int C)
{
    __shared__ float t[32][33];
    const int tx = threadIdx.x & 31, ty = (threadIdx.x >> 5) & 7;
    const int x0 = blockIdx.x * 32;   // n
    const int y0 = blockIdx.y * 32;   // k
#pragma unroll
    for (int i = 0; i < 32; i += 8)
        t[ty + i][tx] = in[(size_t)(y0 + ty + i) * C + x0 + tx];
    __syncthreads();
    const int Rw = R >> 1;
    const int wl = threadIdx.x & 15;
    const int nl = threadIdx.x >> 4;      // 0..15
#pragma unroll
    for (int half = 0; half < 2; half++) {
        const int n_l = nl + half * 16;
        uint32_t h, l;
        split2(t[2 * wl][n_l], t[2 * wl + 1][n_l], h, l);
        const size_t idx = (size_t)(x0 + n_l) * Rw + (y0 >> 1) + wl;
        ohi[idx] = h;
        olo[idx] = l;
    }
}

// ===========================================================================
// bf16 HMMA GEMM (3-term split): D = (Ahi+Alo) @ (Bhi+Blo)^T + bias
//   Tile 128x128, BK=32 (16 packed words), double-buffered cp.async.
//   8 warps (2m x 4n), mma m16n8k16.
// ===========================================================================
#define GLD 20                        // words per row (16 + pad4); A-pattern CF
#define GSTG (128*GLD)
#define GEMM_SMEM (8*GSTG*4)          // 2 stages x 4 matrices = 81920 B

template<int NTOT, bool QKV>
__global__ __launch_bounds__(256, 2)
void hmma_gemm(const uint32_t* __restrict__ Ahi, const uint32_t* __restrict__ Alo,
               const uint32_t* __restrict__ Bhi, const uint32_t* __restrict__ Blo,
               const float* __restrict__ bias, float* __restrict__ out)
{
    extern __shared__ uint32_t smu[];
    const uint32_t sbase = smem_u32(smu);

    const int tid  = threadIdx.x;
    const int lane = tid & 31;
    const int wid  = tid >> 5;
    const int wm   = wid & 1;
    const int wn   = wid >> 1;
    const int m0   = blockIdx.y * 128;
    const int n0   = blockIdx.x * 128;
    const int g    = lane >> 2;
    const int tig  = lane & 3;

    const uint32_t* src[4];
    src[0] = Ahi + (size_t)m0 * KW_;
    src[1] = Alo + (size_t)m0 * KW_;
    src[2] = Bhi + (size_t)n0 * KW_;
    src[3] = Blo + (size_t)n0 * KW_;

    float acc[4][4][4];
#pragma unroll
    for (int i = 0; i < 4; i++)
#pragma unroll
        for (int j = 0; j < 4; j++)
#pragma unroll
            for (int e = 0; e < 4; e++) acc[i][j][e] = 0.f;

    const int crow = tid >> 2;          // 0..63
    const int cc4  = tid & 3;           // 4-word chunk

#pragma unroll 1
    for (int kc = -1; kc < 32; kc++) {
        const int knext = kc + 1;
        if (knext < 32) {
            const int s = knext & 1;
            const uint32_t stg = sbase + s * 4 * GSTG * 4;
#pragma unroll
            for (int m = 0; m < 4; m++) {
#pragma unroll
                for (int i = 0; i < 2; i++) {
                    const int row = crow + i * 64;
                    const uint32_t so = stg + (uint32_t)(m * GSTG + row * GLD + cc4 * 4) * 4u;
                    CP_ASYNC16(so, src[m] + (size_t)row * KW_ + knext * 16 + cc4 * 4);
                }
            }
            CP_COMMIT();
        }
        if (kc < 0) continue;

        if (knext < 32) CP_WAIT(1); else CP_WAIT(0);
        __syncthreads();

        const uint32_t* st = smu + (kc & 1) * 4 * GSTG;
        const uint32_t* Ah = st;
        const uint32_t* Al = st + GSTG;
        const uint32_t* Bh = st + 2 * GSTG;
        const uint32_t* Bl = st + 3 * GSTG;

#pragma unroll
        for (int ks = 0; ks < 2; ks++) {
            const int k0 = ks * 8;
            uint32_t ah[4][4], al[4][4];
#pragma unroll
            for (int mt = 0; mt < 4; mt++) {
                const int r  = wm * 64 + mt * 16;
                const int i0 = (r + g)     * GLD + k0 + tig;
                const int i1 = (r + 8 + g) * GLD + k0 + tig;
                ah[mt][0] = Ah[i0];     ah[mt][1] = Ah[i1];
                ah[mt][2] = Ah[i0 + 4]; ah[mt][3] = Ah[i1 + 4];
                al[mt][0] = Al[i0];     al[mt][1] = Al[i1];
                al[mt][2] = Al[i0 + 4]; al[mt][3] = Al[i1 + 4];
            }
#pragma unroll
            for (int nt = 0; nt < 4; nt++) {
                const int nb = (wn * 32 + nt * 8 + g) * GLD + k0 + tig;
                const uint32_t bh0 = Bh[nb], bh1 = Bh[nb + 4];
                const uint32_t bl0 = Bl[nb], bl1 = Bl[nb + 4];
#pragma unroll
                for (int mt = 0; mt < 4; mt++) {
                    MMA_BF16(acc[mt][nt], ah[mt][0], ah[mt][1], ah[mt][2], ah[mt][3], bh0, bh1);
                    MMA_BF16(acc[mt][nt], al[mt][0], al[mt][1], al[mt][2], al[mt][3], bh0, bh1);
                    MMA_BF16(acc[mt][nt], ah[mt][0], ah[mt][1], ah[mt][2], ah[mt][3], bl0, bl1);
                }
            }
        }
        __syncthreads();
    }

    // ---- epilogue ----
#pragma unroll
    for (int mt = 0; mt < 4; mt++) {
#pragma unroll
        for (int nt = 0; nt < 4; nt++) {
            const int n = n0 + wn * 32 + nt * 8 + tig * 2;
            const float bx = bias[n], by = bias[n + 1];
#pragma unroll
            for (int half = 0; half < 2; half++) {
                const int m = m0 + wm * 64 + mt * 16 + g + half * 8;
                const float vx = acc[mt][nt][half * 2 + 0] + bx;
                const float vy = acc[mt][nt][half * 2 + 1] + by;
                if (QKV) {
                    const int bb = m >> 11;
                    const int tt = m & (T_ - 1);
                    const int which = n >> 10;
                    const int cc = n & (C_ - 1);
                    const int h = cc >> 6;
                    const int d = cc & (HD_ - 1);
                    const size_t base = ((size_t)(bb * NH_ + h) * T_ + tt);
                    if (which == 2) {
                        float2 v; v.x = vx; v.y = vy;
                        *(float2*)&g_v[base * HD_ + d] = v;
                    } else {
                        uint32_t hw, lw;
                        split2(vx, vy, hw, lw);
                        const size_t idx = base * (HD_/2) + (d >> 1);
                        if (which == 0) { g_qhi[idx] = hw; g_qlo[idx] = lw; }
                        else            { g_khi[idx] = hw; g_klo[idx] = lw; }
                    }
                } else {
                    float2 v; v.x = vx; v.y = vy;
                    *(float2*)&out[(size_t)m * NTOT + n] = v;
                }
            }
        }
    }
}

// ===========================================================================
// bf16 HMMA flash attention: BQ=64, BK=32, 8 warps (4m x 2n).
//   QK: Qhi@Khi + Qlo@Khi + Qhi@Klo (m16n8k16, 4 k-steps over HD=64).
//   PV: Phi@Vhi + Plo@Vhi + Phi@Vlo (2 k-steps over 32 keys).
// Word offsets in smem:
//   Qh 0(2304) Ql 2304 Kh 4608(1152) Kl 5760 Vph 6912(1152) Vpl 8064
//   Psh 9216(1280) Psl 10496 | rowm 11776 rowl 11840 smax 11904 ssum 12032
// ===========================================================================
#define FQ_LD 36    // 16 words + pad4  (A/B k-major pattern)
#define FV_LD 72    // 64 + pad8        (pair-packed V, B-pattern)
#define FP_LD 20    // 16 + pad4        (packed P, A-pattern)
#define FL_SMEM (12160 * 4)

__global__ __launch_bounds__(256, 2)
void flash_hmma()
{
    extern __shared__ uint32_t smu[];
    uint32_t* Qh  = smu;
    uint32_t* Ql  = smu + 2304;
    uint32_t* Kh  = smu + 4608;
    uint32_t* Kl  = smu + 5760;
    uint32_t* Vph = smu + 6912;
    uint32_t* Vpl = smu + 8064;
    uint32_t* Psh = smu + 9216;
    uint32_t* Psl = smu + 10496;
    float* rowm = (float*)(smu + 11776);
    float* rowl = (float*)(smu + 11840);
    float* smax = (float*)(smu + 11904);
    float* ssum = (float*)(smu + 12032);

    const int tid  = threadIdx.x;
    const int lane = tid & 31;
    const int wid  = tid >> 5;
    const int wm   = wid & 3;
    const int wn   = wid >> 2;
    const int g    = lane >> 2;
    const int tig  = lane & 3;

    const int qi = blockIdx.x;
    const int bh = blockIdx.y;
    const int q0 = qi * 64;

    const uint32_t* Qgh = g_qhi + (size_t)bh * T_ * 32 + (size_t)q0 * 32;
    const uint32_t* Qgl = g_qlo + (size_t)bh * T_ * 32 + (size_t)q0 * 32;
    const uint32_t* Kgh = g_khi + (size_t)bh * T_ * 32;
    const uint32_t* Kgl = g_klo + (size_t)bh * T_ * 32;
    const float*    Vg  = g_v   + (size_t)bh * T_ * HD_;

    // stage Q (packed): 64 rows x 32 words x {hi,lo}
    {
        const int r = tid >> 2, c = tid & 3;
        *(uint4*)&Qh[r * FQ_LD + c * 8]     = *(const uint4*)(Qgh + r * 32 + c * 8);
        *(uint4*)&Qh[r * FQ_LD + c * 8 + 4] = *(const uint4*)(Qgh + r * 32 + c * 8 + 4);
        *(uint4*)&Ql[r * FQ_LD + c * 8]     = *(const uint4*)(Qgl + r * 32 + c * 8);
        *(uint4*)&Ql[r * FQ_LD + c * 8 + 4] = *(const uint4*)(Qgl + r * 32 + c * 8 + 4);
    }
    if (tid < 64) { rowm[tid] = -INFINITY; rowl[tid] = 0.f; }

    const int rlo = wm * 16 + g;
    const int rhi = rlo + 8;
    __syncthreads();

    // hoist Q fragments (loop-invariant)
    uint32_t qah[4][4], qal[4][4];
#pragma unroll
    for (int ks = 0; ks < 4; ks++) {
        const int i0 = rlo * FQ_LD + ks * 8 + tig;
        const int i1 = rhi * FQ_LD + ks * 8 + tig;
        qah[ks][0] = Qh[i0];     qah[ks][1] = Qh[i1];
        qah[ks][2] = Qh[i0 + 4]; qah[ks][3] = Qh[i1 + 4];
        qal[ks][0] = Ql[i0];     qal[ks][1] = Ql[i1];
        qal[ks][2] = Ql[i0 + 4]; qal[ks][3] = Ql[i1 + 4];
    }

    float o[4][4];
#pragma unroll
    for (int nt = 0; nt < 4; nt++)
#pragma unroll
        for (int e = 0; e < 4; e++) o[nt][e] = 0.f;

    const int nkt = 2 * qi + 2;
    for (int kt = 0; kt < nkt; kt++) {
        __syncthreads();   // protect K/V/P from previous iteration's readers
        // stage K (packed): 32 rows x 8 chunks x {hi,lo}
        {
            const int m = tid >> 7, r = (tid >> 2) & 31, c = tid & 3;
            uint32_t* dst = m ? Kl : Kh;
            const uint32_t* s = (m ? Kgl : Kgh) + (size_t)(kt * 32 + r) * 32 + c * 8;
            *(uint4*)&dst[r * FQ_LD + c * 8]     = *(const uint4*)s;
            *(uint4*)&dst[r * FQ_LD + c * 8 + 4] = *(const uint4*)(s + 4);
        }
        // stage V: f32 -> pair-packed bf16 hi/lo  (16 pair-rows x 64 cols)
        {
            const int pr = tid >> 4, d4 = tid & 15;
            const float* v0 = Vg + (size_t)(kt * 32 + 2 * pr)     * HD_ + d4 * 4;
            const float* v1 = Vg + (size_t)(kt * 32 + 2 * pr + 1) * HD_ + d4 * 4;
            float4 a = *(const float4*)v0;
            float4 b = *(const float4*)v1;
            uint4 h, l;
            split2(a.x, b.x, h.x, l.x);
            split2(a.y, b.y, h.y, l.y);
            split2(a.z, b.z, h.z, l.z);
            split2(a.w, b.w, h.w, l.w);
            *(uint4*)&Vph[pr * FV_LD + d4 * 4] = h;
            *(uint4*)&Vpl[pr * FV_LD + d4 * 4] = l;
        }
        __syncthreads();   // (A)

        // ---- S = Q @ K^T ----
        float s[2][4];
#pragma unroll
        for (int nt = 0; nt < 2; nt++)
#pragma unroll
            for (int e = 0; e < 4; e++) s[nt][e] = 0.f;

#pragma unroll
        for (int ks = 0; ks < 4; ks++) {
#pragma unroll
            for (int nt = 0; nt < 2; nt++) {
                const int nb = (wn * 16 + nt * 8 + g) * FQ_LD + ks * 8 + tig;
                const uint32_t bh0 = Kh[nb], bh1 = Kh[nb + 4];
                const uint32_t bl0 = Kl[nb], bl1 = Kl[nb + 4];
                MMA_BF16(s[nt], qah[ks][0], qah[ks][1], qah[ks][2], qah[ks][3], bh0, bh1);
                MMA_BF16(s[nt], qal[ks][0], qal[ks][1], qal[ks][2], qal[ks][3], bh0, bh1);
                MMA_BF16(s[nt], qah[ks][0], qah[ks][1], qah[ks][2], qah[ks][3], bl0, bl1);
            }
        }

        // ---- scale + causal mask + row max ----
        const int qrow_lo = q0 + rlo;
        const int qrow_hi = q0 + rhi;
        float mlo = -INFINITY, mhi = -INFINITY;
#pragma unroll
        for (int nt = 0; nt < 2; nt++) {
            const int colb = kt * 32 + wn * 16 + nt * 8 + 2 * tig;
#pragma unroll
            for (int j = 0; j < 2; j++) {
                float v0 = s[nt][j] * 0.125f;
                if (colb + j > qrow_lo) v0 = -INFINITY;
                s[nt][j] = v0;
                mlo = fmaxf(mlo, v0);
                float v1 = s[nt][2 + j] * 0.125f;
                if (colb + j > qrow_hi) v1 = -INFINITY;
                s[nt][2 + j] = v1;
                mhi = fmaxf(mhi, v1);
            }
        }
#pragma unroll
        for (int off = 1; off < 4; off <<= 1) {
            mlo = fmaxf(mlo, __shfl_xor_sync(0xffffffffu, mlo, off));
            mhi = fmaxf(mhi, __shfl_xor_sync(0xffffffffu, mhi, off));
        }
        if (tig == 0) { smax[wn * 64 + rlo] = mlo; smax[wn * 64 + rhi] = mhi; }
        __syncthreads();   // (B)

        // ---- combine stats, exp, write split-packed P ----
        const float mold_lo = rowm[rlo];
        const float mold_hi = rowm[rhi];
        const float mnew_lo = fmaxf(mold_lo, fmaxf(smax[rlo], smax[64 + rlo]));
        const float mnew_hi = fmaxf(mold_hi, fmaxf(smax[rhi], smax[64 + rhi]));
        const float corr_lo = __expf(mold_lo - mnew_lo);
        const float corr_hi = __expf(mold_hi - mnew_hi);

        float sumlo = 0.f, sumhi = 0.f;
#pragma unroll
        for (int nt = 0; nt < 2; nt++) {
            float p0 = __expf(s[nt][0] - mnew_lo);
            float p1 = __expf(s[nt][1] - mnew_lo);
            float p2 = __expf(s[nt][2] - mnew_hi);
            float p3 = __expf(s[nt][3] - mnew_hi);
            sumlo += p0 + p1;
            sumhi += p2 + p3;
            const int w = wn * 8 + nt * 4 + tig;
            uint32_t hw, lw;
            split2(p0, p1, hw, lw);
            Psh[rlo * FP_LD + w] = hw;
            Psl[rlo * FP_LD + w] = lw;
            split2(p2, p3, hw, lw);
            Psh[rhi * FP_LD + w] = hw;
            Psl[rhi * FP_LD + w] = lw;
        }
#pragma unroll
        for (int off = 1; off < 4; off <<= 1) {
            sumlo += __shfl_xor_sync(0xffffffffu, sumlo, off);
            sumhi += __shfl_xor_sync(0xffffffffu, sumhi, off);
        }
        if (tig == 0) { ssum[wn * 64 + rlo] = sumlo; ssum[wn * 64 + rhi] = sumhi; }

#pragma unroll
        for (int nt = 0; nt < 4; nt++) {
            o[nt][0] *= corr_lo; o[nt][1] *= corr_lo;
            o[nt][2] *= corr_hi; o[nt][3] *= corr_hi;
        }
        __syncthreads();   // (C)

        if (tid < 64) {
            const int r = tid;
            const float mo = rowm[r];
            const float mn = fmaxf(mo, fmaxf(smax[r], smax[64 + r]));
            const float c  = __expf(mo - mn);
            rowl[r] = rowl[r] * c + ssum[r] + ssum[64 + r];
            rowm[r] = mn;
        }

        // ---- O += P @ V ----
#pragma unroll
        for (int ks = 0; ks < 2; ks++) {
            const int i0 = rlo * FP_LD + ks * 8 + tig;
            const int i1 = rhi * FP_LD + ks * 8 + tig;
            const uint32_t ah0 = Psh[i0], ah1 = Psh[i1];
            const uint32_t ah2 = Psh[i0 + 4], ah3 = Psh[i1 + 4];
            const uint32_t al0 = Psl[i0], al1 = Psl[i1];
            const uint32_t al2 = Psl[i0 + 4], al3 = Psl[i1 + 4];
#pragma unroll
            for (int nt = 0; nt < 4; nt++) {
                const int col = wn * 32 + nt * 8 + g;
                const int b0i = (ks * 8 + tig)     * FV_LD + col;
                const int b1i = (ks * 8 + tig + 4) * FV_LD + col;
                const uint32_t vh0 = Vph[b0i], vh1 = Vph[b1i];
                const uint32_t vl0 = Vpl[b0i], vl1 = Vpl[b1i];
                MMA_BF16(o[nt], ah0, ah1, ah2, ah3, vh0, vh1);
                MMA_BF16(o[nt], al0, al1, al2, al3, vh0, vh1);
                MMA_BF16(o[nt], ah0, ah1, ah2, ah3, vl0, vl1);
            }
        }
    }

    // ---- normalize + store split-packed output ----
    __syncthreads();
    const float inv_lo = 1.f / rowl[rlo];
    const float inv_hi = 1.f / rowl[rhi];
    const int b = bh >> 4, h = bh & 15;
    const int t_lo = q0 + rlo, t_hi = q0 + rhi;
#pragma unroll
    for (int nt = 0; nt < 4; nt++) {
        const int d = wn * 32 + nt * 8 + 2 * tig;
        const int w = (h * HD_ + d) >> 1;
        uint32_t hw, lw;
        split2(o[nt][0] * inv_lo, o[nt][1] * inv_lo, hw, lw);
        g_ahi[(size_t)(b * T_ + t_lo) * KW_ + w] = hw;
        g_alo[(size_t)(b * T_ + t_lo) * KW_ + w] = lw;
        split2(o[nt][2] * inv_hi, o[nt][3] * inv_hi, hw, lw);
        g_ahi[(size_t)(b * T_ + t_hi) * KW_ + w] = hw;
        g_alo[(size_t)(b * T_ + t_hi) * KW_ + w] = lw;
    }
}

// ===========================================================================
// Launch
// ===========================================================================
extern "C" void kernel_launch(void* const* d_in, const int* in_sizes, int n_in,
                              void* d_out, int out_size)
{
    const float* x      = (const float*)d_in[0];
    const float* w_attn = (const float*)d_in[1];
    const float* b_attn = (const float*)d_in[2];
    const float* w_proj = (const float*)d_in[3];
    const float* b_proj = (const float*)d_in[4];
    float* out = (float*)d_out;

    uint32_t *xhi, *xlo, *ahi, *alo, *wthi, *wtlo, *wphi, *wplo;
    cudaGetSymbolAddress((void**)&xhi,  g_xhi);
    cudaGetSymbolAddress((void**)&xlo,  g_xlo);
    cudaGetSymbolAddress((void**)&ahi,  g_ahi);
    cudaGetSymbolAddress((void**)&alo,  g_alo);
    cudaGetSymbolAddress((void**)&wthi, g_wthi);
    cudaGetSymbolAddress((void**)&wtlo, g_wtlo);
    cudaGetSymbolAddress((void**)&wphi, g_wphi);
    cudaGetSymbolAddress((void**)&wplo, g_wplo);

    cudaFuncSetAttribute(flash_hmma,
                         cudaFuncAttributeMaxDynamicSharedMemorySize, FL_SMEM);
    cudaFuncSetAttribute(hmma_gemm<3072, true>,
                         cudaFuncAttributeMaxDynamicSharedMemorySize, GEMM_SMEM);
    cudaFuncSetAttribute(hmma_gemm<1024, false>,
                         cudaFuncAttributeMaxDynamicSharedMemorySize, GEMM_SMEM);

    // Prologue: split+pack x; transpose+split+pack weights
    split_pack_elem<<<(M_*C_/4 + 255)/256, 256>>>(x, xhi, xlo, M_*C_/4);
    transpose_split_pack<<<dim3(3072/32, 1024/32), 256>>>(w_attn, wthi, wtlo, 1024, 3072);
    transpose_split_pack<<<dim3(1024/32, 1024/32), 256>>>(w_proj, wphi, wplo, 1024, 1024);

    // QKV GEMM
    hmma_gemm<3072, true><<<dim3(3072/128, M_/128), 256, GEMM_SMEM>>>(
        xhi, xlo, wthi, wtlo, b_attn, nullptr);

    // Flash attention
    flash_hmma<<<dim3(T_/64, B_*NH_), 256, FL_SMEM>>>();

    // Output projection
    hmma_gemm<1024, false><<<dim3(1024/128, M_/128), 256, GEMM_SMEM>>>(
        ahi, alo, wphi, wplo, b_proj, out);
}

// round 10
// speedup vs baseline: 2.6969x; 1.0278x over previous
#include <cuda_runtime.h>
#include <cuda.h>
#include <math.h>
#include <stdint.h>

#define B_   4
#define T_   2048
#define C_   1024
#define NH_  16
#define HD_  64
#define M_   (B_*T_)      // 8192
#define KW_  (C_/2)       // 512 packed words per K=1024 row

// Scratch (allocation-free: __device__ globals)
__device__ uint32_t g_qhi[B_*NH_*T_*HD_/2], g_qlo[B_*NH_*T_*HD_/2];
__device__ uint32_t g_khi[B_*NH_*T_*HD_/2], g_klo[B_*NH_*T_*HD_/2];
__device__ float    g_v  [B_*NH_*T_*HD_];
__device__ uint32_t g_xhi[M_*KW_],  g_xlo[M_*KW_];
__device__ uint32_t g_ahi[M_*KW_],  g_alo[M_*KW_];
__device__ uint32_t g_wthi[3*C_*KW_], g_wtlo[3*C_*KW_];
__device__ uint32_t g_wphi[C_*KW_],   g_wplo[C_*KW_];

// ===========================================================================
// Helpers
// ===========================================================================
// split pair (even,odd) into packed bf16x2 hi + residual lo (even in low 16).
__device__ __forceinline__ void split2(float e, float o, uint32_t& hi, uint32_t& lo) {
    asm("cvt.rn.bf16x2.f32 %0, %1, %2;" : "=r"(hi) : "f"(o), "f"(e));
    float he = __uint_as_float(hi << 16);
    float ho = __uint_as_float(hi & 0xffff0000u);
    asm("cvt.rn.bf16x2.f32 %0, %1, %2;" : "=r"(lo) : "f"(o - ho), "f"(e - he));
}

#define MMA_BF16(c, a0v, a1v, a2v, a3v, b0v, b1v) \
    asm volatile("mma.sync.aligned.m16n8k16.row.col.f32.bf16.bf16.f32 " \
        "{%0,%1,%2,%3}, {%4,%5,%6,%7}, {%8,%9}, {%0,%1,%2,%3};" \
        : "+f"((c)[0]), "+f"((c)[1]), "+f"((c)[2]), "+f"((c)[3]) \
        : "r"(a0v), "r"(a1v), "r"(a2v), "r"(a3v), "r"(b0v), "r"(b1v))

#define LDSM_X4(r0,r1,r2,r3, addr) \
    asm volatile("ldmatrix.sync.aligned.m8n8.x4.shared.b16 {%0,%1,%2,%3}, [%4];" \
        : "=r"(r0), "=r"(r1), "=r"(r2), "=r"(r3) : "r"(addr))
#define LDSM_X2(r0,r1, addr) \
    asm volatile("ldmatrix.sync.aligned.m8n8.x2.shared.b16 {%0,%1}, [%2];" \
        : "=r"(r0), "=r"(r1) : "r"(addr))

__device__ __forceinline__ uint32_t smem_u32(const void* p) {
    uint32_t a;
    asm("{ .reg .u64 t; cvta.to.shared.u64 t, %1; cvt.u32.u64 %0, t; }" : "=r"(a) : "l"(p));
    return a;
}
#define CP_ASYNC16(saddr, gptr) \
    asm volatile("cp.async.cg.shared.global [%0], [%1], 16;" :: "r"(saddr), "l"(gptr))
#define CP_COMMIT() asm volatile("cp.async.commit_group;" ::: "memory")
#define CP_WAIT(n)  asm volatile("cp.async.wait_group %0;" :: "n"(n) : "memory")

// ===========================================================================
// Prologue kernels
// ===========================================================================
__global__ __launch_bounds__(256)
void split_pack_elem(const float* __restrict__ in, uint32_t* __restrict__ hi,
                     uint32_t* __restrict__ lo, int n4)
{
    int i = blockIdx.x * 256 + threadIdx.x;
    if (i < n4) {
        float4 v = ((const float4*)in)[i];
        uint2 h, l;
        split2(v.x, v.y, h.x, l.x);
        split2(v.z, v.w, h.y, l.y);
        ((uint2*)hi)[i] = h;
        ((uint2*)lo)[i] = l;
    }
}

__global__ __launch_bounds__(256)
void transpose_split_pack(const float* __restrict__ in, uint32_t* __restrict__ ohi,
                          uint32_t* __restrict__ olo, int R, int C)
{
    __shared__ float t[32][33];
    const int tx = threadIdx.x & 31, ty = (threadIdx.x >> 5) & 7;
    const int x0 = blockIdx.x * 32;
    const int y0 = blockIdx.y * 32;
#pragma unroll
    for (int i = 0; i < 32; i += 8)
        t[ty + i][tx] = in[(size_t)(y0 + ty + i) * C + x0 + tx];
    __syncthreads();
    const int Rw = R >> 1;
    const int wl = threadIdx.x & 15;
    const int nl = threadIdx.x >> 4;
#pragma unroll
    for (int half = 0; half < 2; half++) {
        const int n_l = nl + half * 16;
        uint32_t h, l;
        split2(t[2 * wl][n_l], t[2 * wl + 1][n_l], h, l);
        const size_t idx = (size_t)(x0 + n_l) * Rw + (y0 >> 1) + wl;
        ohi[idx] = h;
        olo[idx] = l;
    }
}

// ===========================================================================
// bf16 HMMA GEMM (3-term split), ldmatrix fragment loads.
// ===========================================================================
#define GLD 20
#define GSTG (128*GLD)
#define GEMM_SMEM (8*GSTG*4)

template<int NTOT, bool QKV>
__global__ __launch_bounds__(256, 2)
void hmma_gemm(const uint32_t* __restrict__ Ahi, const uint32_t* __restrict__ Alo,
               const uint32_t* __restrict__ Bhi, const uint32_t* __restrict__ Blo,
               const float* __restrict__ bias, float* __restrict__ out)
{
    extern __shared__ uint32_t smu[];
    const uint32_t sbase = smem_u32(smu);

    const int tid  = threadIdx.x;
    const int lane = tid & 31;
    const int wid  = tid >> 5;
    const int wm   = wid & 1;
    const int wn   = wid >> 1;
    const int m0   = blockIdx.y * 128;
    const int n0   = blockIdx.x * 128;
    const int g    = lane >> 2;
    const int tig  = lane & 3;

    const uint32_t* src[4];
    src[0] = Ahi + (size_t)m0 * KW_;
    src[1] = Alo + (size_t)m0 * KW_;
    src[2] = Bhi + (size_t)n0 * KW_;
    src[3] = Blo + (size_t)n0 * KW_;

    float acc[4][4][4];
#pragma unroll
    for (int i = 0; i < 4; i++)
#pragma unroll
        for (int j = 0; j < 4; j++)
#pragma unroll
            for (int e = 0; e < 4; e++) acc[i][j][e] = 0.f;

    const int crow = tid >> 2;
    const int cc4  = tid & 3;

    // ldmatrix lane address offsets (in words)
    const int sub  = lane >> 3, lrow = lane & 7;
    const int arow = (sub & 1) * 8 + lrow;       // A x4 row offset
    const int acol = (sub >> 1) * 4;             // A x4 word-col offset
    uint32_t awoff[4];
#pragma unroll
    for (int mt = 0; mt < 4; mt++)
        awoff[mt] = (uint32_t)((wm * 64 + mt * 16 + arow) * GLD + acol);
    const int bsub = (lane >> 3) & 1;            // B x2 (lanes 0-15 used)
    uint32_t bwoff[4];
#pragma unroll
    for (int nt = 0; nt < 4; nt++)
        bwoff[nt] = (uint32_t)((wn * 32 + nt * 8 + lrow) * GLD + bsub * 4);

#pragma unroll 1
    for (int kc = -1; kc < 32; kc++) {
        const int knext = kc + 1;
        if (knext < 32) {
            const int s = knext & 1;
            const uint32_t stg = sbase + s * 4 * GSTG * 4;
#pragma unroll
            for (int m = 0; m < 4; m++) {
#pragma unroll
                for (int i = 0; i < 2; i++) {
                    const int row = crow + i * 64;
                    const uint32_t so = stg + (uint32_t)(m * GSTG + row * GLD + cc4 * 4) * 4u;
                    CP_ASYNC16(so, src[m] + (size_t)row * KW_ + knext * 16 + cc4 * 4);
                }
            }
            CP_COMMIT();
        }
        if (kc < 0) continue;

        if (knext < 32) CP_WAIT(1); else CP_WAIT(0);
        __syncthreads();

        const uint32_t stg = sbase + (kc & 1) * 4 * GSTG * 4;
        const uint32_t bAh = stg;
        const uint32_t bAl = stg + GSTG * 4;
        const uint32_t bBh = stg + 2 * GSTG * 4;
        const uint32_t bBl = stg + 3 * GSTG * 4;

#pragma unroll
        for (int ks = 0; ks < 2; ks++) {
            const uint32_t k0w = ks * 8;
            uint32_t ah[4][4], al[4][4];
#pragma unroll
            for (int mt = 0; mt < 4; mt++) {
                LDSM_X4(ah[mt][0], ah[mt][1], ah[mt][2], ah[mt][3],
                        bAh + (awoff[mt] + k0w) * 4u);
                LDSM_X4(al[mt][0], al[mt][1], al[mt][2], al[mt][3],
                        bAl + (awoff[mt] + k0w) * 4u);
            }
#pragma unroll
            for (int nt = 0; nt < 4; nt++) {
                uint32_t bh0, bh1, bl0, bl1;
                LDSM_X2(bh0, bh1, bBh + (bwoff[nt] + k0w) * 4u);
                LDSM_X2(bl0, bl1, bBl + (bwoff[nt] + k0w) * 4u);
#pragma unroll
                for (int mt = 0; mt < 4; mt++) {
                    MMA_BF16(acc[mt][nt], ah[mt][0], ah[mt][1], ah[mt][2], ah[mt][3], bh0, bh1);
                    MMA_BF16(acc[mt][nt], al[mt][0], al[mt][1], al[mt][2], al[mt][3], bh0, bh1);
                    MMA_BF16(acc[mt][nt], ah[mt][0], ah[mt][1], ah[mt][2], ah[mt][3], bl0, bl1);
                }
            }
        }
        __syncthreads();
    }

    // ---- epilogue ----
#pragma unroll
    for (int mt = 0; mt < 4; mt++) {
#pragma unroll
        for (int nt = 0; nt < 4; nt++) {
            const int n = n0 + wn * 32 + nt * 8 + tig * 2;
            const float bx = bias[n], by = bias[n + 1];
#pragma unroll
            for (int half = 0; half < 2; half++) {
                const int m = m0 + wm * 64 + mt * 16 + g + half * 8;
                const float vx = acc[mt][nt][half * 2 + 0] + bx;
                const float vy = acc[mt][nt][half * 2 + 1] + by;
                if (QKV) {
                    const int bb = m >> 11;
                    const int tt = m & (T_ - 1);
                    const int which = n >> 10;
                    const int cc = n & (C_ - 1);
                    const int h = cc >> 6;
                    const int d = cc & (HD_ - 1);
                    const size_t base = ((size_t)(bb * NH_ + h) * T_ + tt);
                    if (which == 2) {
                        float2 v; v.x = vx; v.y = vy;
                        *(float2*)&g_v[base * HD_ + d] = v;
                    } else {
                        uint32_t hw, lw;
                        split2(vx, vy, hw, lw);
                        const size_t idx = base * (HD_/2) + (d >> 1);
                        if (which == 0) { g_qhi[idx] = hw; g_qlo[idx] = lw; }
                        else            { g_khi[idx] = hw; g_klo[idx] = lw; }
                    }
                } else {
                    float2 v; v.x = vx; v.y = vy;
                    *(float2*)&out[(size_t)m * NTOT + n] = v;
                }
            }
        }
    }
}

// ===========================================================================
// bf16 HMMA flash attention, ldmatrix for K and P fragments.
// ===========================================================================
#define FQ_LD 36
#define FV_LD 72
#define FP_LD 20
#define FL_SMEM (12160 * 4)

__global__ __launch_bounds__(256, 2)
void flash_hmma()
{
    extern __shared__ uint32_t smu[];
    uint32_t* Qh  = smu;
    uint32_t* Ql  = smu + 2304;
    uint32_t* Kh  = smu + 4608;
    uint32_t* Kl  = smu + 5760;
    uint32_t* Vph = smu + 6912;
    uint32_t* Vpl = smu + 8064;
    uint32_t* Psh = smu + 9216;
    uint32_t* Psl = smu + 10496;
    float* rowm = (float*)(smu + 11776);
    float* rowl = (float*)(smu + 11840);
    float* smax = (float*)(smu + 11904);
    float* ssum = (float*)(smu + 12032);

    const uint32_t sm_base = smem_u32(smu);
    const uint32_t bKh = sm_base + 4608 * 4;
    const uint32_t bKl = sm_base + 5760 * 4;
    const uint32_t bPh = sm_base + 9216 * 4;
    const uint32_t bPl = sm_base + 10496 * 4;

    const int tid  = threadIdx.x;
    const int lane = tid & 31;
    const int wid  = tid >> 5;
    const int wm   = wid & 3;
    const int wn   = wid >> 2;
    const int g    = lane >> 2;
    const int tig  = lane & 3;

    const int qi = blockIdx.x;
    const int bh = blockIdx.y;
    const int q0 = qi * 64;

    const uint32_t* Qgh = g_qhi + (size_t)bh * T_ * 32 + (size_t)q0 * 32;
    const uint32_t* Qgl = g_qlo + (size_t)bh * T_ * 32 + (size_t)q0 * 32;
    const uint32_t* Kgh = g_khi + (size_t)bh * T_ * 32;
    const uint32_t* Kgl = g_klo + (size_t)bh * T_ * 32;
    const float*    Vg  = g_v   + (size_t)bh * T_ * HD_;

    // ldmatrix lane offsets
    const int sub  = lane >> 3, lrow = lane & 7;
    const int bsub = (lane >> 3) & 1;
    uint32_t kwoff[2];
#pragma unroll
    for (int nt = 0; nt < 2; nt++)
        kwoff[nt] = (uint32_t)((wn * 16 + nt * 8 + lrow) * FQ_LD + bsub * 4);
    const uint32_t pwoff =
        (uint32_t)((wm * 16 + (sub & 1) * 8 + lrow) * FP_LD + (sub >> 1) * 4);

    // stage Q (packed)
    {
        const int r = tid >> 2, c = tid & 3;
        *(uint4*)&Qh[r * FQ_LD + c * 8]     = *(const uint4*)(Qgh + r * 32 + c * 8);
        *(uint4*)&Qh[r * FQ_LD + c * 8 + 4] = *(const uint4*)(Qgh + r * 32 + c * 8 + 4);
        *(uint4*)&Ql[r * FQ_LD + c * 8]     = *(const uint4*)(Qgl + r * 32 + c * 8);
        *(uint4*)&Ql[r * FQ_LD + c * 8 + 4] = *(const uint4*)(Qgl + r * 32 + c * 8 + 4);
    }
    if (tid < 64) { rowm[tid] = -INFINITY; rowl[tid] = 0.f; }

    const int rlo = wm * 16 + g;
    const int rhi = rlo + 8;
    __syncthreads();

    // hoist Q fragments via ldmatrix (loop-invariant)
    uint32_t qah[4][4], qal[4][4];
    {
        const uint32_t bQh = sm_base;
        const uint32_t bQl = sm_base + 2304 * 4;
        const uint32_t qwoff =
            (uint32_t)((wm * 16 + (sub & 1) * 8 + lrow) * FQ_LD + (sub >> 1) * 4);
#pragma unroll
        for (int ks = 0; ks < 4; ks++) {
            LDSM_X4(qah[ks][0], qah[ks][1], qah[ks][2], qah[ks][3],
                    bQh + (qwoff + ks * 8) * 4u);
            LDSM_X4(qal[ks][0], qal[ks][1], qal[ks][2], qal[ks][3],
                    bQl + (qwoff + ks * 8) * 4u);
        }
    }

    float o[4][4];
#pragma unroll
    for (int nt = 0; nt < 4; nt++)
#pragma unroll
        for (int e = 0; e < 4; e++) o[nt][e] = 0.f;

    const int nkt = 2 * qi + 2;
    for (int kt = 0; kt < nkt; kt++) {
        __syncthreads();
        // stage K (packed)
        {
            const int m = tid >> 7, r = (tid >> 2) & 31, c = tid & 3;
            uint32_t* dst = m ? Kl : Kh;
            const uint32_t* s = (m ? Kgl : Kgh) + (size_t)(kt * 32 + r) * 32 + c * 8;
            *(uint4*)&dst[r * FQ_LD + c * 8]     = *(const uint4*)s;
            *(uint4*)&dst[r * FQ_LD + c * 8 + 4] = *(const uint4*)(s + 4);
        }
        // stage V pair-packed
        {
            const int pr = tid >> 4, d4 = tid & 15;
            const float* v0 = Vg + (size_t)(kt * 32 + 2 * pr)     * HD_ + d4 * 4;
            const float* v1 = Vg + (size_t)(kt * 32 + 2 * pr + 1) * HD_ + d4 * 4;
            float4 a = *(const float4*)v0;
            float4 b = *(const float4*)v1;
            uint4 h, l;
            split2(a.x, b.x, h.x, l.x);
            split2(a.y, b.y, h.y, l.y);
            split2(a.z, b.z, h.z, l.z);
            split2(a.w, b.w, h.w, l.w);
            *(uint4*)&Vph[pr * FV_LD + d4 * 4] = h;
            *(uint4*)&Vpl[pr * FV_LD + d4 * 4] = l;
        }
        __syncthreads();   // (A)

        // ---- S = Q @ K^T ----
        float s[2][4];
#pragma unroll
        for (int nt = 0; nt < 2; nt++)
#pragma unroll
            for (int e = 0; e < 4; e++) s[nt][e] = 0.f;

#pragma unroll
        for (int ks = 0; ks < 4; ks++) {
#pragma unroll
            for (int nt = 0; nt < 2; nt++) {
                uint32_t bh0, bh1, bl0, bl1;
                LDSM_X2(bh0, bh1, bKh + (kwoff[nt] + ks * 8) * 4u);
                LDSM_X2(bl0, bl1, bKl + (kwoff[nt] + ks * 8) * 4u);
                MMA_BF16(s[nt], qah[ks][0], qah[ks][1], qah[ks][2], qah[ks][3], bh0, bh1);
                MMA_BF16(s[nt], qal[ks][0], qal[ks][1], qal[ks][2], qal[ks][3], bh0, bh1);
                MMA_BF16(s[nt], qah[ks][0], qah[ks][1], qah[ks][2], qah[ks][3], bl0, bl1);
            }
        }

        // ---- scale + causal mask + row max ----
        const int qrow_lo = q0 + rlo;
        const int qrow_hi = q0 + rhi;
        float mlo = -INFINITY, mhi = -INFINITY;
#pragma unroll
        for (int nt = 0; nt < 2; nt++) {
            const int colb = kt * 32 + wn * 16 + nt * 8 + 2 * tig;
#pragma unroll
            for (int j = 0; j < 2; j++) {
                float v0 = s[nt][j] * 0.125f;
                if (colb + j > qrow_lo) v0 = -INFINITY;
                s[nt][j] = v0;
                mlo = fmaxf(mlo, v0);
                float v1 = s[nt][2 + j] * 0.125f;
                if (colb + j > qrow_hi) v1 = -INFINITY;
                s[nt][2 + j] = v1;
                mhi = fmaxf(mhi, v1);
            }
        }
#pragma unroll
        for (int off = 1; off < 4; off <<= 1) {
            mlo = fmaxf(mlo, __shfl_xor_sync(0xffffffffu, mlo, off));
            mhi = fmaxf(mhi, __shfl_xor_sync(0xffffffffu, mhi, off));
        }
        if (tig == 0) { smax[wn * 64 + rlo] = mlo; smax[wn * 64 + rhi] = mhi; }
        __syncthreads();   // (B)

        // ---- combine stats, exp, write split-packed P ----
        const float mold_lo = rowm[rlo];
        const float mold_hi = rowm[rhi];
        const float mnew_lo = fmaxf(mold_lo, fmaxf(smax[rlo], smax[64 + rlo]));
        const float mnew_hi = fmaxf(mold_hi, fmaxf(smax[rhi], smax[64 + rhi]));
        const float corr_lo = __expf(mold_lo - mnew_lo);
        const float corr_hi = __expf(mold_hi - mnew_hi);

        float sumlo = 0.f, sumhi = 0.f;
#pragma unroll
        for (int nt = 0; nt < 2; nt++) {
            float p0 = __expf(s[nt][0] - mnew_lo);
            float p1 = __expf(s[nt][1] - mnew_lo);
            float p2 = __expf(s[nt][2] - mnew_hi);
            float p3 = __expf(s[nt][3] - mnew_hi);
            sumlo += p0 + p1;
            sumhi += p2 + p3;
            const int w = wn * 8 + nt * 4 + tig;
            uint32_t hw, lw;
            split2(p0, p1, hw, lw);
            Psh[rlo * FP_LD + w] = hw;
            Psl[rlo * FP_LD + w] = lw;
            split2(p2, p3, hw, lw);
            Psh[rhi * FP_LD + w] = hw;
            Psl[rhi * FP_LD + w] = lw;
        }
#pragma unroll
        for (int off = 1; off < 4; off <<= 1) {
            sumlo += __shfl_xor_sync(0xffffffffu, sumlo, off);
            sumhi += __shfl_xor_sync(0xffffffffu, sumhi, off);
        }
        if (tig == 0) { ssum[wn * 64 + rlo] = sumlo; ssum[wn * 64 + rhi] = sumhi; }

#pragma unroll
        for (int nt = 0; nt < 4; nt++) {
            o[nt][0] *= corr_lo; o[nt][1] *= corr_lo;
            o[nt][2] *= corr_hi; o[nt][3] *= corr_hi;
        }
        __syncthreads();   // (C)

        if (tid < 64) {
            const int r = tid;
            const float mo = rowm[r];
            const float mn = fmaxf(mo, fmaxf(smax[r], smax[64 + r]));
            const float c  = __expf(mo - mn);
            rowl[r] = rowl[r] * c + ssum[r] + ssum[64 + r];
            rowm[r] = mn;
        }

        // ---- O += P @ V ----
#pragma unroll
        for (int ks = 0; ks < 2; ks++) {
            uint32_t ah0, ah1, ah2, ah3, al0, al1, al2, al3;
            LDSM_X4(ah0, ah1, ah2, ah3, bPh + (pwoff + ks * 8) * 4u);
            LDSM_X4(al0, al1, al2, al3, bPl + (pwoff + ks * 8) * 4u);
#pragma unroll
            for (int nt = 0; nt < 4; nt++) {
                const int col = wn * 32 + nt * 8 + g;
                const int b0i = (ks * 8 + tig)     * FV_LD + col;
                const int b1i = (ks * 8 + tig + 4) * FV_LD + col;
                const uint32_t vh0 = Vph[b0i], vh1 = Vph[b1i];
                const uint32_t vl0 = Vpl[b0i], vl1 = Vpl[b1i];
                MMA_BF16(o[nt], ah0, ah1, ah2, ah3, vh0, vh1);
                MMA_BF16(o[nt], al0, al1, al2, al3, vh0, vh1);
                MMA_BF16(o[nt], ah0, ah1, ah2, ah3, vl0, vl1);
            }
        }
    }

    // ---- normalize + store split-packed output ----
    __syncthreads();
    const float inv_lo = 1.f / rowl[rlo];
    const float inv_hi = 1.f / rowl[rhi];
    const int b = bh >> 4, h = bh & 15;
    const int t_lo = q0 + rlo, t_hi = q0 + rhi;
#pragma unroll
    for (int nt = 0; nt < 4; nt++) {
        const int d = wn * 32 + nt * 8 + 2 * tig;
        const int w = (h * HD_ + d) >> 1;
        uint32_t hw, lw;
        split2(o[nt][0] * inv_lo, o[nt][1] * inv_lo, hw, lw);
        g_ahi[(size_t)(b * T_ + t_lo) * KW_ + w] = hw;
        g_alo[(size_t)(b * T_ + t_lo) * KW_ + w] = lw;
        split2(o[nt][2] * inv_hi, o[nt][3] * inv_hi, hw, lw);
        g_ahi[(size_t)(b * T_ + t_hi) * KW_ + w] = hw;
        g_alo[(size_t)(b * T_ + t_hi) * KW_ + w] = lw;
    }
}

// ===========================================================================
// Launch
// ===========================================================================
extern "C" void kernel_launch(void* const* d_in, const int* in_sizes, int n_in,
                              void* d_out, int out_size)
{
    const float* x      = (const float*)d_in[0];
    const float* w_attn = (const float*)d_in[1];
    const float* b_attn = (const float*)d_in[2];
    const float* w_proj = (const float*)d_in[3];
    const float* b_proj = (const float*)d_in[4];
    float* out = (float*)d_out;

    uint32_t *xhi, *xlo, *ahi, *alo, *wthi, *wtlo, *wphi, *wplo;
    cudaGetSymbolAddress((void**)&xhi,  g_xhi);
    cudaGetSymbolAddress((void**)&xlo,  g_xlo);
    cudaGetSymbolAddress((void**)&ahi,  g_ahi);
    cudaGetSymbolAddress((void**)&alo,  g_alo);
    cudaGetSymbolAddress((void**)&wthi, g_wthi);
    cudaGetSymbolAddress((void**)&wtlo, g_wtlo);
    cudaGetSymbolAddress((void**)&wphi, g_wphi);
    cudaGetSymbolAddress((void**)&wplo, g_wplo);

    cudaFuncSetAttribute(flash_hmma,
                         cudaFuncAttributeMaxDynamicSharedMemorySize, FL_SMEM);
    cudaFuncSetAttribute(hmma_gemm<3072, true>,
                         cudaFuncAttributeMaxDynamicSharedMemorySize, GEMM_SMEM);
    cudaFuncSetAttribute(hmma_gemm<1024, false>,
                         cudaFuncAttributeMaxDynamicSharedMemorySize, GEMM_SMEM);

    split_pack_elem<<<(M_*C_/4 + 255)/256, 256>>>(x, xhi, xlo, M_*C_/4);
    transpose_split_pack<<<dim3(3072/32, 1024/32), 256>>>(w_attn, wthi, wtlo, 1024, 3072);
    transpose_split_pack<<<dim3(1024/32, 1024/32), 256>>>(w_proj, wphi, wplo, 1024, 1024);

    hmma_gemm<3072, true><<<dim3(3072/128, M_/128), 256, GEMM_SMEM>>>(
        xhi, xlo, wthi, wtlo, b_attn, nullptr);

    flash_hmma<<<dim3(T_/64, B_*NH_), 256, FL_SMEM>>>();

    hmma_gemm<1024, false><<<dim3(1024/128, M_/128), 256, GEMM_SMEM>>>(
        ahi, alo, wphi, wplo, b_proj, out);
}

// round 11
// speedup vs baseline: 2.8732x; 1.0653x over previous
#include <cuda_runtime.h>
#include <cuda.h>
#include <math.h>
#include <stdint.h>

#define B_   4
#define T_   2048
#define C_   1024
#define NH_  16
#define HD_  64
#define M_   (B_*T_)      // 8192
#define KW_  (C_/2)       // 512 packed words per K=1024 row

// Scratch (allocation-free: __device__ globals)
__device__ uint32_t g_qhi[B_*NH_*T_*HD_/2], g_qlo[B_*NH_*T_*HD_/2];
__device__ uint32_t g_khi[B_*NH_*T_*HD_/2], g_klo[B_*NH_*T_*HD_/2];
__device__ float    g_v  [B_*NH_*T_*HD_];
__device__ uint32_t g_xhi[M_*KW_],  g_xlo[M_*KW_];
__device__ uint32_t g_ahi[M_*KW_],  g_alo[M_*KW_];
__device__ uint32_t g_wthi[3*C_*KW_], g_wtlo[3*C_*KW_];
__device__ uint32_t g_wphi[C_*KW_],   g_wplo[C_*KW_];

// ===========================================================================
// Helpers
// ===========================================================================
// split pair (even,odd) into packed bf16x2 hi + residual lo (even in low 16).
__device__ __forceinline__ void split2(float e, float o, uint32_t& hi, uint32_t& lo) {
    asm("cvt.rn.bf16x2.f32 %0, %1, %2;" : "=r"(hi) : "f"(o), "f"(e));
    float he = __uint_as_float(hi << 16);
    float ho = __uint_as_float(hi & 0xffff0000u);
    asm("cvt.rn.bf16x2.f32 %0, %1, %2;" : "=r"(lo) : "f"(o - ho), "f"(e - he));
}

#define MMA_BF16(c, a0v, a1v, a2v, a3v, b0v, b1v) \
    asm volatile("mma.sync.aligned.m16n8k16.row.col.f32.bf16.bf16.f32 " \
        "{%0,%1,%2,%3}, {%4,%5,%6,%7}, {%8,%9}, {%0,%1,%2,%3};" \
        : "+f"((c)[0]), "+f"((c)[1]), "+f"((c)[2]), "+f"((c)[3]) \
        : "r"(a0v), "r"(a1v), "r"(a2v), "r"(a3v), "r"(b0v), "r"(b1v))

#define LDSM_X4(r0,r1,r2,r3, addr) \
    asm volatile("ldmatrix.sync.aligned.m8n8.x4.shared.b16 {%0,%1,%2,%3}, [%4];" \
        : "=r"(r0), "=r"(r1), "=r"(r2), "=r"(r3) : "r"(addr))
#define LDSM_X2(r0,r1, addr) \
    asm volatile("ldmatrix.sync.aligned.m8n8.x2.shared.b16 {%0,%1}, [%2];" \
        : "=r"(r0), "=r"(r1) : "r"(addr))

__device__ __forceinline__ uint32_t smem_u32(const void* p) {
    uint32_t a;
    asm("{ .reg .u64 t; cvta.to.shared.u64 t, %1; cvt.u32.u64 %0, t; }" : "=r"(a) : "l"(p));
    return a;
}
#define CP_ASYNC16(saddr, gptr) \
    asm volatile("cp.async.cg.shared.global [%0], [%1], 16;" :: "r"(saddr), "l"(gptr))
#define CP_COMMIT() asm volatile("cp.async.commit_group;" ::: "memory")
#define CP_WAIT(n)  asm volatile("cp.async.wait_group %0;" :: "n"(n) : "memory")

// ===========================================================================
// Prologue kernels
// ===========================================================================
__global__ __launch_bounds__(256)
void split_pack_elem(const float* __restrict__ in, uint32_t* __restrict__ hi,
                     uint32_t* __restrict__ lo, int n4)
{
    int i = blockIdx.x * 256 + threadIdx.x;
    if (i < n4) {
        float4 v = ((const float4*)in)[i];
        uint2 h, l;
        split2(v.x, v.y, h.x, l.x);
        split2(v.z, v.w, h.y, l.y);
        ((uint2*)hi)[i] = h;
        ((uint2*)lo)[i] = l;
    }
}

__global__ __launch_bounds__(256)
void transpose_split_pack(const float* __restrict__ in, uint32_t* __restrict__ ohi,
                          uint32_t* __restrict__ olo, int R, int C)
{
    __shared__ float t[32][33];
    const int tx = threadIdx.x & 31, ty = (threadIdx.x >> 5) & 7;
    const int x0 = blockIdx.x * 32;
    const int y0 = blockIdx.y * 32;
#pragma unroll
    for (int i = 0; i < 32; i += 8)
        t[ty + i][tx] = in[(size_t)(y0 + ty + i) * C + x0 + tx];
    __syncthreads();
    const int Rw = R >> 1;
    const int wl = threadIdx.x & 15;
    const int nl = threadIdx.x >> 4;
#pragma unroll
    for (int half = 0; half < 2; half++) {
        const int n_l = nl + half * 16;
        uint32_t h, l;
        split2(t[2 * wl][n_l], t[2 * wl + 1][n_l], h, l);
        const size_t idx = (size_t)(x0 + n_l) * Rw + (y0 >> 1) + wl;
        ohi[idx] = h;
        olo[idx] = l;
    }
}

// ===========================================================================
// bf16 HMMA GEMM (3-term split), ldmatrix loads, term-grouped MMA order.
// ===========================================================================
#define GLD 20
#define GSTG (128*GLD)
#define GEMM_SMEM (8*GSTG*4)

template<int NTOT, bool QKV>
__global__ __launch_bounds__(256, 2)
void hmma_gemm(const uint32_t* __restrict__ Ahi, const uint32_t* __restrict__ Alo,
               const uint32_t* __restrict__ Bhi, const uint32_t* __restrict__ Blo,
               const float* __restrict__ bias, float* __restrict__ out)
{
    extern __shared__ uint32_t smu[];
    const uint32_t sbase = smem_u32(smu);

    const int tid  = threadIdx.x;
    const int lane = tid & 31;
    const int wid  = tid >> 5;
    const int wm   = wid & 1;
    const int wn   = wid >> 1;
    const int m0   = blockIdx.y * 128;
    const int n0   = blockIdx.x * 128;
    const int g    = lane >> 2;
    const int tig  = lane & 3;

    const uint32_t* src[4];
    src[0] = Ahi + (size_t)m0 * KW_;
    src[1] = Alo + (size_t)m0 * KW_;
    src[2] = Bhi + (size_t)n0 * KW_;
    src[3] = Blo + (size_t)n0 * KW_;

    float acc[4][4][4];
#pragma unroll
    for (int i = 0; i < 4; i++)
#pragma unroll
        for (int j = 0; j < 4; j++)
#pragma unroll
            for (int e = 0; e < 4; e++) acc[i][j][e] = 0.f;

    const int crow = tid >> 2;
    const int cc4  = tid & 3;

    const int sub  = lane >> 3, lrow = lane & 7;
    const int arow = (sub & 1) * 8 + lrow;
    const int acol = (sub >> 1) * 4;
    uint32_t awoff[4];
#pragma unroll
    for (int mt = 0; mt < 4; mt++)
        awoff[mt] = (uint32_t)((wm * 64 + mt * 16 + arow) * GLD + acol);
    const int bsub = (lane >> 3) & 1;
    uint32_t bwoff[4];
#pragma unroll
    for (int nt = 0; nt < 4; nt++)
        bwoff[nt] = (uint32_t)((wn * 32 + nt * 8 + lrow) * GLD + bsub * 4);

#pragma unroll 1
    for (int kc = -1; kc < 32; kc++) {
        const int knext = kc + 1;
        if (knext < 32) {
            const int s = knext & 1;
            const uint32_t stg = sbase + s * 4 * GSTG * 4;
#pragma unroll
            for (int m = 0; m < 4; m++) {
#pragma unroll
                for (int i = 0; i < 2; i++) {
                    const int row = crow + i * 64;
                    const uint32_t so = stg + (uint32_t)(m * GSTG + row * GLD + cc4 * 4) * 4u;
                    CP_ASYNC16(so, src[m] + (size_t)row * KW_ + knext * 16 + cc4 * 4);
                }
            }
            CP_COMMIT();
        }
        if (kc < 0) continue;

        if (knext < 32) CP_WAIT(1); else CP_WAIT(0);
        __syncthreads();

        const uint32_t stg = sbase + (kc & 1) * 4 * GSTG * 4;
        const uint32_t bAh = stg;
        const uint32_t bAl = stg + GSTG * 4;
        const uint32_t bBh = stg + 2 * GSTG * 4;
        const uint32_t bBl = stg + 3 * GSTG * 4;

#pragma unroll
        for (int ks = 0; ks < 2; ks++) {
            const uint32_t k0w = ks * 8;
            uint32_t ah[4][4], al[4][4];
#pragma unroll
            for (int mt = 0; mt < 4; mt++) {
                LDSM_X4(ah[mt][0], ah[mt][1], ah[mt][2], ah[mt][3],
                        bAh + (awoff[mt] + k0w) * 4u);
                LDSM_X4(al[mt][0], al[mt][1], al[mt][2], al[mt][3],
                        bAl + (awoff[mt] + k0w) * 4u);
            }
#pragma unroll
            for (int nt = 0; nt < 4; nt++) {
                uint32_t bh0, bh1, bl0, bl1;
                LDSM_X2(bh0, bh1, bBh + (bwoff[nt] + k0w) * 4u);
                LDSM_X2(bl0, bl1, bBl + (bwoff[nt] + k0w) * 4u);
                // term-grouped: consecutive MMAs hit different accumulators
#pragma unroll
                for (int mt = 0; mt < 4; mt++)
                    MMA_BF16(acc[mt][nt], ah[mt][0], ah[mt][1], ah[mt][2], ah[mt][3], bh0, bh1);
#pragma unroll
                for (int mt = 0; mt < 4; mt++)
                    MMA_BF16(acc[mt][nt], al[mt][0], al[mt][1], al[mt][2], al[mt][3], bh0, bh1);
#pragma unroll
                for (int mt = 0; mt < 4; mt++)
                    MMA_BF16(acc[mt][nt], ah[mt][0], ah[mt][1], ah[mt][2], ah[mt][3], bl0, bl1);
            }
        }
        __syncthreads();
    }

    // ---- epilogue ----
#pragma unroll
    for (int mt = 0; mt < 4; mt++) {
#pragma unroll
        for (int nt = 0; nt < 4; nt++) {
            const int n = n0 + wn * 32 + nt * 8 + tig * 2;
            const float bx = bias[n], by = bias[n + 1];
#pragma unroll
            for (int half = 0; half < 2; half++) {
                const int m = m0 + wm * 64 + mt * 16 + g + half * 8;
                const float vx = acc[mt][nt][half * 2 + 0] + bx;
                const float vy = acc[mt][nt][half * 2 + 1] + by;
                if (QKV) {
                    const int bb = m >> 11;
                    const int tt = m & (T_ - 1);
                    const int which = n >> 10;
                    const int cc = n & (C_ - 1);
                    const int h = cc >> 6;
                    const int d = cc & (HD_ - 1);
                    const size_t base = ((size_t)(bb * NH_ + h) * T_ + tt);
                    if (which == 2) {
                        float2 v; v.x = vx; v.y = vy;
                        *(float2*)&g_v[base * HD_ + d] = v;
                    } else {
                        uint32_t hw, lw;
                        split2(vx, vy, hw, lw);
                        const size_t idx = base * (HD_/2) + (d >> 1);
                        if (which == 0) { g_qhi[idx] = hw; g_qlo[idx] = lw; }
                        else            { g_khi[idx] = hw; g_klo[idx] = lw; }
                    }
                } else {
                    float2 v; v.x = vx; v.y = vy;
                    *(float2*)&out[(size_t)m * NTOT + n] = v;
                }
            }
        }
    }
}

// ===========================================================================
// bf16 HMMA flash attention v4 (FA2-style register reuse):
//   BQ=128, BK=32, 8 warps; each warp owns 16 full rows of S (16x32).
//   Row stats in registers (quad shuffles only).  P never touches smem:
//   S accumulator -> split2 -> PV A-fragments directly.
//   2 barriers per key tile.
// Smem (words): Qh 0(4608) Ql 4608 Kh 9216(1152) Kl 10368 Vph 11520(1152)
//   Vpl 12672 -> total 13824
// ===========================================================================
#define FQ_LD 36
#define FV_LD 72
#define FL_SMEM (13824 * 4)

__global__ __launch_bounds__(256, 2)
void flash_hmma()
{
    extern __shared__ uint32_t smu[];
    uint32_t* Qh  = smu;
    uint32_t* Ql  = smu + 4608;
    uint32_t* Kh  = smu + 9216;
    uint32_t* Kl  = smu + 10368;
    uint32_t* Vph = smu + 11520;
    uint32_t* Vpl = smu + 12672;

    const uint32_t sm_base = smem_u32(smu);
    const uint32_t bQh = sm_base;
    const uint32_t bQl = sm_base + 4608 * 4;
    const uint32_t bKh = sm_base + 9216 * 4;
    const uint32_t bKl = sm_base + 10368 * 4;

    const int tid  = threadIdx.x;
    const int lane = tid & 31;
    const int wm   = tid >> 5;        // warp owns rows wm*16..wm*16+15
    const int g    = lane >> 2;
    const int tig  = lane & 3;

    const int qi = blockIdx.x;        // 0..15
    const int bh = blockIdx.y;        // 0..63
    const int q0 = qi * 128;

    const uint32_t* Qgh = g_qhi + (size_t)bh * T_ * 32 + (size_t)q0 * 32;
    const uint32_t* Qgl = g_qlo + (size_t)bh * T_ * 32 + (size_t)q0 * 32;
    const uint32_t* Kgh = g_khi + (size_t)bh * T_ * 32;
    const uint32_t* Kgl = g_klo + (size_t)bh * T_ * 32;
    const float*    Vg  = g_v   + (size_t)bh * T_ * HD_;

    const int sub  = lane >> 3, lrow = lane & 7;

    // K ldmatrix.x4 lane offset: tile group tg covers (ntile pair, k-half)
    // tg0:(nt0,k0-7) tg1:(nt0,k8-15) tg2:(nt1,k0-7) tg3:(nt1,k8-15)
    uint32_t kwoff4[2];
#pragma unroll
    for (int np = 0; np < 2; np++)
        kwoff4[np] = (uint32_t)((np * 16 + (sub >> 1) * 8 + lrow) * FQ_LD + (sub & 1) * 4);

    // stage Q (packed): 128 rows x 32 words x {hi,lo}; 1024 uint4 per matrix
    {
#pragma unroll
        for (int it = 0; it < 4; it++) {
            const int u = tid + it * 256;
            const int r = u >> 3, wc = (u & 7) * 4;
            *(uint4*)&Qh[r * FQ_LD + wc] = *(const uint4*)(Qgh + r * 32 + wc);
            *(uint4*)&Ql[r * FQ_LD + wc] = *(const uint4*)(Qgl + r * 32 + wc);
        }
    }

    const int rlo = wm * 16 + g;      // local row (c0,c1)
    const int rhi = rlo + 8;
    __syncthreads();

    // hoist Q fragments (loop-invariant)
    uint32_t qah[4][4], qal[4][4];
    {
        const uint32_t qwoff =
            (uint32_t)((wm * 16 + (sub & 1) * 8 + lrow) * FQ_LD + (sub >> 1) * 4);
#pragma unroll
        for (int ks = 0; ks < 4; ks++) {
            LDSM_X4(qah[ks][0], qah[ks][1], qah[ks][2], qah[ks][3],
                    bQh + (qwoff + ks * 8) * 4u);
            LDSM_X4(qal[ks][0], qal[ks][1], qal[ks][2], qal[ks][3],
                    bQl + (qwoff + ks * 8) * 4u);
        }
    }

    float o[8][4];
#pragma unroll
    for (int nt = 0; nt < 8; nt++)
#pragma unroll
        for (int e = 0; e < 4; e++) o[nt][e] = 0.f;

    float mrun_lo = -INFINITY, mrun_hi = -INFINITY;
    float lrun_lo = 0.f,       lrun_hi = 0.f;

    const int qrow_lo = q0 + rlo;
    const int qrow_hi = q0 + rhi;

    const int nkt = 4 * qi + 4;
    for (int kt = 0; kt < nkt; kt++) {
        __syncthreads();   // protect K/V from previous iteration's readers
        // stage K (packed): 32 rows x 8 words-of-4 x {hi,lo}
        {
            const int m = tid >> 7, r = (tid >> 2) & 31, c = tid & 3;
            uint32_t* dst = m ? Kl : Kh;
            const uint32_t* s = (m ? Kgl : Kgh) + (size_t)(kt * 32 + r) * 32 + c * 8;
            *(uint4*)&dst[r * FQ_LD + c * 8]     = *(const uint4*)s;
            *(uint4*)&dst[r * FQ_LD + c * 8 + 4] = *(const uint4*)(s + 4);
        }
        // stage V pair-packed: 16 pair-rows x 64 cols
        {
            const int pr = tid >> 4, d4 = tid & 15;
            const float* v0 = Vg + (size_t)(kt * 32 + 2 * pr)     * HD_ + d4 * 4;
            const float* v1 = Vg + (size_t)(kt * 32 + 2 * pr + 1) * HD_ + d4 * 4;
            float4 a = *(const float4*)v0;
            float4 b = *(const float4*)v1;
            uint4 h, l;
            split2(a.x, b.x, h.x, l.x);
            split2(a.y, b.y, h.y, l.y);
            split2(a.z, b.z, h.z, l.z);
            split2(a.w, b.w, h.w, l.w);
            *(uint4*)&Vph[pr * FV_LD + d4 * 4] = h;
            *(uint4*)&Vpl[pr * FV_LD + d4 * 4] = l;
        }
        __syncthreads();   // (A) K/V ready

        // ---- S = Q @ K^T : warp tile 16x32, s[nt] nt=0..3 ----
        float s[4][4];
#pragma unroll
        for (int nt = 0; nt < 4; nt++)
#pragma unroll
            for (int e = 0; e < 4; e++) s[nt][e] = 0.f;

#pragma unroll
        for (int ks = 0; ks < 4; ks++) {
#pragma unroll
            for (int np = 0; np < 2; np++) {
                uint32_t bh0, bh1, bh2, bh3, bl0, bl1, bl2, bl3;
                LDSM_X4(bh0, bh1, bh2, bh3, bKh + (kwoff4[np] + ks * 8) * 4u);
                LDSM_X4(bl0, bl1, bl2, bl3, bKl + (kwoff4[np] + ks * 8) * 4u);
                MMA_BF16(s[2*np],   qah[ks][0], qah[ks][1], qah[ks][2], qah[ks][3], bh0, bh1);
                MMA_BF16(s[2*np+1], qah[ks][0], qah[ks][1], qah[ks][2], qah[ks][3], bh2, bh3);
                MMA_BF16(s[2*np],   qal[ks][0], qal[ks][1], qal[ks][2], qal[ks][3], bh0, bh1);
                MMA_BF16(s[2*np+1], qal[ks][0], qal[ks][1], qal[ks][2], qal[ks][3], bh2, bh3);
                MMA_BF16(s[2*np],   qah[ks][0], qah[ks][1], qah[ks][2], qah[ks][3], bl0, bl1);
                MMA_BF16(s[2*np+1], qah[ks][0], qah[ks][1], qah[ks][2], qah[ks][3], bl2, bl3);
            }
        }

        // ---- scale + causal mask + row max (registers + quad shuffle) ----
        float mlo = -INFINITY, mhi = -INFINITY;
        const bool needmask = (kt * 32 + 31) > (q0 + wm * 16);
#pragma unroll
        for (int nt = 0; nt < 4; nt++) {
            const int colb = kt * 32 + nt * 8 + 2 * tig;
#pragma unroll
            for (int j = 0; j < 2; j++) {
                float v0 = s[nt][j] * 0.125f;
                float v1 = s[nt][2 + j] * 0.125f;
                if (needmask) {
                    if (colb + j > qrow_lo) v0 = -INFINITY;
                    if (colb + j > qrow_hi) v1 = -INFINITY;
                }
                s[nt][j] = v0;
                s[nt][2 + j] = v1;
                mlo = fmaxf(mlo, v0);
                mhi = fmaxf(mhi, v1);
            }
        }
#pragma unroll
        for (int off = 1; off < 4; off <<= 1) {
            mlo = fmaxf(mlo, __shfl_xor_sync(0xffffffffu, mlo, off));
            mhi = fmaxf(mhi, __shfl_xor_sync(0xffffffffu, mhi, off));
        }

        // ---- online softmax update (all registers) ----
        const float mnew_lo = fmaxf(mrun_lo, mlo);
        const float mnew_hi = fmaxf(mrun_hi, mhi);
        const float corr_lo = __expf(mrun_lo - mnew_lo);
        const float corr_hi = __expf(mrun_hi - mnew_hi);
        mrun_lo = mnew_lo; mrun_hi = mnew_hi;

        float sumlo = 0.f, sumhi = 0.f;
        uint32_t pah[2][4], pal[2][4];   // PV A-fragments per k16 chunk
#pragma unroll
        for (int nt = 0; nt < 4; nt++) {
            float p0 = __expf(s[nt][0] - mnew_lo);
            float p1 = __expf(s[nt][1] - mnew_lo);
            float p2 = __expf(s[nt][2] - mnew_hi);
            float p3 = __expf(s[nt][3] - mnew_hi);
            sumlo += p0 + p1;
            sumhi += p2 + p3;
            const int ks = nt >> 1;          // k16 chunk
            const int hi2 = (nt & 1) * 2;    // a0/a1 vs a2/a3
            split2(p0, p1, pah[ks][hi2],     pal[ks][hi2]);
            split2(p2, p3, pah[ks][hi2 + 1], pal[ks][hi2 + 1]);
        }
#pragma unroll
        for (int off = 1; off < 4; off <<= 1) {
            sumlo += __shfl_xor_sync(0xffffffffu, sumlo, off);
            sumhi += __shfl_xor_sync(0xffffffffu, sumhi, off);
        }
        lrun_lo = lrun_lo * corr_lo + sumlo;
        lrun_hi = lrun_hi * corr_hi + sumhi;

        // rescale O
#pragma unroll
        for (int nt = 0; nt < 8; nt++) {
            o[nt][0] *= corr_lo; o[nt][1] *= corr_lo;
            o[nt][2] *= corr_hi; o[nt][3] *= corr_hi;
        }

        // ---- O += P @ V (P fragments from registers) ----
#pragma unroll
        for (int ks = 0; ks < 2; ks++) {
#pragma unroll
            for (int nt = 0; nt < 8; nt++) {
                const int col = nt * 8 + g;
                const int b0i = (ks * 8 + tig)     * FV_LD + col;
                const int b1i = (ks * 8 + tig + 4) * FV_LD + col;
                const uint32_t vh0 = Vph[b0i], vh1 = Vph[b1i];
                const uint32_t vl0 = Vpl[b0i], vl1 = Vpl[b1i];
                MMA_BF16(o[nt], pah[ks][0], pah[ks][1], pah[ks][2], pah[ks][3], vh0, vh1);
                MMA_BF16(o[nt], pal[ks][0], pal[ks][1], pal[ks][2], pal[ks][3], vh0, vh1);
                MMA_BF16(o[nt], pah[ks][0], pah[ks][1], pah[ks][2], pah[ks][3], vl0, vl1);
            }
        }
    }

    // ---- normalize + store split-packed output ----
    const float inv_lo = 1.f / lrun_lo;
    const float inv_hi = 1.f / lrun_hi;
    const int b = bh >> 4, h = bh & 15;
    const int t_lo = q0 + rlo, t_hi = q0 + rhi;
#pragma unroll
    for (int nt = 0; nt < 8; nt++) {
        const int d = nt * 8 + 2 * tig;
        const int w = (h * HD_ + d) >> 1;
        uint32_t hw, lw;
        split2(o[nt][0] * inv_lo, o[nt][1] * inv_lo, hw, lw);
        g_ahi[(size_t)(b * T_ + t_lo) * KW_ + w] = hw;
        g_alo[(size_t)(b * T_ + t_lo) * KW_ + w] = lw;
        split2(o[nt][2] * inv_hi, o[nt][3] * inv_hi, hw, lw);
        g_ahi[(size_t)(b * T_ + t_hi) * KW_ + w] = hw;
        g_alo[(size_t)(b * T_ + t_hi) * KW_ + w] = lw;
    }
}

// ===========================================================================
// Launch
// ===========================================================================
extern "C" void kernel_launch(void* const* d_in, const int* in_sizes, int n_in,
                              void* d_out, int out_size)
{
    const float* x      = (const float*)d_in[0];
    const float* w_attn = (const float*)d_in[1];
    const float* b_attn = (const float*)d_in[2];
    const float* w_proj = (const float*)d_in[3];
    const float* b_proj = (const float*)d_in[4];
    float* out = (float*)d_out;

    uint32_t *xhi, *xlo, *ahi, *alo, *wthi, *wtlo, *wphi, *wplo;
    cudaGetSymbolAddress((void**)&xhi,  g_xhi);
    cudaGetSymbolAddress((void**)&xlo,  g_xlo);
    cudaGetSymbolAddress((void**)&ahi,  g_ahi);
    cudaGetSymbolAddress((void**)&alo,  g_alo);
    cudaGetSymbolAddress((void**)&wthi, g_wthi);
    cudaGetSymbolAddress((void**)&wtlo, g_wtlo);
    cudaGetSymbolAddress((void**)&wphi, g_wphi);
    cudaGetSymbolAddress((void**)&wplo, g_wplo);

    cudaFuncSetAttribute(flash_hmma,
                         cudaFuncAttributeMaxDynamicSharedMemorySize, FL_SMEM);
    cudaFuncSetAttribute(hmma_gemm<3072, true>,
                         cudaFuncAttributeMaxDynamicSharedMemorySize, GEMM_SMEM);
    cudaFuncSetAttribute(hmma_gemm<1024, false>,
                         cudaFuncAttributeMaxDynamicSharedMemorySize, GEMM_SMEM);

    split_pack_elem<<<(M_*C_/4 + 255)/256, 256>>>(x, xhi, xlo, M_*C_/4);
    transpose_split_pack<<<dim3(3072/32, 1024/32), 256>>>(w_attn, wthi, wtlo, 1024, 3072);
    transpose_split_pack<<<dim3(1024/32, 1024/32), 256>>>(w_proj, wphi, wplo, 1024, 1024);

    hmma_gemm<3072, true><<<dim3(3072/128, M_/128), 256, GEMM_SMEM>>>(
        xhi, xlo, wthi, wtlo, b_attn, nullptr);

    flash_hmma<<<dim3(T_/128, B_*NH_), 256, FL_SMEM>>>();

    hmma_gemm<1024, false><<<dim3(1024/128, M_/128), 256, GEMM_SMEM>>>(
        ahi, alo, wphi, wplo, b_proj, out);
}

// round 12
// speedup vs baseline: 2.9324x; 1.0206x over previous
#include <cuda_runtime.h>
#include <cuda.h>
#include <math.h>
#include <stdint.h>

#define B_   4
#define T_   2048
#define C_   1024
#define NH_  16
#define HD_  64
#define M_   (B_*T_)      // 8192
#define KW_  (C_/2)       // 512 packed words per K=1024 row

// Scratch (allocation-free: __device__ globals)
__device__ uint32_t g_qhi[B_*NH_*T_*HD_/2], g_qlo[B_*NH_*T_*HD_/2];
__device__ uint32_t g_khi[B_*NH_*T_*HD_/2], g_klo[B_*NH_*T_*HD_/2];
__device__ float    g_v  [B_*NH_*T_*HD_];
__device__ uint32_t g_xhi[M_*KW_],  g_xlo[M_*KW_];
__device__ uint32_t g_ahi[M_*KW_],  g_alo[M_*KW_];
__device__ uint32_t g_wthi[3*C_*KW_], g_wtlo[3*C_*KW_];
__device__ uint32_t g_wphi[C_*KW_],   g_wplo[C_*KW_];

// ===========================================================================
// Helpers
// ===========================================================================
__device__ __forceinline__ void split2(float e, float o, uint32_t& hi, uint32_t& lo) {
    asm("cvt.rn.bf16x2.f32 %0, %1, %2;" : "=r"(hi) : "f"(o), "f"(e));
    float he = __uint_as_float(hi << 16);
    float ho = __uint_as_float(hi & 0xffff0000u);
    asm("cvt.rn.bf16x2.f32 %0, %1, %2;" : "=r"(lo) : "f"(o - ho), "f"(e - he));
}

#define MMA_BF16(c, a0v, a1v, a2v, a3v, b0v, b1v) \
    asm volatile("mma.sync.aligned.m16n8k16.row.col.f32.bf16.bf16.f32 " \
        "{%0,%1,%2,%3}, {%4,%5,%6,%7}, {%8,%9}, {%0,%1,%2,%3};" \
        : "+f"((c)[0]), "+f"((c)[1]), "+f"((c)[2]), "+f"((c)[3]) \
        : "r"(a0v), "r"(a1v), "r"(a2v), "r"(a3v), "r"(b0v), "r"(b1v))

#define LDSM_X4(r0,r1,r2,r3, addr) \
    asm volatile("ldmatrix.sync.aligned.m8n8.x4.shared.b16 {%0,%1,%2,%3}, [%4];" \
        : "=r"(r0), "=r"(r1), "=r"(r2), "=r"(r3) : "r"(addr))
#define LDSM_X2(r0,r1, addr) \
    asm volatile("ldmatrix.sync.aligned.m8n8.x2.shared.b16 {%0,%1}, [%2];" \
        : "=r"(r0), "=r"(r1) : "r"(addr))

__device__ __forceinline__ uint32_t smem_u32(const void* p) {
    uint32_t a;
    asm("{ .reg .u64 t; cvta.to.shared.u64 t, %1; cvt.u32.u64 %0, t; }" : "=r"(a) : "l"(p));
    return a;
}
#define CP_ASYNC16(saddr, gptr) \
    asm volatile("cp.async.cg.shared.global [%0], [%1], 16;" :: "r"(saddr), "l"(gptr))
#define CP_COMMIT() asm volatile("cp.async.commit_group;" ::: "memory")
#define CP_WAIT(n)  asm volatile("cp.async.wait_group %0;" :: "n"(n) : "memory")

// ===========================================================================
// Prologue kernels
// ===========================================================================
__global__ __launch_bounds__(256)
void split_pack_elem(const float* __restrict__ in, uint32_t* __restrict__ hi,
                     uint32_t* __restrict__ lo, int n4)
{
    int i = blockIdx.x * 256 + threadIdx.x;
    if (i < n4) {
        float4 v = ((const float4*)in)[i];
        uint2 h, l;
        split2(v.x, v.y, h.x, l.x);
        split2(v.z, v.w, h.y, l.y);
        ((uint2*)hi)[i] = h;
        ((uint2*)lo)[i] = l;
    }
}

__global__ __launch_bounds__(256)
void transpose_split_pack(const float* __restrict__ in, uint32_t* __restrict__ ohi,
                          uint32_t* __restrict__ olo, int R, int C)
{
    __shared__ float t[32][33];
    const int tx = threadIdx.x & 31, ty = (threadIdx.x >> 5) & 7;
    const int x0 = blockIdx.x * 32;
    const int y0 = blockIdx.y * 32;
#pragma unroll
    for (int i = 0; i < 32; i += 8)
        t[ty + i][tx] = in[(size_t)(y0 + ty + i) * C + x0 + tx];
    __syncthreads();
    const int Rw = R >> 1;
    const int wl = threadIdx.x & 15;
    const int nl = threadIdx.x >> 4;
#pragma unroll
    for (int half = 0; half < 2; half++) {
        const int n_l = nl + half * 16;
        uint32_t h, l;
        split2(t[2 * wl][n_l], t[2 * wl + 1][n_l], h, l);
        const size_t idx = (size_t)(x0 + n_l) * Rw + (y0 >> 1) + wl;
        ohi[idx] = h;
        olo[idx] = l;
    }
}

// ===========================================================================
// bf16 HMMA GEMM (3-term split): single barrier per K chunk.
//   wait(stage kc) -> sync -> submit(stage kc+1) -> compute(stage kc)
// ===========================================================================
#define GLD 20
#define GSTG (128*GLD)
#define GEMM_SMEM (8*GSTG*4)

template<int NTOT, bool QKV>
__global__ __launch_bounds__(256, 2)
void hmma_gemm(const uint32_t* __restrict__ Ahi, const uint32_t* __restrict__ Alo,
               const uint32_t* __restrict__ Bhi, const uint32_t* __restrict__ Blo,
               const float* __restrict__ bias, float* __restrict__ out)
{
    extern __shared__ uint32_t smu[];
    const uint32_t sbase = smem_u32(smu);

    const int tid  = threadIdx.x;
    const int lane = tid & 31;
    const int wid  = tid >> 5;
    const int wm   = wid & 1;
    const int wn   = wid >> 1;
    const int m0   = blockIdx.y * 128;
    const int n0   = blockIdx.x * 128;
    const int g    = lane >> 2;
    const int tig  = lane & 3;

    const uint32_t* src[4];
    src[0] = Ahi + (size_t)m0 * KW_;
    src[1] = Alo + (size_t)m0 * KW_;
    src[2] = Bhi + (size_t)n0 * KW_;
    src[3] = Blo + (size_t)n0 * KW_;

    float acc[4][4][4];
#pragma unroll
    for (int i = 0; i < 4; i++)
#pragma unroll
        for (int j = 0; j < 4; j++)
#pragma unroll
            for (int e = 0; e < 4; e++) acc[i][j][e] = 0.f;

    const int crow = tid >> 2;
    const int cc4  = tid & 3;

    const int sub  = lane >> 3, lrow = lane & 7;
    const int arow = (sub & 1) * 8 + lrow;
    const int acol = (sub >> 1) * 4;
    uint32_t awoff[4];
#pragma unroll
    for (int mt = 0; mt < 4; mt++)
        awoff[mt] = (uint32_t)((wm * 64 + mt * 16 + arow) * GLD + acol);
    const int bsub = (lane >> 3) & 1;
    uint32_t bwoff[4];
#pragma unroll
    for (int nt = 0; nt < 4; nt++)
        bwoff[nt] = (uint32_t)((wn * 32 + nt * 8 + lrow) * GLD + bsub * 4);

    // prologue: submit stage 0
    {
        const uint32_t stg = sbase;
#pragma unroll
        for (int m = 0; m < 4; m++)
#pragma unroll
            for (int i = 0; i < 2; i++) {
                const int row = crow + i * 64;
                const uint32_t so = stg + (uint32_t)(m * GSTG + row * GLD + cc4 * 4) * 4u;
                CP_ASYNC16(so, src[m] + (size_t)row * KW_ + cc4 * 4);
            }
        CP_COMMIT();
    }

#pragma unroll 1
    for (int kc = 0; kc < 32; kc++) {
        CP_WAIT(0);
        __syncthreads();   // stage kc visible; all reads of stage kc-1 complete

        if (kc + 1 < 32) {
            const uint32_t stg = sbase + ((kc + 1) & 1) * 4 * GSTG * 4;
#pragma unroll
            for (int m = 0; m < 4; m++)
#pragma unroll
                for (int i = 0; i < 2; i++) {
                    const int row = crow + i * 64;
                    const uint32_t so = stg + (uint32_t)(m * GSTG + row * GLD + cc4 * 4) * 4u;
                    CP_ASYNC16(so, src[m] + (size_t)row * KW_ + (kc + 1) * 16 + cc4 * 4);
                }
            CP_COMMIT();
        }

        const uint32_t stg = sbase + (kc & 1) * 4 * GSTG * 4;
        const uint32_t bAh = stg;
        const uint32_t bAl = stg + GSTG * 4;
        const uint32_t bBh = stg + 2 * GSTG * 4;
        const uint32_t bBl = stg + 3 * GSTG * 4;

#pragma unroll
        for (int ks = 0; ks < 2; ks++) {
            const uint32_t k0w = ks * 8;
            uint32_t ah[4][4], al[4][4];
#pragma unroll
            for (int mt = 0; mt < 4; mt++) {
                LDSM_X4(ah[mt][0], ah[mt][1], ah[mt][2], ah[mt][3],
                        bAh + (awoff[mt] + k0w) * 4u);
                LDSM_X4(al[mt][0], al[mt][1], al[mt][2], al[mt][3],
                        bAl + (awoff[mt] + k0w) * 4u);
            }
#pragma unroll
            for (int nt = 0; nt < 4; nt++) {
                uint32_t bh0, bh1, bl0, bl1;
                LDSM_X2(bh0, bh1, bBh + (bwoff[nt] + k0w) * 4u);
                LDSM_X2(bl0, bl1, bBl + (bwoff[nt] + k0w) * 4u);
#pragma unroll
                for (int mt = 0; mt < 4; mt++)
                    MMA_BF16(acc[mt][nt], ah[mt][0], ah[mt][1], ah[mt][2], ah[mt][3], bh0, bh1);
#pragma unroll
                for (int mt = 0; mt < 4; mt++)
                    MMA_BF16(acc[mt][nt], al[mt][0], al[mt][1], al[mt][2], al[mt][3], bh0, bh1);
#pragma unroll
                for (int mt = 0; mt < 4; mt++)
                    MMA_BF16(acc[mt][nt], ah[mt][0], ah[mt][1], ah[mt][2], ah[mt][3], bl0, bl1);
            }
        }
    }

    // ---- epilogue ----
#pragma unroll
    for (int mt = 0; mt < 4; mt++) {
#pragma unroll
        for (int nt = 0; nt < 4; nt++) {
            const int n = n0 + wn * 32 + nt * 8 + tig * 2;
            const float bx = bias[n], by = bias[n + 1];
#pragma unroll
            for (int half = 0; half < 2; half++) {
                const int m = m0 + wm * 64 + mt * 16 + g + half * 8;
                const float vx = acc[mt][nt][half * 2 + 0] + bx;
                const float vy = acc[mt][nt][half * 2 + 1] + by;
                if (QKV) {
                    const int bb = m >> 11;
                    const int tt = m & (T_ - 1);
                    const int which = n >> 10;
                    const int cc = n & (C_ - 1);
                    const int h = cc >> 6;
                    const int d = cc & (HD_ - 1);
                    const size_t base = ((size_t)(bb * NH_ + h) * T_ + tt);
                    if (which == 2) {
                        float2 v; v.x = vx; v.y = vy;
                        *(float2*)&g_v[base * HD_ + d] = v;
                    } else {
                        uint32_t hw, lw;
                        split2(vx, vy, hw, lw);
                        const size_t idx = base * (HD_/2) + (d >> 1);
                        if (which == 0) { g_qhi[idx] = hw; g_qlo[idx] = lw; }
                        else            { g_khi[idx] = hw; g_klo[idx] = lw; }
                    }
                } else {
                    float2 v; v.x = vx; v.y = vy;
                    *(float2*)&out[(size_t)m * NTOT + n] = v;
                }
            }
        }
    }
}

// ===========================================================================
// bf16 HMMA flash attention v5:
//   FA2 register softmax + cp.async double-buffered K + register-prefetched V.
//   Single __syncthreads per key tile.
// Smem (words): Qh 0(4608) Ql 4608 | Kbuf0 9216 Kbuf1 11520 (each Kh 1152 + Kl 1152)
//   | Vbuf0 13824 Vbuf1 16128 (each Vph 1152 + Vpl 1152) -> 18432 words
// ===========================================================================
#define FQ_LD 36
#define FV_LD 72
#define FL_SMEM (18432 * 4)

__global__ __launch_bounds__(256, 2)
void flash_hmma()
{
    extern __shared__ uint32_t smu[];
    const uint32_t sm_base = smem_u32(smu);
    uint32_t* Qh = smu;
    uint32_t* Ql = smu + 4608;

    const uint32_t bQh = sm_base;
    const uint32_t bQl = sm_base + 4608 * 4;
    const uint32_t kbase[2] = { sm_base + 9216 * 4, sm_base + 11520 * 4 };
    const uint32_t vword[2] = { 13824u, 16128u };

    const int tid  = threadIdx.x;
    const int lane = tid & 31;
    const int wm   = tid >> 5;
    const int g    = lane >> 2;
    const int tig  = lane & 3;

    const int qi = blockIdx.x;
    const int bh = blockIdx.y;
    const int q0 = qi * 128;

    const uint32_t* Qgh = g_qhi + (size_t)bh * T_ * 32 + (size_t)q0 * 32;
    const uint32_t* Qgl = g_qlo + (size_t)bh * T_ * 32 + (size_t)q0 * 32;
    const uint32_t* Kgh = g_khi + (size_t)bh * T_ * 32;
    const uint32_t* Kgl = g_klo + (size_t)bh * T_ * 32;
    const float*    Vg  = g_v   + (size_t)bh * T_ * HD_;

    const int sub  = lane >> 3, lrow = lane & 7;

    uint32_t kwoff4[2];
#pragma unroll
    for (int np = 0; np < 2; np++)
        kwoff4[np] = (uint32_t)((np * 16 + (sub >> 1) * 8 + lrow) * FQ_LD + (sub & 1) * 4);

    // K cp.async mapping: tid 0-127 -> Kh, 128-255 -> Kl; 2x16B per thread
    const int km = tid >> 7, kr = (tid >> 2) & 31, kcc = tid & 3;
    const uint32_t kdst = (uint32_t)((km ? 1152 : 0) + kr * FQ_LD + kcc * 8) * 4u;
    const uint32_t* kgsrc = km ? Kgl : Kgh;

    // V prefetch mapping
    const int pr = tid >> 4, d4 = tid & 15;

    const int nkt = 4 * qi + 4;

    // prologue: stage Q, submit K(0), prefetch V(0)
#pragma unroll
    for (int it = 0; it < 4; it++) {
        const int u = tid + it * 256;
        const int r = u >> 3, wc = (u & 7) * 4;
        *(uint4*)&Qh[r * FQ_LD + wc] = *(const uint4*)(Qgh + r * 32 + wc);
        *(uint4*)&Ql[r * FQ_LD + wc] = *(const uint4*)(Qgl + r * 32 + wc);
    }
    CP_ASYNC16(kbase[0] + kdst,      kgsrc + (size_t)kr * 32 + kcc * 8);
    CP_ASYNC16(kbase[0] + kdst + 16, kgsrc + (size_t)kr * 32 + kcc * 8 + 4);
    CP_COMMIT();
    float4 va = *(const float4*)(Vg + (size_t)(2 * pr)     * HD_ + d4 * 4);
    float4 vb = *(const float4*)(Vg + (size_t)(2 * pr + 1) * HD_ + d4 * 4);

    const int rlo = wm * 16 + g;
    const int rhi = rlo + 8;
    __syncthreads();   // Q visible

    // hoist Q fragments (loop-invariant)
    uint32_t qah[4][4], qal[4][4];
    {
        const uint32_t qwoff =
            (uint32_t)((wm * 16 + (sub & 1) * 8 + lrow) * FQ_LD + (sub >> 1) * 4);
#pragma unroll
        for (int ks = 0; ks < 4; ks++) {
            LDSM_X4(qah[ks][0], qah[ks][1], qah[ks][2], qah[ks][3],
                    bQh + (qwoff + ks * 8) * 4u);
            LDSM_X4(qal[ks][0], qal[ks][1], qal[ks][2], qal[ks][3],
                    bQl + (qwoff + ks * 8) * 4u);
        }
    }

    float o[8][4];
#pragma unroll
    for (int nt = 0; nt < 8; nt++)
#pragma unroll
        for (int e = 0; e < 4; e++) o[nt][e] = 0.f;

    float mrun_lo = -INFINITY, mrun_hi = -INFINITY;
    float lrun_lo = 0.f,       lrun_hi = 0.f;

    const int qrow_lo = q0 + rlo;
    const int qrow_hi = q0 + rhi;

#pragma unroll 1
    for (int kt = 0; kt < nkt; kt++) {
        // store prefetched V(kt) into Vbuf[kt&1] (pre-sync: safe, buffer's old
        // readers passed the previous iteration's barrier)
        {
            uint32_t* Vph = smu + vword[kt & 1];
            uint32_t* Vpl = Vph + 1152;
            uint4 h, l;
            split2(va.x, vb.x, h.x, l.x);
            split2(va.y, vb.y, h.y, l.y);
            split2(va.z, vb.z, h.z, l.z);
            split2(va.w, vb.w, h.w, l.w);
            *(uint4*)&Vph[pr * FV_LD + d4 * 4] = h;
            *(uint4*)&Vpl[pr * FV_LD + d4 * 4] = l;
        }
        CP_WAIT(0);        // K(kt) landed
        __syncthreads();   // all buffers for kt visible; kt-1 readers done

        if (kt + 1 < nkt) {
            // submit K(kt+1) (post-sync: target buffer's readers finished)
            CP_ASYNC16(kbase[(kt + 1) & 1] + kdst,
                       kgsrc + (size_t)((kt + 1) * 32 + kr) * 32 + kcc * 8);
            CP_ASYNC16(kbase[(kt + 1) & 1] + kdst + 16,
                       kgsrc + (size_t)((kt + 1) * 32 + kr) * 32 + kcc * 8 + 4);
            CP_COMMIT();
            // prefetch V(kt+1)
            va = *(const float4*)(Vg + (size_t)((kt + 1) * 32 + 2 * pr)     * HD_ + d4 * 4);
            vb = *(const float4*)(Vg + (size_t)((kt + 1) * 32 + 2 * pr + 1) * HD_ + d4 * 4);
        }

        const uint32_t bKh = kbase[kt & 1];
        const uint32_t bKl = bKh + 1152 * 4;
        const uint32_t* Vph = smu + vword[kt & 1];
        const uint32_t* Vpl = Vph + 1152;

        // ---- S = Q @ K^T : warp tile 16x32 ----
        float s[4][4];
#pragma unroll
        for (int nt = 0; nt < 4; nt++)
#pragma unroll
            for (int e = 0; e < 4; e++) s[nt][e] = 0.f;

#pragma unroll
        for (int ks = 0; ks < 4; ks++) {
#pragma unroll
            for (int np = 0; np < 2; np++) {
                uint32_t bh0, bh1, bh2, bh3, bl0, bl1, bl2, bl3;
                LDSM_X4(bh0, bh1, bh2, bh3, bKh + (kwoff4[np] + ks * 8) * 4u);
                LDSM_X4(bl0, bl1, bl2, bl3, bKl + (kwoff4[np] + ks * 8) * 4u);
                MMA_BF16(s[2*np],   qah[ks][0], qah[ks][1], qah[ks][2], qah[ks][3], bh0, bh1);
                MMA_BF16(s[2*np+1], qah[ks][0], qah[ks][1], qah[ks][2], qah[ks][3], bh2, bh3);
                MMA_BF16(s[2*np],   qal[ks][0], qal[ks][1], qal[ks][2], qal[ks][3], bh0, bh1);
                MMA_BF16(s[2*np+1], qal[ks][0], qal[ks][1], qal[ks][2], qal[ks][3], bh2, bh3);
                MMA_BF16(s[2*np],   qah[ks][0], qah[ks][1], qah[ks][2], qah[ks][3], bl0, bl1);
                MMA_BF16(s[2*np+1], qah[ks][0], qah[ks][1], qah[ks][2], qah[ks][3], bl2, bl3);
            }
        }

        // ---- scale + causal mask + row max ----
        float mlo = -INFINITY, mhi = -INFINITY;
        const bool needmask = (kt * 32 + 31) > (q0 + wm * 16);
#pragma unroll
        for (int nt = 0; nt < 4; nt++) {
            const int colb = kt * 32 + nt * 8 + 2 * tig;
#pragma unroll
            for (int j = 0; j < 2; j++) {
                float v0 = s[nt][j] * 0.125f;
                float v1 = s[nt][2 + j] * 0.125f;
                if (needmask) {
                    if (colb + j > qrow_lo) v0 = -INFINITY;
                    if (colb + j > qrow_hi) v1 = -INFINITY;
                }
                s[nt][j] = v0;
                s[nt][2 + j] = v1;
                mlo = fmaxf(mlo, v0);
                mhi = fmaxf(mhi, v1);
            }
        }
#pragma unroll
        for (int off = 1; off < 4; off <<= 1) {
            mlo = fmaxf(mlo, __shfl_xor_sync(0xffffffffu, mlo, off));
            mhi = fmaxf(mhi, __shfl_xor_sync(0xffffffffu, mhi, off));
        }

        // ---- online softmax (registers) ----
        const float mnew_lo = fmaxf(mrun_lo, mlo);
        const float mnew_hi = fmaxf(mrun_hi, mhi);
        const float corr_lo = __expf(mrun_lo - mnew_lo);
        const float corr_hi = __expf(mrun_hi - mnew_hi);
        mrun_lo = mnew_lo; mrun_hi = mnew_hi;

        float sumlo = 0.f, sumhi = 0.f;
        uint32_t pah[2][4], pal[2][4];
#pragma unroll
        for (int nt = 0; nt < 4; nt++) {
            float p0 = __expf(s[nt][0] - mnew_lo);
            float p1 = __expf(s[nt][1] - mnew_lo);
            float p2 = __expf(s[nt][2] - mnew_hi);
            float p3 = __expf(s[nt][3] - mnew_hi);
            sumlo += p0 + p1;
            sumhi += p2 + p3;
            const int ks = nt >> 1;
            const int hi2 = (nt & 1) * 2;
            split2(p0, p1, pah[ks][hi2],     pal[ks][hi2]);
            split2(p2, p3, pah[ks][hi2 + 1], pal[ks][hi2 + 1]);
        }
#pragma unroll
        for (int off = 1; off < 4; off <<= 1) {
            sumlo += __shfl_xor_sync(0xffffffffu, sumlo, off);
            sumhi += __shfl_xor_sync(0xffffffffu, sumhi, off);
        }
        lrun_lo = lrun_lo * corr_lo + sumlo;
        lrun_hi = lrun_hi * corr_hi + sumhi;

#pragma unroll
        for (int nt = 0; nt < 8; nt++) {
            o[nt][0] *= corr_lo; o[nt][1] *= corr_lo;
            o[nt][2] *= corr_hi; o[nt][3] *= corr_hi;
        }

        // ---- O += P @ V ----
#pragma unroll
        for (int ks = 0; ks < 2; ks++) {
#pragma unroll
            for (int nt = 0; nt < 8; nt++) {
                const int col = nt * 8 + g;
                const int b0i = (ks * 8 + tig)     * FV_LD + col;
                const int b1i = (ks * 8 + tig + 4) * FV_LD + col;
                const uint32_t vh0 = Vph[b0i], vh1 = Vph[b1i];
                const uint32_t vl0 = Vpl[b0i], vl1 = Vpl[b1i];
                MMA_BF16(o[nt], pah[ks][0], pah[ks][1], pah[ks][2], pah[ks][3], vh0, vh1);
                MMA_BF16(o[nt], pal[ks][0], pal[ks][1], pal[ks][2], pal[ks][3], vh0, vh1);
                MMA_BF16(o[nt], pah[ks][0], pah[ks][1], pah[ks][2], pah[ks][3], vl0, vl1);
            }
        }
    }

    // ---- normalize + store split-packed output ----
    const float inv_lo = 1.f / lrun_lo;
    const float inv_hi = 1.f / lrun_hi;
    const int b = bh >> 4, h = bh & 15;
    const int t_lo = q0 + rlo, t_hi = q0 + rhi;
#pragma unroll
    for (int nt = 0; nt < 8; nt++) {
        const int d = nt * 8 + 2 * tig;
        const int w = (h * HD_ + d) >> 1;
        uint32_t hw, lw;
        split2(o[nt][0] * inv_lo, o[nt][1] * inv_lo, hw, lw);
        g_ahi[(size_t)(b * T_ + t_lo) * KW_ + w] = hw;
        g_alo[(size_t)(b * T_ + t_lo) * KW_ + w] = lw;
        split2(o[nt][2] * inv_hi, o[nt][3] * inv_hi, hw, lw);
        g_ahi[(size_t)(b * T_ + t_hi) * KW_ + w] = hw;
        g_alo[(size_t)(b * T_ + t_hi) * KW_ + w] = lw;
    }
}

// ===========================================================================
// Launch
// ===========================================================================
extern "C" void kernel_launch(void* const* d_in, const int* in_sizes, int n_in,
                              void* d_out, int out_size)
{
    const float* x      = (const float*)d_in[0];
    const float* w_attn = (const float*)d_in[1];
    const float* b_attn = (const float*)d_in[2];
    const float* w_proj = (const float*)d_in[3];
    const float* b_proj = (const float*)d_in[4];
    float* out = (float*)d_out;

    uint32_t *xhi, *xlo, *ahi, *alo, *wthi, *wtlo, *wphi, *wplo;
    cudaGetSymbolAddress((void**)&xhi,  g_xhi);
    cudaGetSymbolAddress((void**)&xlo,  g_xlo);
    cudaGetSymbolAddress((void**)&ahi,  g_ahi);
    cudaGetSymbolAddress((void**)&alo,  g_alo);
    cudaGetSymbolAddress((void**)&wthi, g_wthi);
    cudaGetSymbolAddress((void**)&wtlo, g_wtlo);
    cudaGetSymbolAddress((void**)&wphi, g_wphi);
    cudaGetSymbolAddress((void**)&wplo, g_wplo);

    cudaFuncSetAttribute(flash_hmma,
                         cudaFuncAttributeMaxDynamicSharedMemorySize, FL_SMEM);
    cudaFuncSetAttribute(hmma_gemm<3072, true>,
                         cudaFuncAttributeMaxDynamicSharedMemorySize, GEMM_SMEM);
    cudaFuncSetAttribute(hmma_gemm<1024, false>,
                         cudaFuncAttributeMaxDynamicSharedMemorySize, GEMM_SMEM);

    split_pack_elem<<<(M_*C_/4 + 255)/256, 256>>>(x, xhi, xlo, M_*C_/4);
    transpose_split_pack<<<dim3(3072/32, 1024/32), 256>>>(w_attn, wthi, wtlo, 1024, 3072);
    transpose_split_pack<<<dim3(1024/32, 1024/32), 256>>>(w_proj, wphi, wplo, 1024, 1024);

    hmma_gemm<3072, true><<<dim3(3072/128, M_/128), 256, GEMM_SMEM>>>(
        xhi, xlo, wthi, wtlo, b_attn, nullptr);

    flash_hmma<<<dim3(T_/128, B_*NH_), 256, FL_SMEM>>>();

    hmma_gemm<1024, false><<<dim3(1024/128, M_/128), 256, GEMM_SMEM>>>(
        ahi, alo, wphi, wplo, b_proj, out);
}

// round 13
// speedup vs baseline: 3.6742x; 1.2530x over previous
#include <cuda_runtime.h>
#include <cuda.h>
#include <math.h>
#include <stdint.h>

#define B_   4
#define T_   2048
#define C_   1024
#define NH_  16
#define HD_  64
#define M_   (B_*T_)      // 8192
#define KW_  (C_/2)       // 512 packed words per K=1024 row

// Scratch (allocation-free: __device__ globals)
__device__ uint32_t g_qhi[B_*NH_*T_*HD_/2], g_qlo[B_*NH_*T_*HD_/2];
__device__ uint32_t g_khi[B_*NH_*T_*HD_/2], g_klo[B_*NH_*T_*HD_/2];
__device__ float    g_v  [B_*NH_*T_*HD_];
__device__ uint32_t g_xhi[M_*KW_],  g_xlo[M_*KW_];      // fp16 split x
__device__ uint32_t g_ahi[M_*KW_],  g_alo[M_*KW_];      // bf16 split attention out
__device__ uint32_t g_wthi[3*C_*KW_];                   // w_attn^T fp16 (hi only)
__device__ uint32_t g_wphi[C_*KW_],   g_wplo[C_*KW_];   // w_proj^T bf16 split

// ===========================================================================
// Helpers
// ===========================================================================
// bf16 pair split (even in low 16)
__device__ __forceinline__ void split2(float e, float o, uint32_t& hi, uint32_t& lo) {
    asm("cvt.rn.bf16x2.f32 %0, %1, %2;" : "=r"(hi) : "f"(o), "f"(e));
    float he = __uint_as_float(hi << 16);
    float ho = __uint_as_float(hi & 0xffff0000u);
    asm("cvt.rn.bf16x2.f32 %0, %1, %2;" : "=r"(lo) : "f"(o - ho), "f"(e - he));
}
// fp16 pair split (even in low 16)
__device__ __forceinline__ void split2h(float e, float o, uint32_t& hi, uint32_t& lo) {
    asm("cvt.rn.f16x2.f32 %0, %1, %2;" : "=r"(hi) : "f"(o), "f"(e));
    float he, ho;
    asm("{.reg .f16 a,b;\n\tmov.b32 {a,b}, %2;\n\tcvt.f32.f16 %0, a;\n\tcvt.f32.f16 %1, b;}"
        : "=f"(he), "=f"(ho) : "r"(hi));
    asm("cvt.rn.f16x2.f32 %0, %1, %2;" : "=r"(lo) : "f"(o - ho), "f"(e - he));
}
// fp16 pair round (hi only)
__device__ __forceinline__ uint32_t pack2h(float e, float o) {
    uint32_t hi;
    asm("cvt.rn.f16x2.f32 %0, %1, %2;" : "=r"(hi) : "f"(o), "f"(e));
    return hi;
}

#define MMA_BF16(c, a0v, a1v, a2v, a3v, b0v, b1v) \
    asm volatile("mma.sync.aligned.m16n8k16.row.col.f32.bf16.bf16.f32 " \
        "{%0,%1,%2,%3}, {%4,%5,%6,%7}, {%8,%9}, {%0,%1,%2,%3};" \
        : "+f"((c)[0]), "+f"((c)[1]), "+f"((c)[2]), "+f"((c)[3]) \
        : "r"(a0v), "r"(a1v), "r"(a2v), "r"(a3v), "r"(b0v), "r"(b1v))

#define MMA_F16(c, a0v, a1v, a2v, a3v, b0v, b1v) \
    asm volatile("mma.sync.aligned.m16n8k16.row.col.f32.f16.f16.f32 " \
        "{%0,%1,%2,%3}, {%4,%5,%6,%7}, {%8,%9}, {%0,%1,%2,%3};" \
        : "+f"((c)[0]), "+f"((c)[1]), "+f"((c)[2]), "+f"((c)[3]) \
        : "r"(a0v), "r"(a1v), "r"(a2v), "r"(a3v), "r"(b0v), "r"(b1v))

#define LDSM_X4(r0,r1,r2,r3, addr) \
    asm volatile("ldmatrix.sync.aligned.m8n8.x4.shared.b16 {%0,%1,%2,%3}, [%4];" \
        : "=r"(r0), "=r"(r1), "=r"(r2), "=r"(r3) : "r"(addr))
#define LDSM_X2(r0,r1, addr) \
    asm volatile("ldmatrix.sync.aligned.m8n8.x2.shared.b16 {%0,%1}, [%2];" \
        : "=r"(r0), "=r"(r1) : "r"(addr))

__device__ __forceinline__ uint32_t smem_u32(const void* p) {
    uint32_t a;
    asm("{ .reg .u64 t; cvta.to.shared.u64 t, %1; cvt.u32.u64 %0, t; }" : "=r"(a) : "l"(p));
    return a;
}
#define CP_ASYNC16(saddr, gptr) \
    asm volatile("cp.async.cg.shared.global [%0], [%1], 16;" :: "r"(saddr), "l"(gptr))
#define CP_COMMIT() asm volatile("cp.async.commit_group;" ::: "memory")
#define CP_WAIT(n)  asm volatile("cp.async.wait_group %0;" :: "n"(n) : "memory")

// ===========================================================================
// Prologue kernels
// ===========================================================================
__global__ __launch_bounds__(256)
void split_pack_elem_f16(const float* __restrict__ in, uint32_t* __restrict__ hi,
                         uint32_t* __restrict__ lo, int n4)
{
    int i = blockIdx.x * 256 + threadIdx.x;
    if (i < n4) {
        float4 v = ((const float4*)in)[i];
        uint2 h, l;
        split2h(v.x, v.y, h.x, l.x);
        split2h(v.z, v.w, h.y, l.y);
        ((uint2*)hi)[i] = h;
        ((uint2*)lo)[i] = l;
    }
}

// transpose + fp16 round (hi only): in [R=k][C=n] -> out[n][R/2 words]
__global__ __launch_bounds__(256)
void transpose_pack_f16(const float* __restrict__ in, uint32_t* __restrict__ ohi,
                        int R, int C)
{
    __shared__ float t[32][33];
    const int tx = threadIdx.x & 31, ty = (threadIdx.x >> 5) & 7;
    const int x0 = blockIdx.x * 32;
    const int y0 = blockIdx.y * 32;
#pragma unroll
    for (int i = 0; i < 32; i += 8)
        t[ty + i][tx] = in[(size_t)(y0 + ty + i) * C + x0 + tx];
    __syncthreads();
    const int Rw = R >> 1;
    const int wl = threadIdx.x & 15;
    const int nl = threadIdx.x >> 4;
#pragma unroll
    for (int half = 0; half < 2; half++) {
        const int n_l = nl + half * 16;
        ohi[(size_t)(x0 + n_l) * Rw + (y0 >> 1) + wl] =
            pack2h(t[2 * wl][n_l], t[2 * wl + 1][n_l]);
    }
}

// transpose + bf16 split: in [R=k][C=n] -> out_{hi,lo}[n][R/2 words]
__global__ __launch_bounds__(256)
void transpose_split_pack(const float* __restrict__ in, uint32_t* __restrict__ ohi,
                          uint32_t* __restrict__ olo, int R, int C)
{
    __shared__ float t[32][33];
    const int tx = threadIdx.x & 31, ty = (threadIdx.x >> 5) & 7;
    const int x0 = blockIdx.x * 32;
    const int y0 = blockIdx.y * 32;
#pragma unroll
    for (int i = 0; i < 32; i += 8)
        t[ty + i][tx] = in[(size_t)(y0 + ty + i) * C + x0 + tx];
    __syncthreads();
    const int Rw = R >> 1;
    const int wl = threadIdx.x & 15;
    const int nl = threadIdx.x >> 4;
#pragma unroll
    for (int half = 0; half < 2; half++) {
        const int n_l = nl + half * 16;
        uint32_t h, l;
        split2(t[2 * wl][n_l], t[2 * wl + 1][n_l], h, l);
        const size_t idx = (size_t)(x0 + n_l) * Rw + (y0 >> 1) + wl;
        ohi[idx] = h;
        olo[idx] = l;
    }
}

// ===========================================================================
// HMMA GEMM. F16_2T=true: fp16 2-term (Ah,Al,Bh — 3 staged matrices);
//            F16_2T=false: bf16 3-term (Ah,Al,Bh,Bl — 4 staged matrices).
//   Single barrier per K chunk: wait -> sync -> submit next -> compute.
// ===========================================================================
#define GLD 20
#define GSTG (128*GLD)
#define GEMM_SMEM_3 (6*GSTG*4)    // 61440
#define GEMM_SMEM_4 (8*GSTG*4)    // 81920

template<int NTOT, bool QKV, bool F16_2T>
__global__ __launch_bounds__(256, 2)
void hmma_gemm(const uint32_t* __restrict__ Ahi, const uint32_t* __restrict__ Alo,
               const uint32_t* __restrict__ Bhi, const uint32_t* __restrict__ Blo,
               const float* __restrict__ bias, float* __restrict__ out)
{
    constexpr int NMAT = F16_2T ? 3 : 4;
    extern __shared__ uint32_t smu[];
    const uint32_t sbase = smem_u32(smu);

    const int tid  = threadIdx.x;
    const int lane = tid & 31;
    const int wid  = tid >> 5;
    const int wm   = wid & 1;
    const int wn   = wid >> 1;
    const int m0   = blockIdx.y * 128;
    const int n0   = blockIdx.x * 128;
    const int g    = lane >> 2;
    const int tig  = lane & 3;

    const uint32_t* src[4];
    src[0] = Ahi + (size_t)m0 * KW_;
    src[1] = Alo + (size_t)m0 * KW_;
    src[2] = Bhi + (size_t)n0 * KW_;
    src[3] = F16_2T ? nullptr : (Blo + (size_t)n0 * KW_);

    float acc[4][4][4];
#pragma unroll
    for (int i = 0; i < 4; i++)
#pragma unroll
        for (int j = 0; j < 4; j++)
#pragma unroll
            for (int e = 0; e < 4; e++) acc[i][j][e] = 0.f;

    const int crow = tid >> 2;
    const int cc4  = tid & 3;

    const int sub  = lane >> 3, lrow = lane & 7;
    const int arow = (sub & 1) * 8 + lrow;
    const int acol = (sub >> 1) * 4;
    uint32_t awoff[4];
#pragma unroll
    for (int mt = 0; mt < 4; mt++)
        awoff[mt] = (uint32_t)((wm * 64 + mt * 16 + arow) * GLD + acol);
    const int bsub = (lane >> 3) & 1;
    uint32_t bwoff[4];
#pragma unroll
    for (int nt = 0; nt < 4; nt++)
        bwoff[nt] = (uint32_t)((wn * 32 + nt * 8 + lrow) * GLD + bsub * 4);

    // prologue: submit stage 0
    {
#pragma unroll
        for (int m = 0; m < NMAT; m++)
#pragma unroll
            for (int i = 0; i < 2; i++) {
                const int row = crow + i * 64;
                const uint32_t so = sbase + (uint32_t)(m * GSTG + row * GLD + cc4 * 4) * 4u;
                CP_ASYNC16(so, src[m] + (size_t)row * KW_ + cc4 * 4);
            }
        CP_COMMIT();
    }

#pragma unroll 1
    for (int kc = 0; kc < 32; kc++) {
        CP_WAIT(0);
        __syncthreads();

        if (kc + 1 < 32) {
            const uint32_t stg = sbase + ((kc + 1) & 1) * NMAT * GSTG * 4;
#pragma unroll
            for (int m = 0; m < NMAT; m++)
#pragma unroll
                for (int i = 0; i < 2; i++) {
                    const int row = crow + i * 64;
                    const uint32_t so = stg + (uint32_t)(m * GSTG + row * GLD + cc4 * 4) * 4u;
                    CP_ASYNC16(so, src[m] + (size_t)row * KW_ + (kc + 1) * 16 + cc4 * 4);
                }
            CP_COMMIT();
        }

        const uint32_t stg = sbase + (kc & 1) * NMAT * GSTG * 4;
        const uint32_t bAh = stg;
        const uint32_t bAl = stg + GSTG * 4;
        const uint32_t bBh = stg + 2 * GSTG * 4;
        const uint32_t bBl = stg + 3 * GSTG * 4;   // only valid when NMAT==4

#pragma unroll
        for (int ks = 0; ks < 2; ks++) {
            const uint32_t k0w = ks * 8;
            uint32_t ah[4][4], al[4][4];
#pragma unroll
            for (int mt = 0; mt < 4; mt++) {
                LDSM_X4(ah[mt][0], ah[mt][1], ah[mt][2], ah[mt][3],
                        bAh + (awoff[mt] + k0w) * 4u);
                LDSM_X4(al[mt][0], al[mt][1], al[mt][2], al[mt][3],
                        bAl + (awoff[mt] + k0w) * 4u);
            }
#pragma unroll
            for (int nt = 0; nt < 4; nt++) {
                if (F16_2T) {
                    uint32_t bh0, bh1;
                    LDSM_X2(bh0, bh1, bBh + (bwoff[nt] + k0w) * 4u);
#pragma unroll
                    for (int mt = 0; mt < 4; mt++)
                        MMA_F16(acc[mt][nt], ah[mt][0], ah[mt][1], ah[mt][2], ah[mt][3], bh0, bh1);
#pragma unroll
                    for (int mt = 0; mt < 4; mt++)
                        MMA_F16(acc[mt][nt], al[mt][0], al[mt][1], al[mt][2], al[mt][3], bh0, bh1);
                } else {
                    uint32_t bh0, bh1, bl0, bl1;
                    LDSM_X2(bh0, bh1, bBh + (bwoff[nt] + k0w) * 4u);
                    LDSM_X2(bl0, bl1, bBl + (bwoff[nt] + k0w) * 4u);
#pragma unroll
                    for (int mt = 0; mt < 4; mt++)
                        MMA_BF16(acc[mt][nt], ah[mt][0], ah[mt][1], ah[mt][2], ah[mt][3], bh0, bh1);
#pragma unroll
                    for (int mt = 0; mt < 4; mt++)
                        MMA_BF16(acc[mt][nt], al[mt][0], al[mt][1], al[mt][2], al[mt][3], bh0, bh1);
#pragma unroll
                    for (int mt = 0; mt < 4; mt++)
                        MMA_BF16(acc[mt][nt], ah[mt][0], ah[mt][1], ah[mt][2], ah[mt][3], bl0, bl1);
                }
            }
        }
    }

    // ---- epilogue ----
#pragma unroll
    for (int mt = 0; mt < 4; mt++) {
#pragma unroll
        for (int nt = 0; nt < 4; nt++) {
            const int n = n0 + wn * 32 + nt * 8 + tig * 2;
            const float bx = bias[n], by = bias[n + 1];
#pragma unroll
            for (int half = 0; half < 2; half++) {
                const int m = m0 + wm * 64 + mt * 16 + g + half * 8;
                const float vx = acc[mt][nt][half * 2 + 0] + bx;
                const float vy = acc[mt][nt][half * 2 + 1] + by;
                if (QKV) {
                    const int bb = m >> 11;
                    const int tt = m & (T_ - 1);
                    const int which = n >> 10;
                    const int cc = n & (C_ - 1);
                    const int h = cc >> 6;
                    const int d = cc & (HD_ - 1);
                    const size_t base = ((size_t)(bb * NH_ + h) * T_ + tt);
                    if (which == 2) {
                        float2 v; v.x = vx; v.y = vy;
                        *(float2*)&g_v[base * HD_ + d] = v;
                    } else {
                        uint32_t hw, lw;
                        split2(vx, vy, hw, lw);
                        const size_t idx = base * (HD_/2) + (d >> 1);
                        if (which == 0) { g_qhi[idx] = hw; g_qlo[idx] = lw; }
                        else            { g_khi[idx] = hw; g_klo[idx] = lw; }
                    }
                } else {
                    float2 v; v.x = vx; v.y = vy;
                    *(float2*)&out[(size_t)m * NTOT + n] = v;
                }
            }
        }
    }
}

// ===========================================================================
// bf16 HMMA flash attention v5 + tail-packed grid:
//   grid (bh=64, qs=16), qi = 15 - blockIdx.y  (monster CTAs scheduled first)
// ===========================================================================
#define FQ_LD 36
#define FV_LD 72
#define FL_SMEM (18432 * 4)

__global__ __launch_bounds__(256, 2)
void flash_hmma()
{
    extern __shared__ uint32_t smu[];
    const uint32_t sm_base = smem_u32(smu);
    uint32_t* Qh = smu;
    uint32_t* Ql = smu + 4608;

    const uint32_t bQh = sm_base;
    const uint32_t bQl = sm_base + 4608 * 4;
    const uint32_t kbase[2] = { sm_base + 9216 * 4, sm_base + 11520 * 4 };
    const uint32_t vword[2] = { 13824u, 16128u };

    const int tid  = threadIdx.x;
    const int lane = tid & 31;
    const int wm   = tid >> 5;
    const int g    = lane >> 2;
    const int tig  = lane & 3;

    const int bh = blockIdx.x;            // 0..63
    const int qi = 15 - blockIdx.y;       // big qi scheduled first
    const int q0 = qi * 128;

    const uint32_t* Qgh = g_qhi + (size_t)bh * T_ * 32 + (size_t)q0 * 32;
    const uint32_t* Qgl = g_qlo + (size_t)bh * T_ * 32 + (size_t)q0 * 32;
    const uint32_t* Kgh = g_khi + (size_t)bh * T_ * 32;
    const uint32_t* Kgl = g_klo + (size_t)bh * T_ * 32;
    const float*    Vg  = g_v   + (size_t)bh * T_ * HD_;

    const int sub  = lane >> 3, lrow = lane & 7;

    uint32_t kwoff4[2];
#pragma unroll
    for (int np = 0; np < 2; np++)
        kwoff4[np] = (uint32_t)((np * 16 + (sub >> 1) * 8 + lrow) * FQ_LD + (sub & 1) * 4);

    const int km = tid >> 7, kr = (tid >> 2) & 31, kcc = tid & 3;
    const uint32_t kdst = (uint32_t)((km ? 1152 : 0) + kr * FQ_LD + kcc * 8) * 4u;
    const uint32_t* kgsrc = km ? Kgl : Kgh;

    const int pr = tid >> 4, d4 = tid & 15;

    const int nkt = 4 * qi + 4;

    // prologue: stage Q, submit K(0), prefetch V(0)
#pragma unroll
    for (int it = 0; it < 4; it++) {
        const int u = tid + it * 256;
        const int r = u >> 3, wc = (u & 7) * 4;
        *(uint4*)&Qh[r * FQ_LD + wc] = *(const uint4*)(Qgh + r * 32 + wc);
        *(uint4*)&Ql[r * FQ_LD + wc] = *(const uint4*)(Qgl + r * 32 + wc);
    }
    CP_ASYNC16(kbase[0] + kdst,      kgsrc + (size_t)kr * 32 + kcc * 8);
    CP_ASYNC16(kbase[0] + kdst + 16, kgsrc + (size_t)kr * 32 + kcc * 8 + 4);
    CP_COMMIT();
    float4 va = *(const float4*)(Vg + (size_t)(2 * pr)     * HD_ + d4 * 4);
    float4 vb = *(const float4*)(Vg + (size_t)(2 * pr + 1) * HD_ + d4 * 4);

    const int rlo = wm * 16 + g;
    const int rhi = rlo + 8;
    __syncthreads();

    uint32_t qah[4][4], qal[4][4];
    {
        const uint32_t qwoff =
            (uint32_t)((wm * 16 + (sub & 1) * 8 + lrow) * FQ_LD + (sub >> 1) * 4);
#pragma unroll
        for (int ks = 0; ks < 4; ks++) {
            LDSM_X4(qah[ks][0], qah[ks][1], qah[ks][2], qah[ks][3],
                    bQh + (qwoff + ks * 8) * 4u);
            LDSM_X4(qal[ks][0], qal[ks][1], qal[ks][2], qal[ks][3],
                    bQl + (qwoff + ks * 8) * 4u);
        }
    }

    float o[8][4];
#pragma unroll
    for (int nt = 0; nt < 8; nt++)
#pragma unroll
        for (int e = 0; e < 4; e++) o[nt][e] = 0.f;

    float mrun_lo = -INFINITY, mrun_hi = -INFINITY;
    float lrun_lo = 0.f,       lrun_hi = 0.f;

    const int qrow_lo = q0 + rlo;
    const int qrow_hi = q0 + rhi;

#pragma unroll 1
    for (int kt = 0; kt < nkt; kt++) {
        {
            uint32_t* Vph = smu + vword[kt & 1];
            uint32_t* Vpl = Vph + 1152;
            uint4 h, l;
            split2(va.x, vb.x, h.x, l.x);
            split2(va.y, vb.y, h.y, l.y);
            split2(va.z, vb.z, h.z, l.z);
            split2(va.w, vb.w, h.w, l.w);
            *(uint4*)&Vph[pr * FV_LD + d4 * 4] = h;
            *(uint4*)&Vpl[pr * FV_LD + d4 * 4] = l;
        }
        CP_WAIT(0);
        __syncthreads();

        if (kt + 1 < nkt) {
            CP_ASYNC16(kbase[(kt + 1) & 1] + kdst,
                       kgsrc + (size_t)((kt + 1) * 32 + kr) * 32 + kcc * 8);
            CP_ASYNC16(kbase[(kt + 1) & 1] + kdst + 16,
                       kgsrc + (size_t)((kt + 1) * 32 + kr) * 32 + kcc * 8 + 4);
            CP_COMMIT();
            va = *(const float4*)(Vg + (size_t)((kt + 1) * 32 + 2 * pr)     * HD_ + d4 * 4);
            vb = *(const float4*)(Vg + (size_t)((kt + 1) * 32 + 2 * pr + 1) * HD_ + d4 * 4);
        }

        const uint32_t bKh = kbase[kt & 1];
        const uint32_t bKl = bKh + 1152 * 4;
        const uint32_t* Vph = smu + vword[kt & 1];
        const uint32_t* Vpl = Vph + 1152;

        float s[4][4];
#pragma unroll
        for (int nt = 0; nt < 4; nt++)
#pragma unroll
            for (int e = 0; e < 4; e++) s[nt][e] = 0.f;

#pragma unroll
        for (int ks = 0; ks < 4; ks++) {
#pragma unroll
            for (int np = 0; np < 2; np++) {
                uint32_t bh0, bh1, bh2, bh3, bl0, bl1, bl2, bl3;
                LDSM_X4(bh0, bh1, bh2, bh3, bKh + (kwoff4[np] + ks * 8) * 4u);
                LDSM_X4(bl0, bl1, bl2, bl3, bKl + (kwoff4[np] + ks * 8) * 4u);
                MMA_BF16(s[2*np],   qah[ks][0], qah[ks][1], qah[ks][2], qah[ks][3], bh0, bh1);
                MMA_BF16(s[2*np+1], qah[ks][0], qah[ks][1], qah[ks][2], qah[ks][3], bh2, bh3);
                MMA_BF16(s[2*np],   qal[ks][0], qal[ks][1], qal[ks][2], qal[ks][3], bh0, bh1);
                MMA_BF16(s[2*np+1], qal[ks][0], qal[ks][1], qal[ks][2], qal[ks][3], bh2, bh3);
                MMA_BF16(s[2*np],   qah[ks][0], qah[ks][1], qah[ks][2], qah[ks][3], bl0, bl1);
                MMA_BF16(s[2*np+1], qah[ks][0], qah[ks][1], qah[ks][2], qah[ks][3], bl2, bl3);
            }
        }

        float mlo = -INFINITY, mhi = -INFINITY;
        const bool needmask = (kt * 32 + 31) > (q0 + wm * 16);
#pragma unroll
        for (int nt = 0; nt < 4; nt++) {
            const int colb = kt * 32 + nt * 8 + 2 * tig;
#pragma unroll
            for (int j = 0; j < 2; j++) {
                float v0 = s[nt][j] * 0.125f;
                float v1 = s[nt][2 + j] * 0.125f;
                if (needmask) {
                    if (colb + j > qrow_lo) v0 = -INFINITY;
                    if (colb + j > qrow_hi) v1 = -INFINITY;
                }
                s[nt][j] = v0;
                s[nt][2 + j] = v1;
                mlo = fmaxf(mlo, v0);
                mhi = fmaxf(mhi, v1);
            }
        }
#pragma unroll
        for (int off = 1; off < 4; off <<= 1) {
            mlo = fmaxf(mlo, __shfl_xor_sync(0xffffffffu, mlo, off));
            mhi = fmaxf(mhi, __shfl_xor_sync(0xffffffffu, mhi, off));
        }

        const float mnew_lo = fmaxf(mrun_lo, mlo);
        const float mnew_hi = fmaxf(mrun_hi, mhi);
        const float corr_lo = __expf(mrun_lo - mnew_lo);
        const float corr_hi = __expf(mrun_hi - mnew_hi);
        mrun_lo = mnew_lo; mrun_hi = mnew_hi;

        float sumlo = 0.f, sumhi = 0.f;
        uint32_t pah[2][4], pal[2][4];
#pragma unroll
        for (int nt = 0; nt < 4; nt++) {
            float p0 = __expf(s[nt][0] - mnew_lo);
            float p1 = __expf(s[nt][1] - mnew_lo);
            float p2 = __expf(s[nt][2] - mnew_hi);
            float p3 = __expf(s[nt][3] - mnew_hi);
            sumlo += p0 + p1;
            sumhi += p2 + p3;
            const int ks = nt >> 1;
            const int hi2 = (nt & 1) * 2;
            split2(p0, p1, pah[ks][hi2],     pal[ks][hi2]);
            split2(p2, p3, pah[ks][hi2 + 1], pal[ks][hi2 + 1]);
        }
#pragma unroll
        for (int off = 1; off < 4; off <<= 1) {
            sumlo += __shfl_xor_sync(0xffffffffu, sumlo, off);
            sumhi += __shfl_xor_sync(0xffffffffu, sumhi, off);
        }
        lrun_lo = lrun_lo * corr_lo + sumlo;
        lrun_hi = lrun_hi * corr_hi + sumhi;

#pragma unroll
        for (int nt = 0; nt < 8; nt++) {
            o[nt][0] *= corr_lo; o[nt][1] *= corr_lo;
            o[nt][2] *= corr_hi; o[nt][3] *= corr_hi;
        }

#pragma unroll
        for (int ks = 0; ks < 2; ks++) {
#pragma unroll
            for (int nt = 0; nt < 8; nt++) {
                const int col = nt * 8 + g;
                const int b0i = (ks * 8 + tig)     * FV_LD + col;
                const int b1i = (ks * 8 + tig + 4) * FV_LD + col;
                const uint32_t vh0 = Vph[b0i], vh1 = Vph[b1i];
                const uint32_t vl0 = Vpl[b0i], vl1 = Vpl[b1i];
                MMA_BF16(o[nt], pah[ks][0], pah[ks][1], pah[ks][2], pah[ks][3], vh0, vh1);
                MMA_BF16(o[nt], pal[ks][0], pal[ks][1], pal[ks][2], pal[ks][3], vh0, vh1);
                MMA_BF16(o[nt], pah[ks][0], pah[ks][1], pah[ks][2], pah[ks][3], vl0, vl1);
            }
        }
    }

    const float inv_lo = 1.f / lrun_lo;
    const float inv_hi = 1.f / lrun_hi;
    const int b = bh >> 4, h = bh & 15;
    const int t_lo = q0 + rlo, t_hi = q0 + rhi;
#pragma unroll
    for (int nt = 0; nt < 8; nt++) {
        const int d = nt * 8 + 2 * tig;
        const int w = (h * HD_ + d) >> 1;
        uint32_t hw, lw;
        split2(o[nt][0] * inv_lo, o[nt][1] * inv_lo, hw, lw);
        g_ahi[(size_t)(b * T_ + t_lo) * KW_ + w] = hw;
        g_alo[(size_t)(b * T_ + t_lo) * KW_ + w] = lw;
        split2(o[nt][2] * inv_hi, o[nt][3] * inv_hi, hw, lw);
        g_ahi[(size_t)(b * T_ + t_hi) * KW_ + w] = hw;
        g_alo[(size_t)(b * T_ + t_hi) * KW_ + w] = lw;
    }
}

// ===========================================================================
// Launch
// ===========================================================================
extern "C" void kernel_launch(void* const* d_in, const int* in_sizes, int n_in,
                              void* d_out, int out_size)
{
    const float* x      = (const float*)d_in[0];
    const float* w_attn = (const float*)d_in[1];
    const float* b_attn = (const float*)d_in[2];
    const float* w_proj = (const float*)d_in[3];
    const float* b_proj = (const float*)d_in[4];
    float* out = (float*)d_out;

    uint32_t *xhi, *xlo, *ahi, *alo, *wthi, *wphi, *wplo;
    cudaGetSymbolAddress((void**)&xhi,  g_xhi);
    cudaGetSymbolAddress((void**)&xlo,  g_xlo);
    cudaGetSymbolAddress((void**)&ahi,  g_ahi);
    cudaGetSymbolAddress((void**)&alo,  g_alo);
    cudaGetSymbolAddress((void**)&wthi, g_wthi);
    cudaGetSymbolAddress((void**)&wphi, g_wphi);
    cudaGetSymbolAddress((void**)&wplo, g_wplo);

    cudaFuncSetAttribute(flash_hmma,
                         cudaFuncAttributeMaxDynamicSharedMemorySize, FL_SMEM);
    cudaFuncSetAttribute(hmma_gemm<3072, true, true>,
                         cudaFuncAttributeMaxDynamicSharedMemorySize, GEMM_SMEM_3);
    cudaFuncSetAttribute(hmma_gemm<1024, false, false>,
                         cudaFuncAttributeMaxDynamicSharedMemorySize, GEMM_SMEM_4);

    // Prologue: fp16-split x; fp16-round w_attn^T; bf16-split w_proj^T
    split_pack_elem_f16<<<(M_*C_/4 + 255)/256, 256>>>(x, xhi, xlo, M_*C_/4);
    transpose_pack_f16<<<dim3(3072/32, 1024/32), 256>>>(w_attn, wthi, 1024, 3072);
    transpose_split_pack<<<dim3(1024/32, 1024/32), 256>>>(w_proj, wphi, wplo, 1024, 1024);

    // QKV GEMM (fp16 2-term)
    hmma_gemm<3072, true, true><<<dim3(3072/128, M_/128), 256, GEMM_SMEM_3>>>(
        xhi, xlo, wthi, nullptr, b_attn, nullptr);

    // Flash attention (bf16 3-term), tail-packed grid
    flash_hmma<<<dim3(B_*NH_, T_/128), 256, FL_SMEM>>>();

    // Output projection (bf16 3-term)
    hmma_gemm<1024, false, false><<<dim3(1024/128, M_/128), 256, GEMM_SMEM_4>>>(
        ahi, alo, wphi, wplo, b_proj, out);
}

// round 14
// speedup vs baseline: 4.1290x; 1.1238x over previous
#include <cuda_runtime.h>
#include <cuda.h>
#include <math.h>
#include <stdint.h>

#define B_   4
#define T_   2048
#define C_   1024
#define NH_  16
#define HD_  64
#define M_   (B_*T_)      // 8192
#define KW_  (C_/2)       // 512 packed words per K=1024 row

// Scratch (allocation-free: __device__ globals)
__device__ uint32_t g_qhi[B_*NH_*T_*HD_/2], g_qlo[B_*NH_*T_*HD_/2];  // fp16 split
__device__ uint32_t g_khi[B_*NH_*T_*HD_/2], g_klo[B_*NH_*T_*HD_/2];  // fp16 split
__device__ float    g_v  [B_*NH_*T_*HD_];
__device__ uint32_t g_xhi[M_*KW_],  g_xlo[M_*KW_];      // fp16 split x
__device__ uint32_t g_ahi[M_*KW_],  g_alo[M_*KW_];      // fp16 split attention out
__device__ uint32_t g_wthi[3*C_*KW_];                   // w_attn^T fp16
__device__ uint32_t g_wphi[C_*KW_];                     // w_proj^T fp16

// ===========================================================================
// Helpers
// ===========================================================================
// fp16 pair split (even in low 16)
__device__ __forceinline__ void split2h(float e, float o, uint32_t& hi, uint32_t& lo) {
    asm("cvt.rn.f16x2.f32 %0, %1, %2;" : "=r"(hi) : "f"(o), "f"(e));
    float he, ho;
    asm("{.reg .f16 a,b;\n\tmov.b32 {a,b}, %2;\n\tcvt.f32.f16 %0, a;\n\tcvt.f32.f16 %1, b;}"
        : "=f"(he), "=f"(ho) : "r"(hi));
    asm("cvt.rn.f16x2.f32 %0, %1, %2;" : "=r"(lo) : "f"(o - ho), "f"(e - he));
}
// fp16 pair round (hi only)
__device__ __forceinline__ uint32_t pack2h(float e, float o) {
    uint32_t hi;
    asm("cvt.rn.f16x2.f32 %0, %1, %2;" : "=r"(hi) : "f"(o), "f"(e));
    return hi;
}

#define MMA_F16(c, a0v, a1v, a2v, a3v, b0v, b1v) \
    asm volatile("mma.sync.aligned.m16n8k16.row.col.f32.f16.f16.f32 " \
        "{%0,%1,%2,%3}, {%4,%5,%6,%7}, {%8,%9}, {%0,%1,%2,%3};" \
        : "+f"((c)[0]), "+f"((c)[1]), "+f"((c)[2]), "+f"((c)[3]) \
        : "r"(a0v), "r"(a1v), "r"(a2v), "r"(a3v), "r"(b0v), "r"(b1v))

#define LDSM_X4(r0,r1,r2,r3, addr) \
    asm volatile("ldmatrix.sync.aligned.m8n8.x4.shared.b16 {%0,%1,%2,%3}, [%4];" \
        : "=r"(r0), "=r"(r1), "=r"(r2), "=r"(r3) : "r"(addr))
#define LDSM_X2(r0,r1, addr) \
    asm volatile("ldmatrix.sync.aligned.m8n8.x2.shared.b16 {%0,%1}, [%2];" \
        : "=r"(r0), "=r"(r1) : "r"(addr))

__device__ __forceinline__ uint32_t smem_u32(const void* p) {
    uint32_t a;
    asm("{ .reg .u64 t; cvta.to.shared.u64 t, %1; cvt.u32.u64 %0, t; }" : "=r"(a) : "l"(p));
    return a;
}
#define CP_ASYNC16(saddr, gptr) \
    asm volatile("cp.async.cg.shared.global [%0], [%1], 16;" :: "r"(saddr), "l"(gptr))
#define CP_COMMIT() asm volatile("cp.async.commit_group;" ::: "memory")
#define CP_WAIT(n)  asm volatile("cp.async.wait_group %0;" :: "n"(n) : "memory")

// ===========================================================================
// Prologue kernels
// ===========================================================================
__global__ __launch_bounds__(256)
void split_pack_elem_f16(const float* __restrict__ in, uint32_t* __restrict__ hi,
                         uint32_t* __restrict__ lo, int n4)
{
    int i = blockIdx.x * 256 + threadIdx.x;
    if (i < n4) {
        float4 v = ((const float4*)in)[i];
        uint2 h, l;
        split2h(v.x, v.y, h.x, l.x);
        split2h(v.z, v.w, h.y, l.y);
        ((uint2*)hi)[i] = h;
        ((uint2*)lo)[i] = l;
    }
}

// transpose + fp16 round (hi only): in [R=k][C=n] -> out[n][R/2 words]
__global__ __launch_bounds__(256)
void transpose_pack_f16(const float* __restrict__ in, uint32_t* __restrict__ ohi,
                        int R, int C)
{
    __shared__ float t[32][33];
    const int tx = threadIdx.x & 31, ty = (threadIdx.x >> 5) & 7;
    const int x0 = blockIdx.x * 32;
    const int y0 = blockIdx.y * 32;
#pragma unroll
    for (int i = 0; i < 32; i += 8)
        t[ty + i][tx] = in[(size_t)(y0 + ty + i) * C + x0 + tx];
    __syncthreads();
    const int Rw = R >> 1;
    const int wl = threadIdx.x & 15;
    const int nl = threadIdx.x >> 4;
#pragma unroll
    for (int half = 0; half < 2; half++) {
        const int n_l = nl + half * 16;
        ohi[(size_t)(x0 + n_l) * Rw + (y0 >> 1) + wl] =
            pack2h(t[2 * wl][n_l], t[2 * wl + 1][n_l]);
    }
}

// ===========================================================================
// fp16 2-term HMMA GEMM: D = (Ahi+Alo) @ Bhi^T + bias  (3 staged matrices).
//   Single barrier per K chunk: wait -> sync -> submit next -> compute.
// ===========================================================================
#define GLD 20
#define GSTG (128*GLD)
#define GEMM_SMEM (6*GSTG*4)    // 61440

template<int NTOT, bool QKV>
__global__ __launch_bounds__(256, 2)
void hmma_gemm(const uint32_t* __restrict__ Ahi, const uint32_t* __restrict__ Alo,
               const uint32_t* __restrict__ Bhi,
               const float* __restrict__ bias, float* __restrict__ out)
{
    extern __shared__ uint32_t smu[];
    const uint32_t sbase = smem_u32(smu);

    const int tid  = threadIdx.x;
    const int lane = tid & 31;
    const int wid  = tid >> 5;
    const int wm   = wid & 1;
    const int wn   = wid >> 1;
    const int m0   = blockIdx.y * 128;
    const int n0   = blockIdx.x * 128;
    const int g    = lane >> 2;
    const int tig  = lane & 3;

    const uint32_t* src[3];
    src[0] = Ahi + (size_t)m0 * KW_;
    src[1] = Alo + (size_t)m0 * KW_;
    src[2] = Bhi + (size_t)n0 * KW_;

    float acc[4][4][4];
#pragma unroll
    for (int i = 0; i < 4; i++)
#pragma unroll
        for (int j = 0; j < 4; j++)
#pragma unroll
            for (int e = 0; e < 4; e++) acc[i][j][e] = 0.f;

    const int crow = tid >> 2;
    const int cc4  = tid & 3;

    const int sub  = lane >> 3, lrow = lane & 7;
    const int arow = (sub & 1) * 8 + lrow;
    const int acol = (sub >> 1) * 4;
    uint32_t awoff[4];
#pragma unroll
    for (int mt = 0; mt < 4; mt++)
        awoff[mt] = (uint32_t)((wm * 64 + mt * 16 + arow) * GLD + acol);
    const int bsub = (lane >> 3) & 1;
    uint32_t bwoff[4];
#pragma unroll
    for (int nt = 0; nt < 4; nt++)
        bwoff[nt] = (uint32_t)((wn * 32 + nt * 8 + lrow) * GLD + bsub * 4);

    // prologue: submit stage 0
    {
#pragma unroll
        for (int m = 0; m < 3; m++)
#pragma unroll
            for (int i = 0; i < 2; i++) {
                const int row = crow + i * 64;
                const uint32_t so = sbase + (uint32_t)(m * GSTG + row * GLD + cc4 * 4) * 4u;
                CP_ASYNC16(so, src[m] + (size_t)row * KW_ + cc4 * 4);
            }
        CP_COMMIT();
    }

#pragma unroll 1
    for (int kc = 0; kc < 32; kc++) {
        CP_WAIT(0);
        __syncthreads();

        if (kc + 1 < 32) {
            const uint32_t stg = sbase + ((kc + 1) & 1) * 3 * GSTG * 4;
#pragma unroll
            for (int m = 0; m < 3; m++)
#pragma unroll
                for (int i = 0; i < 2; i++) {
                    const int row = crow + i * 64;
                    const uint32_t so = stg + (uint32_t)(m * GSTG + row * GLD + cc4 * 4) * 4u;
                    CP_ASYNC16(so, src[m] + (size_t)row * KW_ + (kc + 1) * 16 + cc4 * 4);
                }
            CP_COMMIT();
        }

        const uint32_t stg = sbase + (kc & 1) * 3 * GSTG * 4;
        const uint32_t bAh = stg;
        const uint32_t bAl = stg + GSTG * 4;
        const uint32_t bBh = stg + 2 * GSTG * 4;

#pragma unroll
        for (int ks = 0; ks < 2; ks++) {
            const uint32_t k0w = ks * 8;
            uint32_t ah[4][4], al[4][4];
#pragma unroll
            for (int mt = 0; mt < 4; mt++) {
                LDSM_X4(ah[mt][0], ah[mt][1], ah[mt][2], ah[mt][3],
                        bAh + (awoff[mt] + k0w) * 4u);
                LDSM_X4(al[mt][0], al[mt][1], al[mt][2], al[mt][3],
                        bAl + (awoff[mt] + k0w) * 4u);
            }
#pragma unroll
            for (int nt = 0; nt < 4; nt++) {
                uint32_t bh0, bh1;
                LDSM_X2(bh0, bh1, bBh + (bwoff[nt] + k0w) * 4u);
#pragma unroll
                for (int mt = 0; mt < 4; mt++)
                    MMA_F16(acc[mt][nt], ah[mt][0], ah[mt][1], ah[mt][2], ah[mt][3], bh0, bh1);
#pragma unroll
                for (int mt = 0; mt < 4; mt++)
                    MMA_F16(acc[mt][nt], al[mt][0], al[mt][1], al[mt][2], al[mt][3], bh0, bh1);
            }
        }
    }

    // ---- epilogue ----
#pragma unroll
    for (int mt = 0; mt < 4; mt++) {
#pragma unroll
        for (int nt = 0; nt < 4; nt++) {
            const int n = n0 + wn * 32 + nt * 8 + tig * 2;
            const float bx = bias[n], by = bias[n + 1];
#pragma unroll
            for (int half = 0; half < 2; half++) {
                const int m = m0 + wm * 64 + mt * 16 + g + half * 8;
                const float vx = acc[mt][nt][half * 2 + 0] + bx;
                const float vy = acc[mt][nt][half * 2 + 1] + by;
                if (QKV) {
                    const int bb = m >> 11;
                    const int tt = m & (T_ - 1);
                    const int which = n >> 10;
                    const int cc = n & (C_ - 1);
                    const int h = cc >> 6;
                    const int d = cc & (HD_ - 1);
                    const size_t base = ((size_t)(bb * NH_ + h) * T_ + tt);
                    if (which == 2) {
                        float2 v; v.x = vx; v.y = vy;
                        *(float2*)&g_v[base * HD_ + d] = v;
                    } else {
                        uint32_t hw, lw;
                        split2h(vx, vy, hw, lw);
                        const size_t idx = base * (HD_/2) + (d >> 1);
                        if (which == 0) { g_qhi[idx] = hw; g_qlo[idx] = lw; }
                        else            { g_khi[idx] = hw; g_klo[idx] = lw; }
                    }
                } else {
                    float2 v; v.x = vx; v.y = vy;
                    *(float2*)&out[(size_t)m * NTOT + n] = v;
                }
            }
        }
    }
}

// ===========================================================================
// fp16 HMMA flash attention v6:
//   QK^T 3-term fp16 (48 MMA/kt/warp), PV 2-term fp16 with single-fp16 V
//   (32 MMA/kt/warp). FA2 register softmax, cp.async K, reg-prefetched V.
//   Tail-packed grid: qi = 15 - blockIdx.y.
// Smem (words): Qh 0(4608) Ql 4608 | Kbuf0 9216 Kbuf1 11520 (Kh 1152 + Kl 1152)
//   | Vbuf0 13824(1152) Vbuf1 14976 -> 16128 words = 64512 B
// ===========================================================================
#define FQ_LD 36
#define FV_LD 72
#define FL_SMEM (16128 * 4)

__global__ __launch_bounds__(256, 2)
void flash_hmma()
{
    extern __shared__ uint32_t smu[];
    const uint32_t sm_base = smem_u32(smu);
    uint32_t* Qh = smu;
    uint32_t* Ql = smu + 4608;

    const uint32_t bQh = sm_base;
    const uint32_t bQl = sm_base + 4608 * 4;
    const uint32_t kbase[2] = { sm_base + 9216 * 4, sm_base + 11520 * 4 };
    const uint32_t vword[2] = { 13824u, 14976u };

    const int tid  = threadIdx.x;
    const int lane = tid & 31;
    const int wm   = tid >> 5;
    const int g    = lane >> 2;
    const int tig  = lane & 3;

    const int bh = blockIdx.x;            // 0..63
    const int qi = 15 - blockIdx.y;       // big qi scheduled first
    const int q0 = qi * 128;

    const uint32_t* Qgh = g_qhi + (size_t)bh * T_ * 32 + (size_t)q0 * 32;
    const uint32_t* Qgl = g_qlo + (size_t)bh * T_ * 32 + (size_t)q0 * 32;
    const uint32_t* Kgh = g_khi + (size_t)bh * T_ * 32;
    const uint32_t* Kgl = g_klo + (size_t)bh * T_ * 32;
    const float*    Vg  = g_v   + (size_t)bh * T_ * HD_;

    const int sub  = lane >> 3, lrow = lane & 7;

    uint32_t kwoff4[2];
#pragma unroll
    for (int np = 0; np < 2; np++)
        kwoff4[np] = (uint32_t)((np * 16 + (sub >> 1) * 8 + lrow) * FQ_LD + (sub & 1) * 4);

    const int km = tid >> 7, kr = (tid >> 2) & 31, kcc = tid & 3;
    const uint32_t kdst = (uint32_t)((km ? 1152 : 0) + kr * FQ_LD + kcc * 8) * 4u;
    const uint32_t* kgsrc = km ? Kgl : Kgh;

    const int pr = tid >> 4, d4 = tid & 15;

    const int nkt = 4 * qi + 4;

    // prologue: stage Q, submit K(0), prefetch V(0)
#pragma unroll
    for (int it = 0; it < 4; it++) {
        const int u = tid + it * 256;
        const int r = u >> 3, wc = (u & 7) * 4;
        *(uint4*)&Qh[r * FQ_LD + wc] = *(const uint4*)(Qgh + r * 32 + wc);
        *(uint4*)&Ql[r * FQ_LD + wc] = *(const uint4*)(Qgl + r * 32 + wc);
    }
    CP_ASYNC16(kbase[0] + kdst,      kgsrc + (size_t)kr * 32 + kcc * 8);
    CP_ASYNC16(kbase[0] + kdst + 16, kgsrc + (size_t)kr * 32 + kcc * 8 + 4);
    CP_COMMIT();
    float4 va = *(const float4*)(Vg + (size_t)(2 * pr)     * HD_ + d4 * 4);
    float4 vb = *(const float4*)(Vg + (size_t)(2 * pr + 1) * HD_ + d4 * 4);

    const int rlo = wm * 16 + g;
    const int rhi = rlo + 8;
    __syncthreads();

    // hoist Q fragments (loop-invariant)
    uint32_t qah[4][4], qal[4][4];
    {
        const uint32_t qwoff =
            (uint32_t)((wm * 16 + (sub & 1) * 8 + lrow) * FQ_LD + (sub >> 1) * 4);
#pragma unroll
        for (int ks = 0; ks < 4; ks++) {
            LDSM_X4(qah[ks][0], qah[ks][1], qah[ks][2], qah[ks][3],
                    bQh + (qwoff + ks * 8) * 4u);
            LDSM_X4(qal[ks][0], qal[ks][1], qal[ks][2], qal[ks][3],
                    bQl + (qwoff + ks * 8) * 4u);
        }
    }

    float o[8][4];
#pragma unroll
    for (int nt = 0; nt < 8; nt++)
#pragma unroll
        for (int e = 0; e < 4; e++) o[nt][e] = 0.f;

    float mrun_lo = -INFINITY, mrun_hi = -INFINITY;
    float lrun_lo = 0.f,       lrun_hi = 0.f;

    const int qrow_lo = q0 + rlo;
    const int qrow_hi = q0 + rhi;

#pragma unroll 1
    for (int kt = 0; kt < nkt; kt++) {
        // store prefetched V(kt) as single fp16 pair-packed
        {
            uint32_t* Vp = smu + vword[kt & 1];
            uint4 h;
            h.x = pack2h(va.x, vb.x);
            h.y = pack2h(va.y, vb.y);
            h.z = pack2h(va.z, vb.z);
            h.w = pack2h(va.w, vb.w);
            *(uint4*)&Vp[pr * FV_LD + d4 * 4] = h;
        }
        CP_WAIT(0);
        __syncthreads();

        if (kt + 1 < nkt) {
            CP_ASYNC16(kbase[(kt + 1) & 1] + kdst,
                       kgsrc + (size_t)((kt + 1) * 32 + kr) * 32 + kcc * 8);
            CP_ASYNC16(kbase[(kt + 1) & 1] + kdst + 16,
                       kgsrc + (size_t)((kt + 1) * 32 + kr) * 32 + kcc * 8 + 4);
            CP_COMMIT();
            va = *(const float4*)(Vg + (size_t)((kt + 1) * 32 + 2 * pr)     * HD_ + d4 * 4);
            vb = *(const float4*)(Vg + (size_t)((kt + 1) * 32 + 2 * pr + 1) * HD_ + d4 * 4);
        }

        const uint32_t bKh = kbase[kt & 1];
        const uint32_t bKl = bKh + 1152 * 4;
        const uint32_t* Vp = smu + vword[kt & 1];

        // ---- S = Q @ K^T : 3-term fp16 ----
        float s[4][4];
#pragma unroll
        for (int nt = 0; nt < 4; nt++)
#pragma unroll
            for (int e = 0; e < 4; e++) s[nt][e] = 0.f;

#pragma unroll
        for (int ks = 0; ks < 4; ks++) {
#pragma unroll
            for (int np = 0; np < 2; np++) {
                uint32_t bh0, bh1, bh2, bh3, bl0, bl1, bl2, bl3;
                LDSM_X4(bh0, bh1, bh2, bh3, bKh + (kwoff4[np] + ks * 8) * 4u);
                LDSM_X4(bl0, bl1, bl2, bl3, bKl + (kwoff4[np] + ks * 8) * 4u);
                MMA_F16(s[2*np],   qah[ks][0], qah[ks][1], qah[ks][2], qah[ks][3], bh0, bh1);
                MMA_F16(s[2*np+1], qah[ks][0], qah[ks][1], qah[ks][2], qah[ks][3], bh2, bh3);
                MMA_F16(s[2*np],   qal[ks][0], qal[ks][1], qal[ks][2], qal[ks][3], bh0, bh1);
                MMA_F16(s[2*np+1], qal[ks][0], qal[ks][1], qal[ks][2], qal[ks][3], bh2, bh3);
                MMA_F16(s[2*np],   qah[ks][0], qah[ks][1], qah[ks][2], qah[ks][3], bl0, bl1);
                MMA_F16(s[2*np+1], qah[ks][0], qah[ks][1], qah[ks][2], qah[ks][3], bl2, bl3);
            }
        }

        // ---- scale + causal mask + row max ----
        float mlo = -INFINITY, mhi = -INFINITY;
        const bool needmask = (kt * 32 + 31) > (q0 + wm * 16);
#pragma unroll
        for (int nt = 0; nt < 4; nt++) {
            const int colb = kt * 32 + nt * 8 + 2 * tig;
#pragma unroll
            for (int j = 0; j < 2; j++) {
                float v0 = s[nt][j] * 0.125f;
                float v1 = s[nt][2 + j] * 0.125f;
                if (needmask) {
                    if (colb + j > qrow_lo) v0 = -INFINITY;
                    if (colb + j > qrow_hi) v1 = -INFINITY;
                }
                s[nt][j] = v0;
                s[nt][2 + j] = v1;
                mlo = fmaxf(mlo, v0);
                mhi = fmaxf(mhi, v1);
            }
        }
#pragma unroll
        for (int off = 1; off < 4; off <<= 1) {
            mlo = fmaxf(mlo, __shfl_xor_sync(0xffffffffu, mlo, off));
            mhi = fmaxf(mhi, __shfl_xor_sync(0xffffffffu, mhi, off));
        }

        // ---- online softmax (registers) ----
        const float mnew_lo = fmaxf(mrun_lo, mlo);
        const float mnew_hi = fmaxf(mrun_hi, mhi);
        const float corr_lo = __expf(mrun_lo - mnew_lo);
        const float corr_hi = __expf(mrun_hi - mnew_hi);
        mrun_lo = mnew_lo; mrun_hi = mnew_hi;

        float sumlo = 0.f, sumhi = 0.f;
        uint32_t pah[2][4], pal[2][4];
#pragma unroll
        for (int nt = 0; nt < 4; nt++) {
            float p0 = __expf(s[nt][0] - mnew_lo);
            float p1 = __expf(s[nt][1] - mnew_lo);
            float p2 = __expf(s[nt][2] - mnew_hi);
            float p3 = __expf(s[nt][3] - mnew_hi);
            sumlo += p0 + p1;
            sumhi += p2 + p3;
            const int ks = nt >> 1;
            const int hi2 = (nt & 1) * 2;
            split2h(p0, p1, pah[ks][hi2],     pal[ks][hi2]);
            split2h(p2, p3, pah[ks][hi2 + 1], pal[ks][hi2 + 1]);
        }
#pragma unroll
        for (int off = 1; off < 4; off <<= 1) {
            sumlo += __shfl_xor_sync(0xffffffffu, sumlo, off);
            sumhi += __shfl_xor_sync(0xffffffffu, sumhi, off);
        }
        lrun_lo = lrun_lo * corr_lo + sumlo;
        lrun_hi = lrun_hi * corr_hi + sumhi;

#pragma unroll
        for (int nt = 0; nt < 8; nt++) {
            o[nt][0] *= corr_lo; o[nt][1] *= corr_lo;
            o[nt][2] *= corr_hi; o[nt][3] *= corr_hi;
        }

        // ---- O += P @ V : 2-term fp16, single-fp16 V ----
#pragma unroll
        for (int ks = 0; ks < 2; ks++) {
#pragma unroll
            for (int nt = 0; nt < 8; nt++) {
                const int col = nt * 8 + g;
                const uint32_t vh0 = Vp[(ks * 8 + tig)     * FV_LD + col];
                const uint32_t vh1 = Vp[(ks * 8 + tig + 4) * FV_LD + col];
                MMA_F16(o[nt], pah[ks][0], pah[ks][1], pah[ks][2], pah[ks][3], vh0, vh1);
                MMA_F16(o[nt], pal[ks][0], pal[ks][1], pal[ks][2], pal[ks][3], vh0, vh1);
            }
        }
    }

    // ---- normalize + store fp16-split output (for fp16 2-term proj GEMM) ----
    const float inv_lo = 1.f / lrun_lo;
    const float inv_hi = 1.f / lrun_hi;
    const int b = bh >> 4, h = bh & 15;
    const int t_lo = q0 + rlo, t_hi = q0 + rhi;
#pragma unroll
    for (int nt = 0; nt < 8; nt++) {
        const int d = nt * 8 + 2 * tig;
        const int w = (h * HD_ + d) >> 1;
        uint32_t hw, lw;
        split2h(o[nt][0] * inv_lo, o[nt][1] * inv_lo, hw, lw);
        g_ahi[(size_t)(b * T_ + t_lo) * KW_ + w] = hw;
        g_alo[(size_t)(b * T_ + t_lo) * KW_ + w] = lw;
        split2h(o[nt][2] * inv_hi, o[nt][3] * inv_hi, hw, lw);
        g_ahi[(size_t)(b * T_ + t_hi) * KW_ + w] = hw;
        g_alo[(size_t)(b * T_ + t_hi) * KW_ + w] = lw;
    }
}

// ===========================================================================
// Launch
// ===========================================================================
extern "C" void kernel_launch(void* const* d_in, const int* in_sizes, int n_in,
                              void* d_out, int out_size)
{
    const float* x      = (const float*)d_in[0];
    const float* w_attn = (const float*)d_in[1];
    const float* b_attn = (const float*)d_in[2];
    const float* w_proj = (const float*)d_in[3];
    const float* b_proj = (const float*)d_in[4];
    float* out = (float*)d_out;

    uint32_t *xhi, *xlo, *ahi, *alo, *wthi, *wphi;
    cudaGetSymbolAddress((void**)&xhi,  g_xhi);
    cudaGetSymbolAddress((void**)&xlo,  g_xlo);
    cudaGetSymbolAddress((void**)&ahi,  g_ahi);
    cudaGetSymbolAddress((void**)&alo,  g_alo);
    cudaGetSymbolAddress((void**)&wthi, g_wthi);
    cudaGetSymbolAddress((void**)&wphi, g_wphi);

    cudaFuncSetAttribute(flash_hmma,
                         cudaFuncAttributeMaxDynamicSharedMemorySize, FL_SMEM);
    cudaFuncSetAttribute(hmma_gemm<3072, true>,
                         cudaFuncAttributeMaxDynamicSharedMemorySize, GEMM_SMEM);
    cudaFuncSetAttribute(hmma_gemm<1024, false>,
                         cudaFuncAttributeMaxDynamicSharedMemorySize, GEMM_SMEM);

    // Prologue: fp16-split x; fp16-round both transposed weights
    split_pack_elem_f16<<<(M_*C_/4 + 255)/256, 256>>>(x, xhi, xlo, M_*C_/4);
    transpose_pack_f16<<<dim3(3072/32, 1024/32), 256>>>(w_attn, wthi, 1024, 3072);
    transpose_pack_f16<<<dim3(1024/32, 1024/32), 256>>>(w_proj, wphi, 1024, 1024);

    // QKV GEMM (fp16 2-term)
    hmma_gemm<3072, true><<<dim3(3072/128, M_/128), 256, GEMM_SMEM>>>(
        xhi, xlo, wthi, b_attn, nullptr);

    // Flash attention (fp16), tail-packed grid
    flash_hmma<<<dim3(B_*NH_, T_/128), 256, FL_SMEM>>>();

    // Output projection (fp16 2-term)
    hmma_gemm<1024, false><<<dim3(1024/128, M_/128), 256, GEMM_SMEM>>>(
        ahi, alo, wphi, b_proj, out);
}